// round 5
// baseline (speedup 1.0000x reference)
#include <cuda_runtime.h>
#include <cuda_bf16.h>
#include <cstdint>
#include <math.h>

#define NN 20000
#define EE 320000
#define DD 128
#define LL 3
#define BN_EPS 1e-5f
#define NT2 2500            // edge tiles (128 edges each)
#define NTN 157             // node tiles (ceil(20000/128))

// shared-tile geometry: bf16 planes [128 rows][128 k] padded to stride 136 (272B)
#define PL 34816            // plane bytes: 128*272
#define OFF_AHI 0
#define OFF_ALO 34816
#define OFF_BHI 69632
#define OFF_BLO 104448
#define SZ_GEMM 139264
#define OFF_SRC 139264
#define OFF_DST 139776
#define OFF_SS  140288
#define OFF_SQ  140800
#define SZ_EDGE 141312
#define OFF_ROW 139264
#define SZ_FIN  139776

// ---------------- scratch (device globals; no allocation) ----------------
__device__ float g_h [NN*DD];
__device__ float g_e [EE*DD];
__device__ float g_et[EE*DD];
__device__ float g_Uh[NN*DD];
__device__ float g_Vh[NN*DD];
__device__ float g_Bh[NN*DD];
__device__ float g_Ch[NN*DD];
__device__ float g_agg[NN*DD];
__device__ float g_tmp[NN*DD];
__device__ float g_cnt[NN];
__device__ int   g_cnti[NN];
__device__ float g_eps[2*DD*NT2];      // edge BN partials
__device__ float g_stats[4*DD];
__device__ float g_scale[2*DD];
__device__ float g_shift[2*DD];
// 17 weight slots: dense [k][n] split planes, hi (16384 ushort) then lo
__device__ unsigned short g_wimg[17*32768];

// ---------------- helpers ----------------
__device__ __forceinline__ float sigm(float v){ return 1.f/(1.f+__expf(-v)); }
__device__ __forceinline__ float silu(float v){ return v*sigm(v); }

__device__ __forceinline__ uint32_t smem_u32(const void* p){
    uint32_t a;
    asm("{ .reg .u64 t; cvta.to.shared.u64 t, %1; cvt.u32.u64 %0, t; }" : "=r"(a) : "l"(p));
    return a;
}
__device__ __forceinline__ void split_bf(float v, __nv_bfloat16& h, __nv_bfloat16& l){
    h = __float2bfloat16(v);
    l = __float2bfloat16(v - __bfloat162float(h));
}
__device__ __forceinline__ unsigned pack_bf2(__nv_bfloat16 a, __nv_bfloat16 b){
    __nv_bfloat162 p = __halves2bfloat162(a, b);
    return *reinterpret_cast<unsigned*>(&p);
}
__device__ __forceinline__ void ldsm4(uint32_t addr, uint32_t r[4]){
    asm volatile("ldmatrix.sync.aligned.m8n8.x4.shared.b16 {%0,%1,%2,%3}, [%4];"
        : "=r"(r[0]), "=r"(r[1]), "=r"(r[2]), "=r"(r[3]) : "r"(addr));
}
__device__ __forceinline__ void ldsm4t(uint32_t addr, uint32_t r[4]){
    asm volatile("ldmatrix.sync.aligned.m8n8.x4.trans.shared.b16 {%0,%1,%2,%3}, [%4];"
        : "=r"(r[0]), "=r"(r[1]), "=r"(r[2]), "=r"(r[3]) : "r"(addr));
}
__device__ __forceinline__ void mma16816(float c[4], const uint32_t a[4], uint32_t b0, uint32_t b1){
    asm volatile("mma.sync.aligned.m16n8k16.row.col.f32.bf16.bf16.f32 "
        "{%0,%1,%2,%3}, {%4,%5,%6,%7}, {%8,%9}, {%0,%1,%2,%3};"
        : "+f"(c[0]), "+f"(c[1]), "+f"(c[2]), "+f"(c[3])
        : "r"(a[0]), "r"(a[1]), "r"(a[2]), "r"(a[3]), "r"(b0), "r"(b1));
}

// warp-tiled split-bf16 GEMM core: acc[2][8][4] = A[128x128] @ B[128x128]
// offA/offB = hi-plane byte offsets in dynamic smem (lo at +PL)
__device__ __forceinline__ void gemm_core(uint32_t sb, int offA, int offB, int t,
                                          float acc[2][8][4]){
    const int lane = t & 31, wid = t >> 5;
    const int wm = wid >> 1, wn = wid & 1;
    uint32_t aBase = sb + offA + (uint32_t)(wm*32 + (lane&7) + ((lane>>3)&1)*8)*272
                   + (uint32_t)((lane>>4)*8)*2;
    uint32_t bBase = sb + offB + (uint32_t)((lane&7) + ((lane>>3)&1)*8)*272
                   + (uint32_t)(wn*64 + (lane>>4)*8)*2;
    #pragma unroll
    for (int kt = 0; kt < 8; kt++){
        uint32_t a0h[4], a1h[4], a0l[4], a1l[4];
        ldsm4(aBase + kt*32,                 a0h);
        ldsm4(aBase + 16*272 + kt*32,        a1h);
        ldsm4(aBase + PL + kt*32,            a0l);
        ldsm4(aBase + PL + 16*272 + kt*32,   a1l);
        uint32_t bh[4][4], bl[4][4];
        #pragma unroll
        for (int np = 0; np < 4; np++){
            ldsm4t(bBase + kt*4352 + np*32,      bh[np]);
            ldsm4t(bBase + PL + kt*4352 + np*32, bl[np]);
        }
        #pragma unroll
        for (int mt = 0; mt < 2; mt++){
            const uint32_t* Ah = mt ? a1h : a0h;
            const uint32_t* Al = mt ? a1l : a0l;
            #pragma unroll
            for (int np = 0; np < 4; np++){
                #pragma unroll
                for (int sub = 0; sub < 2; sub++){
                    float* c = acc[mt][np*2 + sub];
                    uint32_t h0 = bh[np][sub*2], h1 = bh[np][sub*2+1];
                    mma16816(c, Ah, h0, h1);
                    mma16816(c, Ah, bl[np][sub*2], bl[np][sub*2+1]);
                    mma16816(c, Al, h0, h1);
                }
            }
        }
    }
}

// copy a prepped weight slot (dense [k][n] hi+lo) into padded smem planes
__device__ __forceinline__ void copy_w(char* smem, int offB, const unsigned short* wslot, int t){
    const uint4* hi = (const uint4*)wslot;
    const uint4* lo = (const uint4*)(wslot + 16384);
    uint4* dh = (uint4*)(smem + offB);
    uint4* dl = (uint4*)(smem + offB + PL);
    #pragma unroll
    for (int i = t; i < 2048; i += 256){
        int r = i >> 4, c = i & 15;
        dh[r*17 + c] = hi[i];
        dl[r*17 + c] = lo[i];
    }
}

// ---------------- weight prep: fp32 [k][n] -> split bf16 dense planes ----------------
__global__ void k_prep(const float* __restrict__ W, int slot){
    int k = blockIdx.x, n = threadIdx.x;
    unsigned short* base = g_wimg + (size_t)slot*32768;
    __nv_bfloat16 h, l; split_bf(W[k*DD + n], h, l);
    base[k*DD + n]         = __bfloat16_as_ushort(h);
    base[16384 + k*DD + n] = __bfloat16_as_ushort(l);
}

// ---------------- small kernels ----------------
__global__ void k_zero_f4(float4* p, int n){
    int i = blockIdx.x*blockDim.x + threadIdx.x;
    if (i < n) p[i] = make_float4(0.f,0.f,0.f,0.f);
}
__global__ void k_zero_f(float* p, int n){
    int i = blockIdx.x*blockDim.x + threadIdx.x;
    if (i < n) p[i] = 0.f;
}
__global__ void k_zero_i(int* p, int n){
    int i = blockIdx.x*blockDim.x + threadIdx.x;
    if (i < n) p[i] = 0;
}
__global__ void k_count(const int* __restrict__ src){
    int i = blockIdx.x*blockDim.x + threadIdx.x;
    if (i < EE) atomicAdd(&g_cnti[src[i]], 1);
}
__global__ void k_cntf(){
    int i = blockIdx.x*blockDim.x + threadIdx.x;
    if (i < NN) g_cnt[i] = fmaxf((float)g_cnti[i], 1.f);
}
__global__ void k_init_h(const float* __restrict__ x,
                         const float* __restrict__ hw, const float* __restrict__ hb){
    int n = blockIdx.x, d = threadIdx.x;
    float v = fmaf(x[n*2+0], hw[d], fmaf(x[n*2+1], hw[DD+d], hb[d]));
    g_h[n*DD+d] = silu(v);
}
__global__ void k_init_e(const float* __restrict__ ea,
                         const float* __restrict__ ew, const float* __restrict__ eb){
    int e = blockIdx.x, d = threadIdx.x;
    float v = fmaf(ea[e], ew[d], eb[d]);
    g_e[e*DD+d] = silu(v);
}
__global__ void k_node_tmp(){
    int n = blockIdx.x, d = threadIdx.x;
    g_tmp[n*DD + d] = g_Uh[n*DD + d] + g_agg[n*DD + d] / g_cnt[n];
}
template<int R>
__global__ void k_colstats(const float* __restrict__ X, int rows,
                           float* __restrict__ sum, float* __restrict__ sumsq){
    const int d = threadIdx.x;
    const int r0 = blockIdx.x * R;
    const int r1 = min(rows, r0 + R);
    float s = 0.f, q = 0.f;
    for (int r = r0; r < r1; r++){
        float v = X[r*DD + d];
        s += v; q = fmaf(v, v, q);
    }
    atomicAdd(&sum[d], s);
    atomicAdd(&sumsq[d], q);
}
__global__ void k_bn_fin(const float* __restrict__ sum, const float* __restrict__ sumsq,
                         const float* __restrict__ gamma, const float* __restrict__ beta,
                         float rows, float* __restrict__ scale, float* __restrict__ shift){
    int d = threadIdx.x;
    float m   = sum[d] / rows;
    float var = sumsq[d] / rows - m*m;
    float inv = rsqrtf(var + BN_EPS);
    float sc  = inv * gamma[d];
    scale[d] = sc;
    shift[d] = beta[d] - m*sc;
}
__global__ void k_apply4(float4* __restrict__ base, const float4* __restrict__ X,
                         const float4* __restrict__ sc4, const float4* __restrict__ sh4, int n4){
    int i = blockIdx.x*blockDim.x + threadIdx.x;
    if (i >= n4) return;
    int c = i & 31;
    float4 x = X[i], s = sc4[c], h = sh4[c], b = base[i];
    b.x += silu(fmaf(x.x, s.x, h.x));
    b.y += silu(fmaf(x.y, s.y, h.y));
    b.z += silu(fmaf(x.z, s.z, h.z));
    b.w += silu(fmaf(x.w, s.w, h.w));
    base[i] = b;
}
__global__ void k_eps_reduce(float* __restrict__ pst){
    const int row = blockIdx.x;   // 0..255
    const float* p = g_eps + (size_t)row*NT2;
    float s = 0.f;
    for (int i = threadIdx.x; i < NT2; i += 256) s += p[i];
    __shared__ float red[256];
    red[threadIdx.x] = s; __syncthreads();
    for (int o = 128; o > 0; o >>= 1){
        if (threadIdx.x < o) red[threadIdx.x] += red[threadIdx.x + o];
        __syncthreads();
    }
    if (threadIdx.x == 0){
        if (row < DD) pst[2*DD + row]      = red[0];
        else          pst[3*DD + (row-DD)] = red[0];
    }
}

// ---------------- node GEMM: out = A @ W + b (128-row tiles) ----------------
__global__ void __launch_bounds__(256,1) k_mma_gemm(const float* __restrict__ A,
                                                    const unsigned short* __restrict__ wslot,
                                                    const float* __restrict__ bias,
                                                    float* __restrict__ out, int rows){
    extern __shared__ __align__(16) char smem[];
    uint32_t sb = smem_u32(smem);
    const int t = threadIdx.x, lane = t & 31, wid = t >> 5;
    const int wm = wid >> 1, wn = wid & 1;
    const int row0 = blockIdx.x * 128;

    copy_w(smem, OFF_BHI, wslot, t);

    const float4* A4 = (const float4*)A;
    #pragma unroll
    for (int it = 0; it < 16; it++){
        int idx = it*256 + t;
        int r = idx >> 5, c4 = idx & 31;
        float4 v = make_float4(0.f,0.f,0.f,0.f);
        if (row0 + r < rows) v = A4[(size_t)(row0 + r)*32 + c4];
        int off = r*272 + c4*8;
        __nv_bfloat16 h0,l0,h1,l1,h2,l2,h3,l3;
        split_bf(v.x,h0,l0); split_bf(v.y,h1,l1); split_bf(v.z,h2,l2); split_bf(v.w,h3,l3);
        *(unsigned*)(smem + OFF_AHI + off)     = pack_bf2(h0,h1);
        *(unsigned*)(smem + OFF_AHI + off + 4) = pack_bf2(h2,h3);
        *(unsigned*)(smem + OFF_ALO + off)     = pack_bf2(l0,l1);
        *(unsigned*)(smem + OFF_ALO + off + 4) = pack_bf2(l2,l3);
    }
    __syncthreads();

    float acc[2][8][4];
    #pragma unroll
    for (int i=0;i<2;i++) for(int j=0;j<8;j++) for(int k=0;k<4;k++) acc[i][j][k]=0.f;
    gemm_core(sb, OFF_AHI, OFF_BHI, t, acc);
    __syncthreads();

    // fragments -> smem D [row][col] stride 132 (overlay B region)
    float* sD = (float*)(smem + OFF_BHI);
    #pragma unroll
    for (int mt = 0; mt < 2; mt++){
        int r0 = wm*32 + mt*16 + (lane>>2);
        #pragma unroll
        for (int nt = 0; nt < 8; nt++){
            int c0 = wn*64 + nt*8 + (lane&3)*2;
            float* c = acc[mt][nt];
            *(float2*)&sD[r0*132 + c0]     = make_float2(c[0], c[1]);
            *(float2*)&sD[(r0+8)*132 + c0] = make_float2(c[2], c[3]);
        }
    }
    __syncthreads();

    float4* out4 = (float4*)out;
    #pragma unroll
    for (int it = 0; it < 16; it++){
        int idx = it*256 + t;
        int r = idx >> 5, c4 = idx & 31;
        if (row0 + r < rows){
            float4 v = *(const float4*)&sD[r*132 + c4*4];
            const float4 b = *(const float4*)(bias + c4*4);
            v.x += b.x; v.y += b.y; v.z += b.z; v.w += b.w;
            out4[(size_t)(row0 + r)*32 + c4] = v;
        }
    }
}

// ---------------- fused edge kernel ----------------
// (APPLY) e = e + silu(et*sc+sh) first; then et = e@Aw + ab + Bh[src] + Ch[dst];
// writes et + BN partials; (DOMSG) scatters sigm(e)*Vh[dst] into agg.
template<int APPLY, int DOMSG>
__global__ void __launch_bounds__(256,1) k_edge_mma(const unsigned short* __restrict__ wslot,
                                                    const float* __restrict__ ab,
                                                    const int* __restrict__ src,
                                                    const int* __restrict__ dst,
                                                    const float* __restrict__ scE,
                                                    const float* __restrict__ shE){
    extern __shared__ __align__(16) char smem[];
    uint32_t sb = smem_u32(smem);
    const int t = threadIdx.x, lane = t & 31, wid = t >> 5;
    const int wm = wid >> 1, wn = wid & 1;
    const int blk = blockIdx.x;
    const int e0 = blk * 128;

    int* shs = (int*)(smem + OFF_SRC);
    int* sht = (int*)(smem + OFF_DST);
    if (t < 128){ shs[t] = src[e0+t]; sht[t] = dst[e0+t]; }

    copy_w(smem, OFF_BHI, wslot, t);

    float4* ge4  = (float4*)g_e;
    const float4* get4 = (const float4*)g_et;
    const float4* sc4 = (const float4*)scE;
    const float4* sh4 = (const float4*)shE;
    #pragma unroll
    for (int it = 0; it < 16; it++){
        int idx = it*256 + t;
        int r = idx >> 5, c4 = idx & 31;
        size_t gi = (size_t)(e0 + r)*32 + c4;
        float4 ev = ge4[gi];
        if (APPLY){
            float4 et = get4[gi], S = sc4[c4], H = sh4[c4];
            ev.x += silu(fmaf(et.x, S.x, H.x));
            ev.y += silu(fmaf(et.y, S.y, H.y));
            ev.z += silu(fmaf(et.z, S.z, H.z));
            ev.w += silu(fmaf(et.w, S.w, H.w));
            ge4[gi] = ev;
        }
        int off = r*272 + c4*8;
        __nv_bfloat16 h0,l0,h1,l1,h2,l2,h3,l3;
        split_bf(ev.x,h0,l0); split_bf(ev.y,h1,l1); split_bf(ev.z,h2,l2); split_bf(ev.w,h3,l3);
        *(unsigned*)(smem + OFF_AHI + off)     = pack_bf2(h0,h1);
        *(unsigned*)(smem + OFF_AHI + off + 4) = pack_bf2(h2,h3);
        *(unsigned*)(smem + OFF_ALO + off)     = pack_bf2(l0,l1);
        *(unsigned*)(smem + OFF_ALO + off + 4) = pack_bf2(l2,l3);
    }
    __syncthreads();

    float acc[2][8][4];
    #pragma unroll
    for (int i=0;i<2;i++) for(int j=0;j<8;j++) for(int k=0;k<4;k++) acc[i][j][k]=0.f;
    gemm_core(sb, OFF_AHI, OFF_BHI, t, acc);
    __syncthreads();

    // fragments -> smem D transposed [col][row] stride 129 (overlay B region)
    float* sDT = (float*)(smem + OFF_BHI);
    #pragma unroll
    for (int mt = 0; mt < 2; mt++){
        int r0 = wm*32 + mt*16 + (lane>>2);
        #pragma unroll
        for (int nt = 0; nt < 8; nt++){
            int c0 = wn*64 + nt*8 + (lane&3)*2;
            float* c = acc[mt][nt];
            sDT[c0*129 + r0]         = c[0];
            sDT[(c0+1)*129 + r0]     = c[1];
            sDT[c0*129 + r0 + 8]     = c[2];
            sDT[(c0+1)*129 + r0 + 8] = c[3];
        }
    }
    __syncthreads();

    // epilogue: col-major threads (A planes still hold e for the gate)
    const int col = t & 127, half = t >> 7;
    const float b = ab[col];
    float s = 0.f, q = 0.f;
    #pragma unroll 4
    for (int r = half*64; r < half*64 + 64; r++){
        int ss = shs[r], tt = sht[r];
        float d = sDT[col*129 + r] + b + g_Bh[(size_t)ss*DD + col] + g_Ch[(size_t)tt*DD + col];
        g_et[(size_t)(e0 + r)*DD + col] = d;
        s += d; q = fmaf(d, d, q);
        if (DOMSG){
            float eh = __bfloat162float(*(const __nv_bfloat16*)(smem + OFF_AHI + r*272 + col*2));
            float el = __bfloat162float(*(const __nv_bfloat16*)(smem + OFF_ALO + r*272 + col*2));
            atomicAdd(&g_agg[(size_t)ss*DD + col], sigm(eh + el) * g_Vh[(size_t)tt*DD + col]);
        }
    }
    float* sS = (float*)(smem + OFF_SS);
    float* sQ = (float*)(smem + OFF_SQ);
    if (half == 0){ sS[col] = s; sQ[col] = q; }
    __syncthreads();
    if (half == 1){ sS[col] += s; sQ[col] += q; }
    __syncthreads();
    if (half == 0){
        g_eps[(size_t)col*NT2 + blk]      = sS[col];
        g_eps[(size_t)(DD+col)*NT2 + blk] = sQ[col];
    }
}

// ---------------- fused final: e-apply -> MLP(2 GEMMs) -> sigmoid dot ----------------
__global__ void __launch_bounds__(256,1) k_final_mma(const unsigned short* __restrict__ w1,
                                                     const unsigned short* __restrict__ w2,
                                                     const float* __restrict__ f1b,
                                                     const float* __restrict__ f2b,
                                                     const float* __restrict__ f3w,
                                                     const float* __restrict__ f3b,
                                                     const float* __restrict__ scE,
                                                     const float* __restrict__ shE,
                                                     float* __restrict__ out){
    extern __shared__ __align__(16) char smem[];
    uint32_t sb = smem_u32(smem);
    const int t = threadIdx.x, lane = t & 31, wid = t >> 5;
    const int wm = wid >> 1, wn = wid & 1;
    const int e0 = blockIdx.x * 128;

    float* sRow = (float*)(smem + OFF_ROW);
    if (t < 128) sRow[t] = 0.f;

    copy_w(smem, OFF_BHI, w1, t);

    const float4* ge4  = (const float4*)g_e;
    const float4* get4 = (const float4*)g_et;
    const float4* sc4  = (const float4*)scE;
    const float4* sh4  = (const float4*)shE;
    #pragma unroll
    for (int it = 0; it < 16; it++){
        int idx = it*256 + t;
        int r = idx >> 5, c4 = idx & 31;
        size_t gi = (size_t)(e0 + r)*32 + c4;
        float4 ev = ge4[gi];
        float4 et = get4[gi], S = sc4[c4], H = sh4[c4];
        ev.x += silu(fmaf(et.x, S.x, H.x));
        ev.y += silu(fmaf(et.y, S.y, H.y));
        ev.z += silu(fmaf(et.z, S.z, H.z));
        ev.w += silu(fmaf(et.w, S.w, H.w));
        int off = r*272 + c4*8;
        __nv_bfloat16 h0,l0,h1,l1,h2,l2,h3,l3;
        split_bf(ev.x,h0,l0); split_bf(ev.y,h1,l1); split_bf(ev.z,h2,l2); split_bf(ev.w,h3,l3);
        *(unsigned*)(smem + OFF_AHI + off)     = pack_bf2(h0,h1);
        *(unsigned*)(smem + OFF_AHI + off + 4) = pack_bf2(h2,h3);
        *(unsigned*)(smem + OFF_ALO + off)     = pack_bf2(l0,l1);
        *(unsigned*)(smem + OFF_ALO + off + 4) = pack_bf2(l2,l3);
    }
    __syncthreads();

    float acc[2][8][4];
    #pragma unroll
    for (int i=0;i<2;i++) for(int j=0;j<8;j++) for(int k=0;k<4;k++) acc[i][j][k]=0.f;
    gemm_core(sb, OFF_AHI, OFF_BHI, t, acc);
    __syncthreads();   // everyone done reading A & B planes

    // stage1 epilogue: silu -> split bf16 straight from fragments into B region
    // (acts as A planes for GEMM 2); W2 loads into A region.
    #pragma unroll
    for (int mt = 0; mt < 2; mt++){
        int r0 = wm*32 + mt*16 + (lane>>2);
        #pragma unroll
        for (int nt = 0; nt < 8; nt++){
            int c0 = wn*64 + nt*8 + (lane&3)*2;
            float* c = acc[mt][nt];
            float v0 = silu(c[0] + f1b[c0]);
            float v1 = silu(c[1] + f1b[c0+1]);
            float v2 = silu(c[2] + f1b[c0]);
            float v3 = silu(c[3] + f1b[c0+1]);
            __nv_bfloat16 h0,l0,h1,l1;
            split_bf(v0,h0,l0); split_bf(v1,h1,l1);
            *(unsigned*)(smem + OFF_BHI + r0*272 + c0*2) = pack_bf2(h0,h1);
            *(unsigned*)(smem + OFF_BLO + r0*272 + c0*2) = pack_bf2(l0,l1);
            split_bf(v2,h0,l0); split_bf(v3,h1,l1);
            *(unsigned*)(smem + OFF_BHI + (r0+8)*272 + c0*2) = pack_bf2(h0,h1);
            *(unsigned*)(smem + OFF_BLO + (r0+8)*272 + c0*2) = pack_bf2(l0,l1);
        }
    }
    copy_w(smem, OFF_AHI, w2, t);
    __syncthreads();

    float acc2[2][8][4];
    #pragma unroll
    for (int i=0;i<2;i++) for(int j=0;j<8;j++) for(int k=0;k<4;k++) acc2[i][j][k]=0.f;
    gemm_core(sb, OFF_BHI, OFF_AHI, t, acc2);

    // stage3: silu(+f2b)*f3w, reduce per row
    #pragma unroll
    for (int mt = 0; mt < 2; mt++){
        float r0s = 0.f, r1s = 0.f;
        #pragma unroll
        for (int nt = 0; nt < 8; nt++){
            int c0 = wn*64 + nt*8 + (lane&3)*2;
            float* c = acc2[mt][nt];
            float w0 = f3w[c0], w1 = f3w[c0+1];
            float b0 = f2b[c0], b1 = f2b[c0+1];
            r0s = fmaf(silu(c[0]+b0), w0, fmaf(silu(c[1]+b1), w1, r0s));
            r1s = fmaf(silu(c[2]+b0), w0, fmaf(silu(c[3]+b1), w1, r1s));
        }
        r0s += __shfl_xor_sync(0xffffffff, r0s, 1);
        r0s += __shfl_xor_sync(0xffffffff, r0s, 2);
        r1s += __shfl_xor_sync(0xffffffff, r1s, 1);
        r1s += __shfl_xor_sync(0xffffffff, r1s, 2);
        if ((lane & 3) == 0){
            int r0 = wm*32 + mt*16 + (lane>>2);
            atomicAdd(&sRow[r0], r0s);
            atomicAdd(&sRow[r0+8], r1s);
        }
    }
    __syncthreads();
    if (t < 128) out[e0 + t] = sigm(sRow[t] + f3b[0]);
}

// ---------------- host orchestration ----------------
extern "C" void kernel_launch(void* const* d_in, const int* in_sizes, int n_in,
                              void* d_out, int out_size){
    const float* x    = (const float*)d_in[0];
    const float* ea   = (const float*)d_in[1];
    const int*   eidx = (const int*)  d_in[2];
    const float* hp_w = (const float*)d_in[3];
    const float* hp_b = (const float*)d_in[4];
    const float* ep_w = (const float*)d_in[5];
    const float* ep_b = (const float*)d_in[6];
    const float* Uw   = (const float*)d_in[7];
    const float* Ub   = (const float*)d_in[8];
    const float* Vw   = (const float*)d_in[9];
    const float* Vb   = (const float*)d_in[10];
    const float* Aw   = (const float*)d_in[11];
    const float* Ab   = (const float*)d_in[12];
    const float* Bw   = (const float*)d_in[13];
    const float* Bb   = (const float*)d_in[14];
    const float* Cw   = (const float*)d_in[15];
    const float* Cb   = (const float*)d_in[16];
    const float* h_g  = (const float*)d_in[17];
    const float* h_bt = (const float*)d_in[18];
    const float* e_g  = (const float*)d_in[19];
    const float* e_bt = (const float*)d_in[20];
    const float* f1w  = (const float*)d_in[21];
    const float* f1b  = (const float*)d_in[22];
    const float* f2w  = (const float*)d_in[23];
    const float* f2b  = (const float*)d_in[24];
    const float* f3w  = (const float*)d_in[25];
    const float* f3b  = (const float*)d_in[26];
    float* out = (float*)d_out;

    const int* src = eidx;        // edge_index[0]: scatter target
    const int* dst = eidx + EE;   // edge_index[1]: gather source

    static bool attr_done = false;
    if (!attr_done){
        cudaFuncSetAttribute(k_mma_gemm,      cudaFuncAttributeMaxDynamicSharedMemorySize, SZ_GEMM);
        cudaFuncSetAttribute(k_edge_mma<0,1>, cudaFuncAttributeMaxDynamicSharedMemorySize, SZ_EDGE);
        cudaFuncSetAttribute(k_edge_mma<1,1>, cudaFuncAttributeMaxDynamicSharedMemorySize, SZ_EDGE);
        cudaFuncSetAttribute(k_edge_mma<1,0>, cudaFuncAttributeMaxDynamicSharedMemorySize, SZ_EDGE);
        cudaFuncSetAttribute(k_final_mma,     cudaFuncAttributeMaxDynamicSharedMemorySize, SZ_FIN);
        attr_done = true;
    }

    void* p;
    cudaGetSymbolAddress(&p, g_agg);   float* pagg  = (float*)p;
    cudaGetSymbolAddress(&p, g_tmp);   float* ptmp  = (float*)p;
    cudaGetSymbolAddress(&p, g_cnti);  int*   pcnti = (int*)p;
    cudaGetSymbolAddress(&p, g_stats); float* pst   = (float*)p;
    cudaGetSymbolAddress(&p, g_scale); float* psc   = (float*)p;
    cudaGetSymbolAddress(&p, g_shift); float* psh   = (float*)p;
    cudaGetSymbolAddress(&p, g_h);     float* ph    = (float*)p;
    cudaGetSymbolAddress(&p, g_Uh);    float* pUh   = (float*)p;
    cudaGetSymbolAddress(&p, g_Vh);    float* pVh   = (float*)p;
    cudaGetSymbolAddress(&p, g_Bh);    float* pBh   = (float*)p;
    cudaGetSymbolAddress(&p, g_Ch);    float* pCh   = (float*)p;
    cudaGetSymbolAddress(&p, g_wimg);  unsigned short* pw = (unsigned short*)p;

    // weight prep: slots U:0-1 V:3-4 A:6-8 B:9-11 C:12-14 f1:15 f2:16
    for (int l = 0; l < 2; l++){
        k_prep<<<DD, DD>>>(Uw + l*DD*DD, 0 + l);
        k_prep<<<DD, DD>>>(Vw + l*DD*DD, 3 + l);
    }
    for (int l = 0; l < 3; l++){
        k_prep<<<DD, DD>>>(Aw + l*DD*DD, 6 + l);
        k_prep<<<DD, DD>>>(Bw + l*DD*DD, 9 + l);
        k_prep<<<DD, DD>>>(Cw + l*DD*DD, 12 + l);
    }
    k_prep<<<DD, DD>>>(f1w, 15);
    k_prep<<<DD, DD>>>(f2w, 16);

    // input projections + counts
    k_init_h<<<NN, DD>>>(x, hp_w, hp_b);
    k_init_e<<<EE, DD>>>(ea, ep_w, ep_b);
    k_zero_i<<<(NN+255)/256, 256>>>(pcnti, NN);
    k_count<<<(EE+255)/256, 256>>>(src);
    k_cntf<<<(NN+255)/256, 256>>>();

    for (int l = 0; l < LL; l++){
        const bool last = (l == LL-1);

        if (!last){
            k_mma_gemm<<<NTN, 256, SZ_GEMM>>>(ph, pw + (size_t)(0+l)*32768, Ub + l*DD, pUh, NN);
            k_mma_gemm<<<NTN, 256, SZ_GEMM>>>(ph, pw + (size_t)(3+l)*32768, Vb + l*DD, pVh, NN);
        }
        k_mma_gemm<<<NTN, 256, SZ_GEMM>>>(ph, pw + (size_t)(9+l)*32768,  Bb + l*DD, pBh, NN);
        k_mma_gemm<<<NTN, 256, SZ_GEMM>>>(ph, pw + (size_t)(12+l)*32768, Cb + l*DD, pCh, NN);

        if (!last) k_zero_f4<<<(NN*DD/4+255)/256, 256>>>((float4*)pagg, NN*DD/4);

        const unsigned short* aimg = pw + (size_t)(6+l)*32768;
        if (l == 0)
            k_edge_mma<0,1><<<NT2, 256, SZ_EDGE>>>(aimg, Ab + l*DD, src, dst, psc+DD, psh+DD);
        else if (!last)
            k_edge_mma<1,1><<<NT2, 256, SZ_EDGE>>>(aimg, Ab + l*DD, src, dst, psc+DD, psh+DD);
        else
            k_edge_mma<1,0><<<NT2, 256, SZ_EDGE>>>(aimg, Ab + l*DD, src, dst, psc+DD, psh+DD);

        k_zero_f<<<1, 256>>>(pst, 2*DD);            // h stats (atomic targets)
        k_eps_reduce<<<2*DD, 256>>>(pst);           // e stats (direct write)
        k_bn_fin<<<1, DD>>>(pst + 2*DD, pst + 3*DD, e_g + l*DD, e_bt + l*DD,
                            (float)EE, psc + DD, psh + DD);
        if (!last){
            k_node_tmp<<<NN, DD>>>();
            k_colstats<256><<<(NN+255)/256, DD>>>(ptmp, NN, pst + 0*DD, pst + 1*DD);
            k_bn_fin<<<1, DD>>>(pst + 0*DD, pst + 1*DD, h_g + l*DD, h_bt + l*DD,
                                (float)NN, psc, psh);
            k_apply4<<<(NN*DD/4+255)/256, 256>>>((float4*)ph, (const float4*)ptmp,
                                                 (const float4*)psc, (const float4*)psh, NN*DD/4);
        }
    }

    // final: fuses layer-2 e BN-apply + 3-layer MLP
    k_final_mma<<<NT2, 256, SZ_FIN>>>(pw + (size_t)15*32768, pw + (size_t)16*32768,
                                      f1b, f2b, f3w, f3b, psc + DD, psh + DD, out);
}

// round 7
// speedup vs baseline: 1.3722x; 1.3722x over previous
#include <cuda_runtime.h>
#include <cuda_bf16.h>
#include <cstdint>
#include <math.h>

#define NN 20000
#define EE 320000
#define DD 128
#define LL 3
#define BN_EPS 1e-5f
#define NT2 2500            // edge tiles (128 edges each)
#define NTN 157             // node tiles (ceil(20000/128))

// shared-tile geometry: bf16 planes [128 rows][128 k] padded to stride 136 (272B)
#define PL 34816            // plane bytes: 128*272
#define OFF_AHI 0
#define OFF_ALO 34816
#define OFF_BHI 69632
#define OFF_BLO 104448
#define SZ_GEMM 139264
#define OFF_SRC 139264
#define OFF_DST 139776
#define OFF_SS  140288
#define OFF_SQ  140800
#define SZ_EDGE 141312
#define OFF_ROW 139264
#define SZ_FIN  139776

// ---------------- scratch (device globals; no allocation) ----------------
__device__ float g_h [NN*DD];
__device__ float g_e [EE*DD];
__device__ float g_et[EE*DD];
__device__ float g_Uh[NN*DD];
__device__ float g_Vh[NN*DD];
__device__ float g_Bh[NN*DD];
__device__ float g_Ch[NN*DD];
__device__ float g_agg[NN*DD];
__device__ float g_tmp[NN*DD];
__device__ float g_cnt[NN];
__device__ int   g_cnti[NN];
__device__ float g_eps[2*DD*NT2];      // edge BN partials
__device__ float g_stats[4*DD];
__device__ float g_scale[2*DD];
__device__ float g_shift[2*DD];
// 17 weight slots: dense [k][n] split planes, hi (16384 ushort) then lo
__device__ unsigned short g_wimg[17*32768];

// ---------------- helpers ----------------
__device__ __forceinline__ float sigm(float v){ return 1.f/(1.f+__expf(-v)); }
__device__ __forceinline__ float silu(float v){ return v*sigm(v); }

__device__ __forceinline__ uint32_t smem_u32(const void* p){
    uint32_t a;
    asm("{ .reg .u64 t; cvta.to.shared.u64 t, %1; cvt.u32.u64 %0, t; }" : "=r"(a) : "l"(p));
    return a;
}
__device__ __forceinline__ void split_bf(float v, __nv_bfloat16& h, __nv_bfloat16& l){
    h = __float2bfloat16(v);
    l = __float2bfloat16(v - __bfloat162float(h));
}
__device__ __forceinline__ unsigned pack_bf2(__nv_bfloat16 a, __nv_bfloat16 b){
    __nv_bfloat162 p = __halves2bfloat162(a, b);
    return *reinterpret_cast<unsigned*>(&p);
}
__device__ __forceinline__ void ldsm4(uint32_t addr, uint32_t r[4]){
    asm volatile("ldmatrix.sync.aligned.m8n8.x4.shared.b16 {%0,%1,%2,%3}, [%4];"
        : "=r"(r[0]), "=r"(r[1]), "=r"(r[2]), "=r"(r[3]) : "r"(addr));
}
__device__ __forceinline__ void ldsm4t(uint32_t addr, uint32_t r[4]){
    asm volatile("ldmatrix.sync.aligned.m8n8.x4.trans.shared.b16 {%0,%1,%2,%3}, [%4];"
        : "=r"(r[0]), "=r"(r[1]), "=r"(r[2]), "=r"(r[3]) : "r"(addr));
}
__device__ __forceinline__ void mma16816(float c[4], const uint32_t a[4], uint32_t b0, uint32_t b1){
    asm volatile("mma.sync.aligned.m16n8k16.row.col.f32.bf16.bf16.f32 "
        "{%0,%1,%2,%3}, {%4,%5,%6,%7}, {%8,%9}, {%0,%1,%2,%3};"
        : "+f"(c[0]), "+f"(c[1]), "+f"(c[2]), "+f"(c[3])
        : "r"(a[0]), "r"(a[1]), "r"(a[2]), "r"(a[3]), "r"(b0), "r"(b1));
}
__device__ __forceinline__ void cp16(uint32_t daddr, const void* src){
    asm volatile("cp.async.cg.shared.global [%0], [%1], 16;" :: "r"(daddr), "l"(src));
}
#define CP_COMMIT() asm volatile("cp.async.commit_group;" ::: "memory")
#define CP_WAIT()   asm volatile("cp.async.wait_group 0;" ::: "memory")

// warp-tiled split-bf16 GEMM core (512 threads / 16 warps, 32x32 warp tiles):
// acc[2][4][4] = A[128x128] @ B[128x128]; offA/offB = hi-plane offsets (lo at +PL)
__device__ __forceinline__ void gemm_core(uint32_t sb, int offA, int offB, int t,
                                          float acc[2][4][4]){
    const int lane = t & 31, wid = t >> 5;
    const int wm = wid >> 2, wn = wid & 3;
    uint32_t aBase = sb + offA + (uint32_t)(wm*32 + (lane&7) + ((lane>>3)&1)*8)*272
                   + (uint32_t)((lane>>4)*8)*2;
    uint32_t bBase = sb + offB + (uint32_t)((lane&7) + ((lane>>3)&1)*8)*272
                   + (uint32_t)(wn*32 + (lane>>4)*8)*2;
    #pragma unroll
    for (int kt = 0; kt < 8; kt++){
        uint32_t a0h[4], a1h[4], a0l[4], a1l[4];
        ldsm4(aBase + kt*32,                 a0h);
        ldsm4(aBase + 16*272 + kt*32,        a1h);
        ldsm4(aBase + PL + kt*32,            a0l);
        ldsm4(aBase + PL + 16*272 + kt*32,   a1l);
        uint32_t bh[2][4], bl[2][4];
        #pragma unroll
        for (int np = 0; np < 2; np++){
            ldsm4t(bBase + kt*4352 + np*32,      bh[np]);
            ldsm4t(bBase + PL + kt*4352 + np*32, bl[np]);
        }
        #pragma unroll
        for (int mt = 0; mt < 2; mt++){
            const uint32_t* Ah = mt ? a1h : a0h;
            const uint32_t* Al = mt ? a1l : a0l;
            #pragma unroll
            for (int np = 0; np < 2; np++){
                #pragma unroll
                for (int sub = 0; sub < 2; sub++){
                    float* c = acc[mt][np*2 + sub];
                    uint32_t h0 = bh[np][sub*2], h1 = bh[np][sub*2+1];
                    mma16816(c, Ah, h0, h1);
                    mma16816(c, Ah, bl[np][sub*2], bl[np][sub*2+1]);
                    mma16816(c, Al, h0, h1);
                }
            }
        }
    }
}

// async copy of a prepped weight slot into padded smem planes (512 threads)
__device__ __forceinline__ void copy_w_async(uint32_t sb, int offB,
                                             const unsigned short* wslot, int t){
    const uint4* hi = (const uint4*)wslot;
    const uint4* lo = (const uint4*)(wslot + 16384);
    #pragma unroll
    for (int i = t; i < 2048; i += 512){
        int r = i >> 4, c = i & 15;
        uint32_t d = sb + offB + (uint32_t)(r*17 + c)*16;
        cp16(d,      hi + i);
        cp16(d + PL, lo + i);
    }
}

// ---------------- weight prep: fp32 [k][n] -> split bf16 dense planes ----------------
__global__ void k_prep(const float* __restrict__ W, int slot){
    int k = blockIdx.x, n = threadIdx.x;
    unsigned short* base = g_wimg + (size_t)slot*32768;
    __nv_bfloat16 h, l; split_bf(W[k*DD + n], h, l);
    base[k*DD + n]         = __bfloat16_as_ushort(h);
    base[16384 + k*DD + n] = __bfloat16_as_ushort(l);
}

// ---------------- small kernels ----------------
__global__ void k_zero_f4(float4* p, int n){
    int i = blockIdx.x*blockDim.x + threadIdx.x;
    if (i < n) p[i] = make_float4(0.f,0.f,0.f,0.f);
}
__global__ void k_zero_i(int* p, int n){
    int i = blockIdx.x*blockDim.x + threadIdx.x;
    if (i < n) p[i] = 0;
}
__global__ void k_count(const int* __restrict__ src){
    int i = blockIdx.x*blockDim.x + threadIdx.x;
    if (i < EE) atomicAdd(&g_cnti[src[i]], 1);
}
__global__ void k_cntf(){
    int i = blockIdx.x*blockDim.x + threadIdx.x;
    if (i < NN) g_cnt[i] = fmaxf((float)g_cnti[i], 1.f);
}
__global__ void k_init_h(const float* __restrict__ x,
                         const float* __restrict__ hw, const float* __restrict__ hb){
    int n = blockIdx.x, d = threadIdx.x;
    float v = fmaf(x[n*2+0], hw[d], fmaf(x[n*2+1], hw[DD+d], hb[d]));
    g_h[n*DD+d] = silu(v);
}
__global__ void k_init_e(const float* __restrict__ ea,
                         const float* __restrict__ ew, const float* __restrict__ eb){
    int e = blockIdx.x, d = threadIdx.x;
    float v = fmaf(ea[e], ew[d], eb[d]);
    g_e[e*DD+d] = silu(v);
}
// fused: tmp = Uh + agg/cnt (write) + column stats into pst[0:2DD]
template<int R>
__global__ void k_node_tmp_stats(float* __restrict__ pst){
    const int d = threadIdx.x;
    const int r0 = blockIdx.x * R;
    const int r1 = min(NN, r0 + R);
    float s = 0.f, q = 0.f;
    for (int r = r0; r < r1; r++){
        float v = g_Uh[(size_t)r*DD + d] + g_agg[(size_t)r*DD + d] / g_cnt[r];
        g_tmp[(size_t)r*DD + d] = v;
        s += v; q = fmaf(v, v, q);
    }
    atomicAdd(&pst[d], s);
    atomicAdd(&pst[DD+d], q);
}
__global__ void k_bn_fin(const float* __restrict__ sum, const float* __restrict__ sumsq,
                         const float* __restrict__ gamma, const float* __restrict__ beta,
                         float rows, float* __restrict__ scale, float* __restrict__ shift){
    int d = threadIdx.x;
    float m   = sum[d] / rows;
    float var = sumsq[d] / rows - m*m;
    float inv = rsqrtf(var + BN_EPS);
    float sc  = inv * gamma[d];
    scale[d] = sc;
    shift[d] = beta[d] - m*sc;
}
__global__ void k_apply4(float4* __restrict__ base, const float4* __restrict__ X,
                         const float4* __restrict__ sc4, const float4* __restrict__ sh4, int n4){
    int i = blockIdx.x*blockDim.x + threadIdx.x;
    if (i >= n4) return;
    int c = i & 31;
    float4 x = X[i], s = sc4[c], h = sh4[c], b = base[i];
    b.x += silu(fmaf(x.x, s.x, h.x));
    b.y += silu(fmaf(x.y, s.y, h.y));
    b.z += silu(fmaf(x.z, s.z, h.z));
    b.w += silu(fmaf(x.w, s.w, h.w));
    base[i] = b;
}
// reduce edge BN partials -> pst[2DD:4DD]; also zeroes pst[row] (h-stat slots)
__global__ void k_eps_reduce(float* __restrict__ pst){
    const int row = blockIdx.x;   // 0..255
    if (threadIdx.x == 0) pst[row] = 0.f;
    const float* p = g_eps + (size_t)row*NT2;
    float s = 0.f;
    for (int i = threadIdx.x; i < NT2; i += 256) s += p[i];
    __shared__ float red[256];
    red[threadIdx.x] = s; __syncthreads();
    for (int o = 128; o > 0; o >>= 1){
        if (threadIdx.x < o) red[threadIdx.x] += red[threadIdx.x + o];
        __syncthreads();
    }
    if (threadIdx.x == 0){
        if (row < DD) pst[2*DD + row]      = red[0];
        else          pst[3*DD + (row-DD)] = red[0];
    }
}

// ---------------- merged node GEMM: out_y = A @ W_y + b_y (grid.y selects) ----------------
__global__ void __launch_bounds__(512,1) k_mma_gemm4(const float* __restrict__ A,
        const unsigned short* __restrict__ w0, const unsigned short* __restrict__ w1,
        const unsigned short* __restrict__ w2, const unsigned short* __restrict__ w3,
        const float* __restrict__ b0, const float* __restrict__ b1,
        const float* __restrict__ b2, const float* __restrict__ b3,
        float* __restrict__ o0, float* __restrict__ o1,
        float* __restrict__ o2, float* __restrict__ o3, int rows){
    extern __shared__ __align__(16) char smem[];
    uint32_t sb = smem_u32(smem);
    const int t = threadIdx.x, lane = t & 31, wid = t >> 5;
    const int wm = wid >> 2, wn = wid & 3;
    const int row0 = blockIdx.x * 128;
    const int y = blockIdx.y;
    const unsigned short* wslot = (y==0) ? w0 : (y==1) ? w1 : (y==2) ? w2 : w3;
    const float* bias           = (y==0) ? b0 : (y==1) ? b1 : (y==2) ? b2 : b3;
    float* out                  = (y==0) ? o0 : (y==1) ? o1 : (y==2) ? o2 : o3;

    copy_w_async(sb, OFF_BHI, wslot, t);
    CP_COMMIT();

    const float4* A4 = (const float4*)A;
    #pragma unroll
    for (int it = 0; it < 8; it++){
        int idx = it*512 + t;
        int r = idx >> 5, c4 = idx & 31;
        float4 v = make_float4(0.f,0.f,0.f,0.f);
        if (row0 + r < rows) v = A4[(size_t)(row0 + r)*32 + c4];
        int off = r*272 + c4*8;
        __nv_bfloat16 h0,l0,h1,l1,h2,l2,h3,l3;
        split_bf(v.x,h0,l0); split_bf(v.y,h1,l1); split_bf(v.z,h2,l2); split_bf(v.w,h3,l3);
        *(unsigned*)(smem + OFF_AHI + off)     = pack_bf2(h0,h1);
        *(unsigned*)(smem + OFF_AHI + off + 4) = pack_bf2(h2,h3);
        *(unsigned*)(smem + OFF_ALO + off)     = pack_bf2(l0,l1);
        *(unsigned*)(smem + OFF_ALO + off + 4) = pack_bf2(l2,l3);
    }
    CP_WAIT();
    __syncthreads();

    float acc[2][4][4];
    #pragma unroll
    for (int i=0;i<2;i++) for(int j=0;j<4;j++) for(int k=0;k<4;k++) acc[i][j][k]=0.f;
    gemm_core(sb, OFF_AHI, OFF_BHI, t, acc);
    __syncthreads();

    // fragments -> smem D [row][col] stride 132 (overlay B region)
    float* sD = (float*)(smem + OFF_BHI);
    #pragma unroll
    for (int mt = 0; mt < 2; mt++){
        int r0 = wm*32 + mt*16 + (lane>>2);
        #pragma unroll
        for (int nt = 0; nt < 4; nt++){
            int c0 = wn*32 + nt*8 + (lane&3)*2;
            float* c = acc[mt][nt];
            *(float2*)&sD[r0*132 + c0]     = make_float2(c[0], c[1]);
            *(float2*)&sD[(r0+8)*132 + c0] = make_float2(c[2], c[3]);
        }
    }
    __syncthreads();

    float4* out4 = (float4*)out;
    #pragma unroll
    for (int it = 0; it < 8; it++){
        int idx = it*512 + t;
        int r = idx >> 5, c4 = idx & 31;
        if (row0 + r < rows){
            float4 v = *(const float4*)&sD[r*132 + c4*4];
            const float4 b = *(const float4*)(bias + c4*4);
            v.x += b.x; v.y += b.y; v.z += b.z; v.w += b.w;
            out4[(size_t)(row0 + r)*32 + c4] = v;
        }
    }
}

// ---------------- fused edge kernel ----------------
template<int APPLY, int DOMSG>
__global__ void __launch_bounds__(512,1) k_edge_mma(const unsigned short* __restrict__ wslot,
                                                    const float* __restrict__ ab,
                                                    const int* __restrict__ src,
                                                    const int* __restrict__ dst,
                                                    const float* __restrict__ scE,
                                                    const float* __restrict__ shE){
    extern __shared__ __align__(16) char smem[];
    uint32_t sb = smem_u32(smem);
    const int t = threadIdx.x, lane = t & 31, wid = t >> 5;
    const int wm = wid >> 2, wn = wid & 3;
    const int blk = blockIdx.x;
    const int e0 = blk * 128;

    copy_w_async(sb, OFF_BHI, wslot, t);
    CP_COMMIT();

    int* shs = (int*)(smem + OFF_SRC);
    int* sht = (int*)(smem + OFF_DST);
    float* sS = (float*)(smem + OFF_SS);
    float* sQ = (float*)(smem + OFF_SQ);
    if (t < 128){ shs[t] = src[e0+t]; sht[t] = dst[e0+t]; sS[t] = 0.f; sQ[t] = 0.f; }

    float4* ge4  = (float4*)g_e;
    const float4* get4 = (const float4*)g_et;
    const float4* sc4 = (const float4*)scE;
    const float4* sh4 = (const float4*)shE;
    #pragma unroll
    for (int it = 0; it < 8; it++){
        int idx = it*512 + t;
        int r = idx >> 5, c4 = idx & 31;
        size_t gi = (size_t)(e0 + r)*32 + c4;
        float4 ev = ge4[gi];
        if (APPLY){
            float4 et = get4[gi], S = sc4[c4], H = sh4[c4];
            ev.x += silu(fmaf(et.x, S.x, H.x));
            ev.y += silu(fmaf(et.y, S.y, H.y));
            ev.z += silu(fmaf(et.z, S.z, H.z));
            ev.w += silu(fmaf(et.w, S.w, H.w));
            ge4[gi] = ev;
        }
        int off = r*272 + c4*8;
        __nv_bfloat16 h0,l0,h1,l1,h2,l2,h3,l3;
        split_bf(ev.x,h0,l0); split_bf(ev.y,h1,l1); split_bf(ev.z,h2,l2); split_bf(ev.w,h3,l3);
        *(unsigned*)(smem + OFF_AHI + off)     = pack_bf2(h0,h1);
        *(unsigned*)(smem + OFF_AHI + off + 4) = pack_bf2(h2,h3);
        *(unsigned*)(smem + OFF_ALO + off)     = pack_bf2(l0,l1);
        *(unsigned*)(smem + OFF_ALO + off + 4) = pack_bf2(l2,l3);
    }
    CP_WAIT();
    __syncthreads();

    float acc[2][4][4];
    #pragma unroll
    for (int i=0;i<2;i++) for(int j=0;j<4;j++) for(int k=0;k<4;k++) acc[i][j][k]=0.f;
    gemm_core(sb, OFF_AHI, OFF_BHI, t, acc);
    __syncthreads();

    // fragments -> smem D transposed [col][row] stride 129 (overlay B region)
    float* sDT = (float*)(smem + OFF_BHI);
    #pragma unroll
    for (int mt = 0; mt < 2; mt++){
        int r0 = wm*32 + mt*16 + (lane>>2);
        #pragma unroll
        for (int nt = 0; nt < 4; nt++){
            int c0 = wn*32 + nt*8 + (lane&3)*2;
            float* c = acc[mt][nt];
            sDT[c0*129 + r0]         = c[0];
            sDT[(c0+1)*129 + r0]     = c[1];
            sDT[c0*129 + r0 + 8]     = c[2];
            sDT[(c0+1)*129 + r0 + 8] = c[3];
        }
    }
    __syncthreads();

    // epilogue: 512 threads, each col handles a 32-row quarter
    const int col = t & 127, qr = t >> 7;
    const float b = ab[col];
    float s = 0.f, q = 0.f;
    #pragma unroll 4
    for (int r = qr*32; r < qr*32 + 32; r++){
        int ss = shs[r], tt = sht[r];
        float d = sDT[col*129 + r] + b + g_Bh[(size_t)ss*DD + col] + g_Ch[(size_t)tt*DD + col];
        g_et[(size_t)(e0 + r)*DD + col] = d;
        s += d; q = fmaf(d, d, q);
        if (DOMSG){
            float eh = __bfloat162float(*(const __nv_bfloat16*)(smem + OFF_AHI + r*272 + col*2));
            float el = __bfloat162float(*(const __nv_bfloat16*)(smem + OFF_ALO + r*272 + col*2));
            atomicAdd(&g_agg[(size_t)ss*DD + col], sigm(eh + el) * g_Vh[(size_t)tt*DD + col]);
        }
    }
    atomicAdd(&sS[col], s);
    atomicAdd(&sQ[col], q);
    __syncthreads();
    if (t < 128){
        g_eps[(size_t)col*NT2 + blk]      = sS[col];
        g_eps[(size_t)(DD+col)*NT2 + blk] = sQ[col];
    }
}

// ---------------- fused final: e-apply -> MLP(2 GEMMs) -> sigmoid dot ----------------
__global__ void __launch_bounds__(512,1) k_final_mma(const unsigned short* __restrict__ w1,
                                                     const unsigned short* __restrict__ w2,
                                                     const float* __restrict__ f1b,
                                                     const float* __restrict__ f2b,
                                                     const float* __restrict__ f3w,
                                                     const float* __restrict__ f3b,
                                                     const float* __restrict__ scE,
                                                     const float* __restrict__ shE,
                                                     float* __restrict__ out){
    extern __shared__ __align__(16) char smem[];
    uint32_t sb = smem_u32(smem);
    const int t = threadIdx.x, lane = t & 31, wid = t >> 5;
    const int wm = wid >> 2, wn = wid & 3;
    const int e0 = blockIdx.x * 128;

    float* sRow = (float*)(smem + OFF_ROW);
    if (t < 128) sRow[t] = 0.f;

    copy_w_async(sb, OFF_BHI, w1, t);
    CP_COMMIT();

    const float4* ge4  = (const float4*)g_e;
    const float4* get4 = (const float4*)g_et;
    const float4* sc4  = (const float4*)scE;
    const float4* sh4  = (const float4*)shE;
    #pragma unroll
    for (int it = 0; it < 8; it++){
        int idx = it*512 + t;
        int r = idx >> 5, c4 = idx & 31;
        size_t gi = (size_t)(e0 + r)*32 + c4;
        float4 ev = ge4[gi];
        float4 et = get4[gi], S = sc4[c4], H = sh4[c4];
        ev.x += silu(fmaf(et.x, S.x, H.x));
        ev.y += silu(fmaf(et.y, S.y, H.y));
        ev.z += silu(fmaf(et.z, S.z, H.z));
        ev.w += silu(fmaf(et.w, S.w, H.w));
        int off = r*272 + c4*8;
        __nv_bfloat16 h0,l0,h1,l1,h2,l2,h3,l3;
        split_bf(ev.x,h0,l0); split_bf(ev.y,h1,l1); split_bf(ev.z,h2,l2); split_bf(ev.w,h3,l3);
        *(unsigned*)(smem + OFF_AHI + off)     = pack_bf2(h0,h1);
        *(unsigned*)(smem + OFF_AHI + off + 4) = pack_bf2(h2,h3);
        *(unsigned*)(smem + OFF_ALO + off)     = pack_bf2(l0,l1);
        *(unsigned*)(smem + OFF_ALO + off + 4) = pack_bf2(l2,l3);
    }
    CP_WAIT();
    __syncthreads();

    float acc[2][4][4];
    #pragma unroll
    for (int i=0;i<2;i++) for(int j=0;j<4;j++) for(int k=0;k<4;k++) acc[i][j][k]=0.f;
    gemm_core(sb, OFF_AHI, OFF_BHI, t, acc);
    __syncthreads();   // everyone done reading A & B planes

    // stage1 epilogue: silu -> split bf16 from fragments into B region
    // (acts as A planes for GEMM 2); W2 async-loads into A region.
    copy_w_async(sb, OFF_AHI, w2, t);
    CP_COMMIT();
    #pragma unroll
    for (int mt = 0; mt < 2; mt++){
        int r0 = wm*32 + mt*16 + (lane>>2);
        #pragma unroll
        for (int nt = 0; nt < 4; nt++){
            int c0 = wn*32 + nt*8 + (lane&3)*2;
            float* c = acc[mt][nt];
            float v0 = silu(c[0] + f1b[c0]);
            float v1 = silu(c[1] + f1b[c0+1]);
            float v2 = silu(c[2] + f1b[c0]);
            float v3 = silu(c[3] + f1b[c0+1]);
            __nv_bfloat16 h0,l0,h1,l1;
            split_bf(v0,h0,l0); split_bf(v1,h1,l1);
            *(unsigned*)(smem + OFF_BHI + r0*272 + c0*2) = pack_bf2(h0,h1);
            *(unsigned*)(smem + OFF_BLO + r0*272 + c0*2) = pack_bf2(l0,l1);
            split_bf(v2,h0,l0); split_bf(v3,h1,l1);
            *(unsigned*)(smem + OFF_BHI + (r0+8)*272 + c0*2) = pack_bf2(h0,h1);
            *(unsigned*)(smem + OFF_BLO + (r0+8)*272 + c0*2) = pack_bf2(l0,l1);
        }
    }
    CP_WAIT();
    __syncthreads();

    #pragma unroll
    for (int i=0;i<2;i++) for(int j=0;j<4;j++) for(int k=0;k<4;k++) acc[i][j][k]=0.f;
    gemm_core(sb, OFF_BHI, OFF_AHI, t, acc);

    // stage3: silu(+f2b)*f3w, reduce per row
    #pragma unroll
    for (int mt = 0; mt < 2; mt++){
        float r0s = 0.f, r1s = 0.f;
        #pragma unroll
        for (int nt = 0; nt < 4; nt++){
            int c0 = wn*32 + nt*8 + (lane&3)*2;
            float* c = acc[mt][nt];
            float w0 = f3w[c0], w1 = f3w[c0+1];
            float b0 = f2b[c0], b1 = f2b[c0+1];
            r0s = fmaf(silu(c[0]+b0), w0, fmaf(silu(c[1]+b1), w1, r0s));
            r1s = fmaf(silu(c[2]+b0), w0, fmaf(silu(c[3]+b1), w1, r1s));
        }
        r0s += __shfl_xor_sync(0xffffffff, r0s, 1);
        r0s += __shfl_xor_sync(0xffffffff, r0s, 2);
        r1s += __shfl_xor_sync(0xffffffff, r1s, 1);
        r1s += __shfl_xor_sync(0xffffffff, r1s, 2);
        if ((lane & 3) == 0){
            int r0 = wm*32 + mt*16 + (lane>>2);
            atomicAdd(&sRow[r0], r0s);
            atomicAdd(&sRow[r0+8], r1s);
        }
    }
    __syncthreads();
    if (t < 128) out[e0 + t] = sigm(sRow[t] + f3b[0]);
}

// ---------------- host orchestration ----------------
extern "C" void kernel_launch(void* const* d_in, const int* in_sizes, int n_in,
                              void* d_out, int out_size){
    const float* x    = (const float*)d_in[0];
    const float* ea   = (const float*)d_in[1];
    const int*   eidx = (const int*)  d_in[2];
    const float* hp_w = (const float*)d_in[3];
    const float* hp_b = (const float*)d_in[4];
    const float* ep_w = (const float*)d_in[5];
    const float* ep_b = (const float*)d_in[6];
    const float* Uw   = (const float*)d_in[7];
    const float* Ub   = (const float*)d_in[8];
    const float* Vw   = (const float*)d_in[9];
    const float* Vb   = (const float*)d_in[10];
    const float* Aw   = (const float*)d_in[11];
    const float* Ab   = (const float*)d_in[12];
    const float* Bw   = (const float*)d_in[13];
    const float* Bb   = (const float*)d_in[14];
    const float* Cw   = (const float*)d_in[15];
    const float* Cb   = (const float*)d_in[16];
    const float* h_g  = (const float*)d_in[17];
    const float* h_bt = (const float*)d_in[18];
    const float* e_g  = (const float*)d_in[19];
    const float* e_bt = (const float*)d_in[20];
    const float* f1w  = (const float*)d_in[21];
    const float* f1b  = (const float*)d_in[22];
    const float* f2w  = (const float*)d_in[23];
    const float* f2b  = (const float*)d_in[24];
    const float* f3w  = (const float*)d_in[25];
    const float* f3b  = (const float*)d_in[26];
    float* out = (float*)d_out;

    const int* src = eidx;        // edge_index[0]: scatter target
    const int* dst = eidx + EE;   // edge_index[1]: gather source

    static bool attr_done = false;
    if (!attr_done){
        cudaFuncSetAttribute(k_mma_gemm4,     cudaFuncAttributeMaxDynamicSharedMemorySize, SZ_GEMM);
        cudaFuncSetAttribute(k_edge_mma<0,1>, cudaFuncAttributeMaxDynamicSharedMemorySize, SZ_EDGE);
        cudaFuncSetAttribute(k_edge_mma<1,1>, cudaFuncAttributeMaxDynamicSharedMemorySize, SZ_EDGE);
        cudaFuncSetAttribute(k_edge_mma<1,0>, cudaFuncAttributeMaxDynamicSharedMemorySize, SZ_EDGE);
        cudaFuncSetAttribute(k_final_mma,     cudaFuncAttributeMaxDynamicSharedMemorySize, SZ_FIN);
        attr_done = true;
    }

    void* p;
    cudaGetSymbolAddress(&p, g_agg);   float* pagg  = (float*)p;
    cudaGetSymbolAddress(&p, g_cnti);  int*   pcnti = (int*)p;
    cudaGetSymbolAddress(&p, g_stats); float* pst   = (float*)p;
    cudaGetSymbolAddress(&p, g_scale); float* psc   = (float*)p;
    cudaGetSymbolAddress(&p, g_shift); float* psh   = (float*)p;
    cudaGetSymbolAddress(&p, g_h);     float* ph    = (float*)p;
    cudaGetSymbolAddress(&p, g_Uh);    float* pUh   = (float*)p;
    cudaGetSymbolAddress(&p, g_Vh);    float* pVh   = (float*)p;
    cudaGetSymbolAddress(&p, g_Bh);    float* pBh   = (float*)p;
    cudaGetSymbolAddress(&p, g_Ch);    float* pCh   = (float*)p;
    cudaGetSymbolAddress(&p, g_tmp);   float* ptmp  = (float*)p;
    cudaGetSymbolAddress(&p, g_wimg);  unsigned short* pw = (unsigned short*)p;

    // weight prep: slots U:0-1 V:3-4 A:6-8 B:9-11 C:12-14 f1:15 f2:16
    for (int l = 0; l < 2; l++){
        k_prep<<<DD, DD>>>(Uw + l*DD*DD, 0 + l);
        k_prep<<<DD, DD>>>(Vw + l*DD*DD, 3 + l);
    }
    for (int l = 0; l < 3; l++){
        k_prep<<<DD, DD>>>(Aw + l*DD*DD, 6 + l);
        k_prep<<<DD, DD>>>(Bw + l*DD*DD, 9 + l);
        k_prep<<<DD, DD>>>(Cw + l*DD*DD, 12 + l);
    }
    k_prep<<<DD, DD>>>(f1w, 15);
    k_prep<<<DD, DD>>>(f2w, 16);

    // input projections + counts
    k_init_h<<<NN, DD>>>(x, hp_w, hp_b);
    k_init_e<<<EE, DD>>>(ea, ep_w, ep_b);
    k_zero_i<<<(NN+255)/256, 256>>>(pcnti, NN);
    k_count<<<(EE+255)/256, 256>>>(src);
    k_cntf<<<(NN+255)/256, 256>>>();

    for (int l = 0; l < LL; l++){
        const bool last = (l == LL-1);

        if (!last){
            dim3 grid(NTN, 4);
            k_mma_gemm4<<<grid, 512, SZ_GEMM>>>(ph,
                pw + (size_t)(0+l)*32768, pw + (size_t)(3+l)*32768,
                pw + (size_t)(9+l)*32768, pw + (size_t)(12+l)*32768,
                Ub + l*DD, Vb + l*DD, Bb + l*DD, Cb + l*DD,
                pUh, pVh, pBh, pCh, NN);
            k_zero_f4<<<(NN*DD/4+255)/256, 256>>>((float4*)pagg, NN*DD/4);
        } else {
            dim3 grid(NTN, 2);
            k_mma_gemm4<<<grid, 512, SZ_GEMM>>>(ph,
                pw + (size_t)(9+l)*32768, pw + (size_t)(12+l)*32768,
                pw + (size_t)(9+l)*32768, pw + (size_t)(12+l)*32768,
                Bb + l*DD, Cb + l*DD, Bb + l*DD, Cb + l*DD,
                pBh, pCh, pBh, pCh, NN);
        }

        const unsigned short* aimg = pw + (size_t)(6+l)*32768;
        if (l == 0)
            k_edge_mma<0,1><<<NT2, 512, SZ_EDGE>>>(aimg, Ab + l*DD, src, dst, psc+DD, psh+DD);
        else if (!last)
            k_edge_mma<1,1><<<NT2, 512, SZ_EDGE>>>(aimg, Ab + l*DD, src, dst, psc+DD, psh+DD);
        else
            k_edge_mma<1,0><<<NT2, 512, SZ_EDGE>>>(aimg, Ab + l*DD, src, dst, psc+DD, psh+DD);

        k_eps_reduce<<<2*DD, 256>>>(pst);           // e stats + zero h-stat slots
        k_bn_fin<<<1, DD>>>(pst + 2*DD, pst + 3*DD, e_g + l*DD, e_bt + l*DD,
                            (float)EE, psc + DD, psh + DD);
        if (!last){
            k_node_tmp_stats<256><<<(NN+255)/256, DD>>>(pst);
            k_bn_fin<<<1, DD>>>(pst + 0*DD, pst + 1*DD, h_g + l*DD, h_bt + l*DD,
                                (float)NN, psc, psh);
            k_apply4<<<(NN*DD/4+255)/256, 256>>>((float4*)ph, (const float4*)ptmp,
                                                 (const float4*)psc, (const float4*)psh, NN*DD/4);
        }
    }

    // final: fuses layer-2 e BN-apply + 3-layer MLP
    k_final_mma<<<NT2, 512, SZ_FIN>>>(pw + (size_t)15*32768, pw + (size_t)16*32768,
                                      f1b, f2b, f3w, f3b, psc + DD, psh + DD, out);
}

// round 8
// speedup vs baseline: 1.6639x; 1.2126x over previous
#include <cuda_runtime.h>
#include <cuda_bf16.h>
#include <cstdint>
#include <math.h>

#define NN 20000
#define EE 320000
#define DD 128
#define LL 3
#define BN_EPS 1e-5f
#define NT2 5000            // edge tiles (64 edges each)
#define NTN 313             // node tiles (ceil(20000/64))

// plane geometry: rows padded to 272B (conflict-free ldmatrix)
#define PL  34816           // full plane (128 rows)
#define HPL 17408           // half plane (64 rows)

// half-M kernels (edge, node GEMM): A(2x17408) + W(2x34816); D overlays A
#define H_AHI 0
#define H_ALO 17408
#define H_BHI 34816
#define H_BLO 69632
#define H_SRC 104448
#define H_DST 104704
#define H_SS  104960
#define H_SQ  105472
#define SZ_EDGE 105984
#define SZ_GEMM 104448

// full-size final kernel
#define F_AHI 0
#define F_ALO 34816
#define F_BHI 69632
#define F_BLO 104448
#define F_ROW 139264
#define SZ_FIN 139776

// ---------------- scratch (device globals; no allocation) ----------------
__device__ float g_h [NN*DD];
__device__ float g_e [EE*DD];
__device__ float g_et[EE*DD];
__device__ float g_Uh[NN*DD];
__device__ float g_Vh[NN*DD];
__device__ float g_Bh[NN*DD];
__device__ float g_Ch[NN*DD];
__device__ float g_agg[NN*DD];
__device__ float g_tmp[NN*DD];
__device__ float g_cnt[NN];
__device__ int   g_cnti[NN];
__device__ float g_eps[2*DD*NT2];      // edge BN partials
__device__ float g_stats[4*DD];
__device__ float g_scale[2*DD];
__device__ float g_shift[2*DD];
// 17 weight slots: dense [k][n] split planes, hi (16384 ushort) then lo
__device__ unsigned short g_wimg[17*32768];

// ---------------- helpers ----------------
__device__ __forceinline__ float sigm(float v){ return 1.f/(1.f+__expf(-v)); }
__device__ __forceinline__ float silu(float v){ return v*sigm(v); }

__device__ __forceinline__ uint32_t smem_u32(const void* p){
    uint32_t a;
    asm("{ .reg .u64 t; cvta.to.shared.u64 t, %1; cvt.u32.u64 %0, t; }" : "=r"(a) : "l"(p));
    return a;
}
__device__ __forceinline__ void split_bf(float v, __nv_bfloat16& h, __nv_bfloat16& l){
    h = __float2bfloat16(v);
    l = __float2bfloat16(v - __bfloat162float(h));
}
__device__ __forceinline__ unsigned pack_bf2(__nv_bfloat16 a, __nv_bfloat16 b){
    __nv_bfloat162 p = __halves2bfloat162(a, b);
    return *reinterpret_cast<unsigned*>(&p);
}
__device__ __forceinline__ void ldsm4(uint32_t addr, uint32_t r[4]){
    asm volatile("ldmatrix.sync.aligned.m8n8.x4.shared.b16 {%0,%1,%2,%3}, [%4];"
        : "=r"(r[0]), "=r"(r[1]), "=r"(r[2]), "=r"(r[3]) : "r"(addr));
}
__device__ __forceinline__ void ldsm4t(uint32_t addr, uint32_t r[4]){
    asm volatile("ldmatrix.sync.aligned.m8n8.x4.trans.shared.b16 {%0,%1,%2,%3}, [%4];"
        : "=r"(r[0]), "=r"(r[1]), "=r"(r[2]), "=r"(r[3]) : "r"(addr));
}
__device__ __forceinline__ void mma16816(float c[4], const uint32_t a[4], uint32_t b0, uint32_t b1){
    asm volatile("mma.sync.aligned.m16n8k16.row.col.f32.bf16.bf16.f32 "
        "{%0,%1,%2,%3}, {%4,%5,%6,%7}, {%8,%9}, {%0,%1,%2,%3};"
        : "+f"(c[0]), "+f"(c[1]), "+f"(c[2]), "+f"(c[3])
        : "r"(a[0]), "r"(a[1]), "r"(a[2]), "r"(a[3]), "r"(b0), "r"(b1));
}
__device__ __forceinline__ void cp16(uint32_t daddr, const void* src){
    asm volatile("cp.async.cg.shared.global [%0], [%1], 16;" :: "r"(daddr), "l"(src));
}
#define CP_COMMIT() asm volatile("cp.async.commit_group;" ::: "memory")
#define CP_WAIT()   asm volatile("cp.async.wait_group 0;" ::: "memory")

// warp-tiled split-bf16 GEMM core (512 threads / 16 warps).
// MSUB = 16-row m-subtiles per warp (1 -> M=64 tile, 2 -> M=128 tile).
// APL  = A plane byte size (lo plane at offA+APL). B lo at offB+PL.
template<int MSUB, int APL>
__device__ __forceinline__ void gemm_core(uint32_t sb, int offA, int offB, int t,
                                          float acc[MSUB][4][4]){
    const int lane = t & 31, wid = t >> 5;
    const int wm = wid >> 2, wn = wid & 3;
    uint32_t aBase = sb + offA + (uint32_t)(wm*(16*MSUB) + (lane&7) + ((lane>>3)&1)*8)*272
                   + (uint32_t)((lane>>4)*8)*2;
    uint32_t bBase = sb + offB + (uint32_t)((lane&7) + ((lane>>3)&1)*8)*272
                   + (uint32_t)(wn*32 + (lane>>4)*8)*2;
    #pragma unroll
    for (int kt = 0; kt < 8; kt++){
        uint32_t ah[MSUB][4], al[MSUB][4];
        #pragma unroll
        for (int ms = 0; ms < MSUB; ms++){
            ldsm4(aBase + ms*16*272 + kt*32,       ah[ms]);
            ldsm4(aBase + APL + ms*16*272 + kt*32, al[ms]);
        }
        uint32_t bh[2][4], bl[2][4];
        #pragma unroll
        for (int np = 0; np < 2; np++){
            ldsm4t(bBase + kt*4352 + np*32,      bh[np]);
            ldsm4t(bBase + PL + kt*4352 + np*32, bl[np]);
        }
        #pragma unroll
        for (int ms = 0; ms < MSUB; ms++){
            #pragma unroll
            for (int np = 0; np < 2; np++){
                #pragma unroll
                for (int sub = 0; sub < 2; sub++){
                    float* c = acc[ms][np*2 + sub];
                    uint32_t h0 = bh[np][sub*2], h1 = bh[np][sub*2+1];
                    mma16816(c, ah[ms], h0, h1);
                    mma16816(c, ah[ms], bl[np][sub*2], bl[np][sub*2+1]);
                    mma16816(c, al[ms], h0, h1);
                }
            }
        }
    }
}

// async copy of a prepped weight slot into padded smem planes (512 threads)
__device__ __forceinline__ void copy_w_async(uint32_t sb, int offB,
                                             const unsigned short* wslot, int t){
    const uint4* hi = (const uint4*)wslot;
    const uint4* lo = (const uint4*)(wslot + 16384);
    #pragma unroll
    for (int i = t; i < 2048; i += 512){
        int r = i >> 4, c = i & 15;
        uint32_t d = sb + offB + (uint32_t)(r*17 + c)*16;
        cp16(d,      hi + i);
        cp16(d + PL, lo + i);
    }
}

// ---------------- weight prep: fp32 [k][n] -> split bf16 dense planes ----------------
__global__ void k_prep(const float* __restrict__ W, int slot){
    int k = blockIdx.x, n = threadIdx.x;
    unsigned short* base = g_wimg + (size_t)slot*32768;
    __nv_bfloat16 h, l; split_bf(W[k*DD + n], h, l);
    base[k*DD + n]         = __bfloat16_as_ushort(h);
    base[16384 + k*DD + n] = __bfloat16_as_ushort(l);
}

// ---------------- small kernels ----------------
__global__ void k_zero_f4(float4* p, int n){
    int i = blockIdx.x*blockDim.x + threadIdx.x;
    if (i < n) p[i] = make_float4(0.f,0.f,0.f,0.f);
}
__global__ void k_zero_i(int* p, int n){
    int i = blockIdx.x*blockDim.x + threadIdx.x;
    if (i < n) p[i] = 0;
}
__global__ void k_count(const int* __restrict__ src){
    int i = blockIdx.x*blockDim.x + threadIdx.x;
    if (i < EE) atomicAdd(&g_cnti[src[i]], 1);
}
__global__ void k_cntf(){
    int i = blockIdx.x*blockDim.x + threadIdx.x;
    if (i < NN) g_cnt[i] = fmaxf((float)g_cnti[i], 1.f);
}
__global__ void k_init_h(const float* __restrict__ x,
                         const float* __restrict__ hw, const float* __restrict__ hb){
    int n = blockIdx.x, d = threadIdx.x;
    float v = fmaf(x[n*2+0], hw[d], fmaf(x[n*2+1], hw[DD+d], hb[d]));
    g_h[n*DD+d] = silu(v);
}
__global__ void k_init_e(const float* __restrict__ ea,
                         const float* __restrict__ ew, const float* __restrict__ eb){
    int e = blockIdx.x, d = threadIdx.x;
    float v = fmaf(ea[e], ew[d], eb[d]);
    g_e[e*DD+d] = silu(v);
}
// fused: tmp = Uh + agg/cnt (write) + column stats into pst[0:2DD]
template<int R>
__global__ void k_node_tmp_stats(float* __restrict__ pst){
    const int d = threadIdx.x;
    const int r0 = blockIdx.x * R;
    const int r1 = min(NN, r0 + R);
    float s = 0.f, q = 0.f;
    for (int r = r0; r < r1; r++){
        float v = g_Uh[(size_t)r*DD + d] + g_agg[(size_t)r*DD + d] / g_cnt[r];
        g_tmp[(size_t)r*DD + d] = v;
        s += v; q = fmaf(v, v, q);
    }
    atomicAdd(&pst[d], s);
    atomicAdd(&pst[DD+d], q);
}
__global__ void k_bn_fin(const float* __restrict__ sum, const float* __restrict__ sumsq,
                         const float* __restrict__ gamma, const float* __restrict__ beta,
                         float rows, float* __restrict__ scale, float* __restrict__ shift){
    int d = threadIdx.x;
    float m   = sum[d] / rows;
    float var = sumsq[d] / rows - m*m;
    float inv = rsqrtf(var + BN_EPS);
    float sc  = inv * gamma[d];
    scale[d] = sc;
    shift[d] = beta[d] - m*sc;
}
__global__ void k_apply4(float4* __restrict__ base, const float4* __restrict__ X,
                         const float4* __restrict__ sc4, const float4* __restrict__ sh4, int n4){
    int i = blockIdx.x*blockDim.x + threadIdx.x;
    if (i >= n4) return;
    int c = i & 31;
    float4 x = X[i], s = sc4[c], h = sh4[c], b = base[i];
    b.x += silu(fmaf(x.x, s.x, h.x));
    b.y += silu(fmaf(x.y, s.y, h.y));
    b.z += silu(fmaf(x.z, s.z, h.z));
    b.w += silu(fmaf(x.w, s.w, h.w));
    base[i] = b;
}
// reduce edge BN partials -> pst[2DD:4DD]; also zeroes pst[row] (h-stat slots)
__global__ void k_eps_reduce(float* __restrict__ pst){
    const int row = blockIdx.x;   // 0..255
    if (threadIdx.x == 0) pst[row] = 0.f;
    const float* p = g_eps + (size_t)row*NT2;
    float s = 0.f;
    for (int i = threadIdx.x; i < NT2; i += 256) s += p[i];
    __shared__ float red[256];
    red[threadIdx.x] = s; __syncthreads();
    for (int o = 128; o > 0; o >>= 1){
        if (threadIdx.x < o) red[threadIdx.x] += red[threadIdx.x + o];
        __syncthreads();
    }
    if (threadIdx.x == 0){
        if (row < DD) pst[2*DD + row]      = red[0];
        else          pst[3*DD + (row-DD)] = red[0];
    }
}

// ---------------- merged node GEMM (M=64 tiles, 2 CTAs/SM) ----------------
__global__ void __launch_bounds__(512,2) k_mma_gemm4(const float* __restrict__ A,
        const unsigned short* __restrict__ w0, const unsigned short* __restrict__ w1,
        const unsigned short* __restrict__ w2, const unsigned short* __restrict__ w3,
        const float* __restrict__ b0, const float* __restrict__ b1,
        const float* __restrict__ b2, const float* __restrict__ b3,
        float* __restrict__ o0, float* __restrict__ o1,
        float* __restrict__ o2, float* __restrict__ o3, int rows){
    extern __shared__ __align__(16) char smem[];
    uint32_t sb = smem_u32(smem);
    const int t = threadIdx.x, lane = t & 31, wid = t >> 5;
    const int wm = wid >> 2, wn = wid & 3;
    const int row0 = blockIdx.x * 64;
    const int y = blockIdx.y;
    const unsigned short* wslot = (y==0) ? w0 : (y==1) ? w1 : (y==2) ? w2 : w3;
    const float* bias           = (y==0) ? b0 : (y==1) ? b1 : (y==2) ? b2 : b3;
    float* out                  = (y==0) ? o0 : (y==1) ? o1 : (y==2) ? o2 : o3;

    copy_w_async(sb, H_BHI, wslot, t);
    CP_COMMIT();

    const float4* A4 = (const float4*)A;
    #pragma unroll
    for (int it = 0; it < 4; it++){
        int idx = it*512 + t;
        int r = idx >> 5, c4 = idx & 31;
        float4 v = make_float4(0.f,0.f,0.f,0.f);
        if (row0 + r < rows) v = A4[(size_t)(row0 + r)*32 + c4];
        int off = r*272 + c4*8;
        __nv_bfloat16 h0,l0,h1,l1,h2,l2,h3,l3;
        split_bf(v.x,h0,l0); split_bf(v.y,h1,l1); split_bf(v.z,h2,l2); split_bf(v.w,h3,l3);
        *(unsigned*)(smem + H_AHI + off)     = pack_bf2(h0,h1);
        *(unsigned*)(smem + H_AHI + off + 4) = pack_bf2(h2,h3);
        *(unsigned*)(smem + H_ALO + off)     = pack_bf2(l0,l1);
        *(unsigned*)(smem + H_ALO + off + 4) = pack_bf2(l2,l3);
    }
    CP_WAIT();
    __syncthreads();

    float acc[1][4][4];
    #pragma unroll
    for (int j=0;j<4;j++) for(int k=0;k<4;k++) acc[0][j][k]=0.f;
    gemm_core<1,HPL>(sb, H_AHI, H_BHI, t, acc);
    __syncthreads();

    // fragments -> smem D [row][col] stride 132 (overlay A region)
    float* sD = (float*)(smem + H_AHI);
    {
        int r0 = wm*16 + (lane>>2);
        #pragma unroll
        for (int nt = 0; nt < 4; nt++){
            int c0 = wn*32 + nt*8 + (lane&3)*2;
            float* c = acc[0][nt];
            *(float2*)&sD[r0*132 + c0]     = make_float2(c[0], c[1]);
            *(float2*)&sD[(r0+8)*132 + c0] = make_float2(c[2], c[3]);
        }
    }
    __syncthreads();

    float4* out4 = (float4*)out;
    #pragma unroll
    for (int it = 0; it < 4; it++){
        int idx = it*512 + t;
        int r = idx >> 5, c4 = idx & 31;
        if (row0 + r < rows){
            float4 v = *(const float4*)&sD[r*132 + c4*4];
            const float4 b = *(const float4*)(bias + c4*4);
            v.x += b.x; v.y += b.y; v.z += b.z; v.w += b.w;
            out4[(size_t)(row0 + r)*32 + c4] = v;
        }
    }
}

// ---------------- fused edge kernel (M=64 tiles, 2 CTAs/SM) ----------------
template<int APPLY, int DOMSG>
__global__ void __launch_bounds__(512,2) k_edge_mma(const unsigned short* __restrict__ wslot,
                                                    const float* __restrict__ ab,
                                                    const int* __restrict__ src,
                                                    const int* __restrict__ dst,
                                                    const float* __restrict__ scE,
                                                    const float* __restrict__ shE){
    extern __shared__ __align__(16) char smem[];
    uint32_t sb = smem_u32(smem);
    const int t = threadIdx.x, lane = t & 31, wid = t >> 5;
    const int wm = wid >> 2, wn = wid & 3;
    const int blk = blockIdx.x;
    const int e0 = blk * 64;

    copy_w_async(sb, H_BHI, wslot, t);
    CP_COMMIT();

    int* shs = (int*)(smem + H_SRC);
    int* sht = (int*)(smem + H_DST);
    float* sS = (float*)(smem + H_SS);
    float* sQ = (float*)(smem + H_SQ);
    if (t < 64){ shs[t] = src[e0+t]; sht[t] = dst[e0+t]; }
    if (t < 128){ sS[t] = 0.f; sQ[t] = 0.f; }

    float4* ge4  = (float4*)g_e;
    const float4* get4 = (const float4*)g_et;
    const float4* sc4 = (const float4*)scE;
    const float4* sh4 = (const float4*)shE;
    #pragma unroll
    for (int it = 0; it < 4; it++){
        int idx = it*512 + t;
        int r = idx >> 5, c4 = idx & 31;
        size_t gi = (size_t)(e0 + r)*32 + c4;
        float4 ev = ge4[gi];
        if (APPLY){
            float4 et = get4[gi], S = sc4[c4], H = sh4[c4];
            ev.x += silu(fmaf(et.x, S.x, H.x));
            ev.y += silu(fmaf(et.y, S.y, H.y));
            ev.z += silu(fmaf(et.z, S.z, H.z));
            ev.w += silu(fmaf(et.w, S.w, H.w));
            ge4[gi] = ev;
        }
        int off = r*272 + c4*8;
        __nv_bfloat16 h0,l0,h1,l1,h2,l2,h3,l3;
        split_bf(ev.x,h0,l0); split_bf(ev.y,h1,l1); split_bf(ev.z,h2,l2); split_bf(ev.w,h3,l3);
        *(unsigned*)(smem + H_AHI + off)     = pack_bf2(h0,h1);
        *(unsigned*)(smem + H_AHI + off + 4) = pack_bf2(h2,h3);
        *(unsigned*)(smem + H_ALO + off)     = pack_bf2(l0,l1);
        *(unsigned*)(smem + H_ALO + off + 4) = pack_bf2(l2,l3);
    }
    CP_WAIT();
    __syncthreads();

    float acc[1][4][4];
    #pragma unroll
    for (int j=0;j<4;j++) for(int k=0;k<4;k++) acc[0][j][k]=0.f;
    gemm_core<1,HPL>(sb, H_AHI, H_BHI, t, acc);
    __syncthreads();

    // fragments -> smem D transposed [col][row] stride 65 (overlay A region)
    float* sDT = (float*)(smem + H_AHI);
    {
        int r0 = wm*16 + (lane>>2);
        #pragma unroll
        for (int nt = 0; nt < 4; nt++){
            int c0 = wn*32 + nt*8 + (lane&3)*2;
            float* c = acc[0][nt];
            sDT[c0*65 + r0]         = c[0];
            sDT[(c0+1)*65 + r0]     = c[1];
            sDT[c0*65 + r0 + 8]     = c[2];
            sDT[(c0+1)*65 + r0 + 8] = c[3];
        }
    }
    __syncthreads();

    // epilogue: 512 threads, each col handles a 16-row quarter
    const int col = t & 127, qr = t >> 7;
    const float b = ab[col];
    float s = 0.f, q = 0.f;
    #pragma unroll 4
    for (int r = qr*16; r < qr*16 + 16; r++){
        int ss = shs[r], tt = sht[r];
        float d = sDT[col*65 + r] + b + g_Bh[(size_t)ss*DD + col] + g_Ch[(size_t)tt*DD + col];
        g_et[(size_t)(e0 + r)*DD + col] = d;
        s += d; q = fmaf(d, d, q);
        if (DOMSG){
            float ev = g_e[(size_t)(e0 + r)*DD + col];  // L1/L2 hit (written above)
            atomicAdd(&g_agg[(size_t)ss*DD + col], sigm(ev) * g_Vh[(size_t)tt*DD + col]);
        }
    }
    atomicAdd(&sS[col], s);
    atomicAdd(&sQ[col], q);
    __syncthreads();
    if (t < 128){
        g_eps[(size_t)col*NT2 + blk]      = sS[col];
        g_eps[(size_t)(DD+col)*NT2 + blk] = sQ[col];
    }
}

// ---------------- fused final: e-apply -> MLP(2 GEMMs) -> sigmoid dot (M=128) ----------------
__global__ void __launch_bounds__(512,1) k_final_mma(const unsigned short* __restrict__ w1,
                                                     const unsigned short* __restrict__ w2,
                                                     const float* __restrict__ f1b,
                                                     const float* __restrict__ f2b,
                                                     const float* __restrict__ f3w,
                                                     const float* __restrict__ f3b,
                                                     const float* __restrict__ scE,
                                                     const float* __restrict__ shE,
                                                     float* __restrict__ out){
    extern __shared__ __align__(16) char smem[];
    uint32_t sb = smem_u32(smem);
    const int t = threadIdx.x, lane = t & 31, wid = t >> 5;
    const int wm = wid >> 2, wn = wid & 3;
    const int e0 = blockIdx.x * 128;

    float* sRow = (float*)(smem + F_ROW);
    if (t < 128) sRow[t] = 0.f;

    copy_w_async(sb, F_BHI, w1, t);
    CP_COMMIT();

    const float4* ge4  = (const float4*)g_e;
    const float4* get4 = (const float4*)g_et;
    const float4* sc4  = (const float4*)scE;
    const float4* sh4  = (const float4*)shE;
    #pragma unroll
    for (int it = 0; it < 8; it++){
        int idx = it*512 + t;
        int r = idx >> 5, c4 = idx & 31;
        size_t gi = (size_t)(e0 + r)*32 + c4;
        float4 ev = ge4[gi];
        float4 et = get4[gi], S = sc4[c4], H = sh4[c4];
        ev.x += silu(fmaf(et.x, S.x, H.x));
        ev.y += silu(fmaf(et.y, S.y, H.y));
        ev.z += silu(fmaf(et.z, S.z, H.z));
        ev.w += silu(fmaf(et.w, S.w, H.w));
        int off = r*272 + c4*8;
        __nv_bfloat16 h0,l0,h1,l1,h2,l2,h3,l3;
        split_bf(ev.x,h0,l0); split_bf(ev.y,h1,l1); split_bf(ev.z,h2,l2); split_bf(ev.w,h3,l3);
        *(unsigned*)(smem + F_AHI + off)     = pack_bf2(h0,h1);
        *(unsigned*)(smem + F_AHI + off + 4) = pack_bf2(h2,h3);
        *(unsigned*)(smem + F_ALO + off)     = pack_bf2(l0,l1);
        *(unsigned*)(smem + F_ALO + off + 4) = pack_bf2(l2,l3);
    }
    CP_WAIT();
    __syncthreads();

    float acc[2][4][4];
    #pragma unroll
    for (int i=0;i<2;i++) for(int j=0;j<4;j++) for(int k=0;k<4;k++) acc[i][j][k]=0.f;
    gemm_core<2,PL>(sb, F_AHI, F_BHI, t, acc);
    __syncthreads();   // everyone done reading A & B planes

    // stage1 epilogue: silu -> split bf16 from fragments into B region
    // (acts as A planes for GEMM 2); W2 async-loads into A region.
    copy_w_async(sb, F_AHI, w2, t);
    CP_COMMIT();
    #pragma unroll
    for (int mt = 0; mt < 2; mt++){
        int r0 = wm*32 + mt*16 + (lane>>2);
        #pragma unroll
        for (int nt = 0; nt < 4; nt++){
            int c0 = wn*32 + nt*8 + (lane&3)*2;
            float* c = acc[mt][nt];
            float v0 = silu(c[0] + f1b[c0]);
            float v1 = silu(c[1] + f1b[c0+1]);
            float v2 = silu(c[2] + f1b[c0]);
            float v3 = silu(c[3] + f1b[c0+1]);
            __nv_bfloat16 h0,l0,h1,l1;
            split_bf(v0,h0,l0); split_bf(v1,h1,l1);
            *(unsigned*)(smem + F_BHI + r0*272 + c0*2) = pack_bf2(h0,h1);
            *(unsigned*)(smem + F_BLO + r0*272 + c0*2) = pack_bf2(l0,l1);
            split_bf(v2,h0,l0); split_bf(v3,h1,l1);
            *(unsigned*)(smem + F_BHI + (r0+8)*272 + c0*2) = pack_bf2(h0,h1);
            *(unsigned*)(smem + F_BLO + (r0+8)*272 + c0*2) = pack_bf2(l0,l1);
        }
    }
    CP_WAIT();
    __syncthreads();

    #pragma unroll
    for (int i=0;i<2;i++) for(int j=0;j<4;j++) for(int k=0;k<4;k++) acc[i][j][k]=0.f;
    gemm_core<2,PL>(sb, F_BHI, F_AHI, t, acc);

    // stage3: silu(+f2b)*f3w, reduce per row
    #pragma unroll
    for (int mt = 0; mt < 2; mt++){
        float r0s = 0.f, r1s = 0.f;
        #pragma unroll
        for (int nt = 0; nt < 4; nt++){
            int c0 = wn*32 + nt*8 + (lane&3)*2;
            float* c = acc[mt][nt];
            float w0 = f3w[c0], w1 = f3w[c0+1];
            float b0 = f2b[c0], b1 = f2b[c0+1];
            r0s = fmaf(silu(c[0]+b0), w0, fmaf(silu(c[1]+b1), w1, r0s));
            r1s = fmaf(silu(c[2]+b0), w0, fmaf(silu(c[3]+b1), w1, r1s));
        }
        r0s += __shfl_xor_sync(0xffffffff, r0s, 1);
        r0s += __shfl_xor_sync(0xffffffff, r0s, 2);
        r1s += __shfl_xor_sync(0xffffffff, r1s, 1);
        r1s += __shfl_xor_sync(0xffffffff, r1s, 2);
        if ((lane & 3) == 0){
            int r0 = wm*32 + mt*16 + (lane>>2);
            atomicAdd(&sRow[r0], r0s);
            atomicAdd(&sRow[r0+8], r1s);
        }
    }
    __syncthreads();
    if (t < 128) out[e0 + t] = sigm(sRow[t] + f3b[0]);
}

// ---------------- host orchestration ----------------
extern "C" void kernel_launch(void* const* d_in, const int* in_sizes, int n_in,
                              void* d_out, int out_size){
    const float* x    = (const float*)d_in[0];
    const float* ea   = (const float*)d_in[1];
    const int*   eidx = (const int*)  d_in[2];
    const float* hp_w = (const float*)d_in[3];
    const float* hp_b = (const float*)d_in[4];
    const float* ep_w = (const float*)d_in[5];
    const float* ep_b = (const float*)d_in[6];
    const float* Uw   = (const float*)d_in[7];
    const float* Ub   = (const float*)d_in[8];
    const float* Vw   = (const float*)d_in[9];
    const float* Vb   = (const float*)d_in[10];
    const float* Aw   = (const float*)d_in[11];
    const float* Ab   = (const float*)d_in[12];
    const float* Bw   = (const float*)d_in[13];
    const float* Bb   = (const float*)d_in[14];
    const float* Cw   = (const float*)d_in[15];
    const float* Cb   = (const float*)d_in[16];
    const float* h_g  = (const float*)d_in[17];
    const float* h_bt = (const float*)d_in[18];
    const float* e_g  = (const float*)d_in[19];
    const float* e_bt = (const float*)d_in[20];
    const float* f1w  = (const float*)d_in[21];
    const float* f1b  = (const float*)d_in[22];
    const float* f2w  = (const float*)d_in[23];
    const float* f2b  = (const float*)d_in[24];
    const float* f3w  = (const float*)d_in[25];
    const float* f3b  = (const float*)d_in[26];
    float* out = (float*)d_out;

    const int* src = eidx;        // edge_index[0]: scatter target
    const int* dst = eidx + EE;   // edge_index[1]: gather source

    static bool attr_done = false;
    if (!attr_done){
        cudaFuncSetAttribute(k_mma_gemm4,     cudaFuncAttributeMaxDynamicSharedMemorySize, SZ_GEMM);
        cudaFuncSetAttribute(k_edge_mma<0,1>, cudaFuncAttributeMaxDynamicSharedMemorySize, SZ_EDGE);
        cudaFuncSetAttribute(k_edge_mma<1,1>, cudaFuncAttributeMaxDynamicSharedMemorySize, SZ_EDGE);
        cudaFuncSetAttribute(k_edge_mma<1,0>, cudaFuncAttributeMaxDynamicSharedMemorySize, SZ_EDGE);
        cudaFuncSetAttribute(k_final_mma,     cudaFuncAttributeMaxDynamicSharedMemorySize, SZ_FIN);
        attr_done = true;
    }

    void* p;
    cudaGetSymbolAddress(&p, g_agg);   float* pagg  = (float*)p;
    cudaGetSymbolAddress(&p, g_cnti);  int*   pcnti = (int*)p;
    cudaGetSymbolAddress(&p, g_stats); float* pst   = (float*)p;
    cudaGetSymbolAddress(&p, g_scale); float* psc   = (float*)p;
    cudaGetSymbolAddress(&p, g_shift); float* psh   = (float*)p;
    cudaGetSymbolAddress(&p, g_h);     float* ph    = (float*)p;
    cudaGetSymbolAddress(&p, g_Uh);    float* pUh   = (float*)p;
    cudaGetSymbolAddress(&p, g_Vh);    float* pVh   = (float*)p;
    cudaGetSymbolAddress(&p, g_Bh);    float* pBh   = (float*)p;
    cudaGetSymbolAddress(&p, g_Ch);    float* pCh   = (float*)p;
    cudaGetSymbolAddress(&p, g_tmp);   float* ptmp  = (float*)p;
    cudaGetSymbolAddress(&p, g_wimg);  unsigned short* pw = (unsigned short*)p;

    // weight prep: slots U:0-1 V:3-4 A:6-8 B:9-11 C:12-14 f1:15 f2:16
    for (int l = 0; l < 2; l++){
        k_prep<<<DD, DD>>>(Uw + l*DD*DD, 0 + l);
        k_prep<<<DD, DD>>>(Vw + l*DD*DD, 3 + l);
    }
    for (int l = 0; l < 3; l++){
        k_prep<<<DD, DD>>>(Aw + l*DD*DD, 6 + l);
        k_prep<<<DD, DD>>>(Bw + l*DD*DD, 9 + l);
        k_prep<<<DD, DD>>>(Cw + l*DD*DD, 12 + l);
    }
    k_prep<<<DD, DD>>>(f1w, 15);
    k_prep<<<DD, DD>>>(f2w, 16);

    // input projections + counts
    k_init_h<<<NN, DD>>>(x, hp_w, hp_b);
    k_init_e<<<EE, DD>>>(ea, ep_w, ep_b);
    k_zero_i<<<(NN+255)/256, 256>>>(pcnti, NN);
    k_count<<<(EE+255)/256, 256>>>(src);
    k_cntf<<<(NN+255)/256, 256>>>();

    for (int l = 0; l < LL; l++){
        const bool last = (l == LL-1);

        if (!last){
            dim3 grid(NTN, 4);
            k_mma_gemm4<<<grid, 512, SZ_GEMM>>>(ph,
                pw + (size_t)(0+l)*32768, pw + (size_t)(3+l)*32768,
                pw + (size_t)(9+l)*32768, pw + (size_t)(12+l)*32768,
                Ub + l*DD, Vb + l*DD, Bb + l*DD, Cb + l*DD,
                pUh, pVh, pBh, pCh, NN);
            k_zero_f4<<<(NN*DD/4+255)/256, 256>>>((float4*)pagg, NN*DD/4);
        } else {
            dim3 grid(NTN, 2);
            k_mma_gemm4<<<grid, 512, SZ_GEMM>>>(ph,
                pw + (size_t)(9+l)*32768, pw + (size_t)(12+l)*32768,
                pw + (size_t)(9+l)*32768, pw + (size_t)(12+l)*32768,
                Bb + l*DD, Cb + l*DD, Bb + l*DD, Cb + l*DD,
                pBh, pCh, pBh, pCh, NN);
        }

        const unsigned short* aimg = pw + (size_t)(6+l)*32768;
        if (l == 0)
            k_edge_mma<0,1><<<NT2, 512, SZ_EDGE>>>(aimg, Ab + l*DD, src, dst, psc+DD, psh+DD);
        else if (!last)
            k_edge_mma<1,1><<<NT2, 512, SZ_EDGE>>>(aimg, Ab + l*DD, src, dst, psc+DD, psh+DD);
        else
            k_edge_mma<1,0><<<NT2, 512, SZ_EDGE>>>(aimg, Ab + l*DD, src, dst, psc+DD, psh+DD);

        k_eps_reduce<<<2*DD, 256>>>(pst);           // e stats + zero h-stat slots
        k_bn_fin<<<1, DD>>>(pst + 2*DD, pst + 3*DD, e_g + l*DD, e_bt + l*DD,
                            (float)EE, psc + DD, psh + DD);
        if (!last){
            k_node_tmp_stats<256><<<(NN+255)/256, DD>>>(pst);
            k_bn_fin<<<1, DD>>>(pst + 0*DD, pst + 1*DD, h_g + l*DD, h_bt + l*DD,
                                (float)NN, psc, psh);
            k_apply4<<<(NN*DD/4+255)/256, 256>>>((float4*)ph, (const float4*)ptmp,
                                                 (const float4*)psc, (const float4*)psh, NN*DD/4);
        }
    }

    // final: fuses layer-2 e BN-apply + 3-layer MLP
    k_final_mma<<<NT2/2, 512, SZ_FIN>>>(pw + (size_t)15*32768, pw + (size_t)16*32768,
                                        f1b, f2b, f3w, f3b, psc + DD, psh + DD, out);
}

// round 9
// speedup vs baseline: 1.6977x; 1.0203x over previous
#include <cuda_runtime.h>
#include <cuda_bf16.h>
#include <cstdint>
#include <math.h>

#define NN 20000
#define EE 320000
#define DD 128
#define LL 3
#define BN_EPS 1e-5f
#define NT2 2500            // edge blocks (128 edges = 2x64 tiles each)
#define NTN 157             // node blocks (2x64 rows each)

// plane geometry: rows padded to 272B (conflict-free ldmatrix)
#define PL  34816           // full plane (128 rows)
#define HPL 17408           // half plane (64 rows)

// half-M kernels (edge, node GEMM): A(2x17408) + W(2x34816); D overlays A
#define H_AHI 0
#define H_ALO 17408
#define H_BHI 34816
#define H_BLO 69632
#define H_SRC 104448
#define H_DST 104960
#define H_SS  105472
#define H_SQ  105984
#define SZ_EDGE 106496
#define SZ_GEMM 104448

// full-size final kernel
#define F_AHI 0
#define F_ALO 34816
#define F_BHI 69632
#define F_BLO 104448
#define F_ROW 139264
#define SZ_FIN 139776

// ---------------- scratch (device globals; no allocation) ----------------
__device__ float g_h [NN*DD];
__device__ float g_e [EE*DD];
__device__ float g_et[EE*DD];
__device__ float g_Uh[NN*DD];
__device__ float g_Vh[NN*DD];
__device__ float g_Bh[NN*DD];
__device__ float g_Ch[NN*DD];
__device__ float g_agg[NN*DD];
__device__ float g_tmp[NN*DD];
__device__ float g_cnt[NN];
__device__ int   g_cnti[NN];
__device__ float g_eps[2*DD*NT2];      // edge BN partials
__device__ float g_stats[4*DD];
__device__ float g_scale[2*DD];
__device__ float g_shift[2*DD];
// 17 weight slots: dense [k][n] split planes, hi (16384 ushort) then lo
__device__ unsigned short g_wimg[17*32768];

// ---------------- helpers ----------------
__device__ __forceinline__ float sigm(float v){ return 1.f/(1.f+__expf(-v)); }
__device__ __forceinline__ float silu(float v){ return v*sigm(v); }

__device__ __forceinline__ uint32_t smem_u32(const void* p){
    uint32_t a;
    asm("{ .reg .u64 t; cvta.to.shared.u64 t, %1; cvt.u32.u64 %0, t; }" : "=r"(a) : "l"(p));
    return a;
}
__device__ __forceinline__ void split_bf(float v, __nv_bfloat16& h, __nv_bfloat16& l){
    h = __float2bfloat16(v);
    l = __float2bfloat16(v - __bfloat162float(h));
}
__device__ __forceinline__ unsigned pack_bf2(__nv_bfloat16 a, __nv_bfloat16 b){
    __nv_bfloat162 p = __halves2bfloat162(a, b);
    return *reinterpret_cast<unsigned*>(&p);
}
__device__ __forceinline__ void ldsm4(uint32_t addr, uint32_t r[4]){
    asm volatile("ldmatrix.sync.aligned.m8n8.x4.shared.b16 {%0,%1,%2,%3}, [%4];"
        : "=r"(r[0]), "=r"(r[1]), "=r"(r[2]), "=r"(r[3]) : "r"(addr));
}
__device__ __forceinline__ void ldsm4t(uint32_t addr, uint32_t r[4]){
    asm volatile("ldmatrix.sync.aligned.m8n8.x4.trans.shared.b16 {%0,%1,%2,%3}, [%4];"
        : "=r"(r[0]), "=r"(r[1]), "=r"(r[2]), "=r"(r[3]) : "r"(addr));
}
__device__ __forceinline__ void mma16816(float c[4], const uint32_t a[4], uint32_t b0, uint32_t b1){
    asm volatile("mma.sync.aligned.m16n8k16.row.col.f32.bf16.bf16.f32 "
        "{%0,%1,%2,%3}, {%4,%5,%6,%7}, {%8,%9}, {%0,%1,%2,%3};"
        : "+f"(c[0]), "+f"(c[1]), "+f"(c[2]), "+f"(c[3])
        : "r"(a[0]), "r"(a[1]), "r"(a[2]), "r"(a[3]), "r"(b0), "r"(b1));
}
__device__ __forceinline__ void cp16(uint32_t daddr, const void* src){
    asm volatile("cp.async.cg.shared.global [%0], [%1], 16;" :: "r"(daddr), "l"(src));
}
#define CP_COMMIT() asm volatile("cp.async.commit_group;" ::: "memory")
#define CP_WAIT()   asm volatile("cp.async.wait_group 0;" ::: "memory")

// warp-tiled split-bf16 GEMM core (512 threads / 16 warps).
// MSUB = 16-row m-subtiles per warp; APL = A plane byte size.
template<int MSUB, int APL>
__device__ __forceinline__ void gemm_core(uint32_t sb, int offA, int offB, int t,
                                          float acc[MSUB][4][4]){
    const int lane = t & 31, wid = t >> 5;
    const int wm = wid >> 2, wn = wid & 3;
    uint32_t aBase = sb + offA + (uint32_t)(wm*(16*MSUB) + (lane&7) + ((lane>>3)&1)*8)*272
                   + (uint32_t)((lane>>4)*8)*2;
    uint32_t bBase = sb + offB + (uint32_t)((lane&7) + ((lane>>3)&1)*8)*272
                   + (uint32_t)(wn*32 + (lane>>4)*8)*2;
    #pragma unroll
    for (int kt = 0; kt < 8; kt++){
        uint32_t ah[MSUB][4], al[MSUB][4];
        #pragma unroll
        for (int ms = 0; ms < MSUB; ms++){
            ldsm4(aBase + ms*16*272 + kt*32,       ah[ms]);
            ldsm4(aBase + APL + ms*16*272 + kt*32, al[ms]);
        }
        uint32_t bh[2][4], bl[2][4];
        #pragma unroll
        for (int np = 0; np < 2; np++){
            ldsm4t(bBase + kt*4352 + np*32,      bh[np]);
            ldsm4t(bBase + PL + kt*4352 + np*32, bl[np]);
        }
        #pragma unroll
        for (int ms = 0; ms < MSUB; ms++){
            #pragma unroll
            for (int np = 0; np < 2; np++){
                #pragma unroll
                for (int sub = 0; sub < 2; sub++){
                    float* c = acc[ms][np*2 + sub];
                    uint32_t h0 = bh[np][sub*2], h1 = bh[np][sub*2+1];
                    mma16816(c, ah[ms], h0, h1);
                    mma16816(c, ah[ms], bl[np][sub*2], bl[np][sub*2+1]);
                    mma16816(c, al[ms], h0, h1);
                }
            }
        }
    }
}

// async copy of a prepped weight slot into padded smem planes (512 threads)
__device__ __forceinline__ void copy_w_async(uint32_t sb, int offB,
                                             const unsigned short* wslot, int t){
    const uint4* hi = (const uint4*)wslot;
    const uint4* lo = (const uint4*)(wslot + 16384);
    #pragma unroll
    for (int i = t; i < 2048; i += 512){
        int r = i >> 4, c = i & 15;
        uint32_t d = sb + offB + (uint32_t)(r*17 + c)*16;
        cp16(d,      hi + i);
        cp16(d + PL, lo + i);
    }
}

// stage 64 rows of fp32 into split-bf16 A planes (H_AHI/H_ALO)
__device__ __forceinline__ void stage_tile(char* smem, const float4* __restrict__ X4,
                                           int row0, int rows, int t){
    #pragma unroll
    for (int it = 0; it < 4; it++){
        int idx = it*512 + t;
        int r = idx >> 5, c4 = idx & 31;
        float4 v = make_float4(0.f,0.f,0.f,0.f);
        if (row0 + r < rows) v = X4[(size_t)(row0 + r)*32 + c4];
        int off = r*272 + c4*8;
        __nv_bfloat16 h0,l0,h1,l1,h2,l2,h3,l3;
        split_bf(v.x,h0,l0); split_bf(v.y,h1,l1); split_bf(v.z,h2,l2); split_bf(v.w,h3,l3);
        *(unsigned*)(smem + H_AHI + off)     = pack_bf2(h0,h1);
        *(unsigned*)(smem + H_AHI + off + 4) = pack_bf2(h2,h3);
        *(unsigned*)(smem + H_ALO + off)     = pack_bf2(l0,l1);
        *(unsigned*)(smem + H_ALO + off + 4) = pack_bf2(l2,l3);
    }
}

// ---------------- merged weight prep: fp32 [k][n] -> split bf16 dense planes ----------------
__global__ void k_prep_all(const float* __restrict__ Uw, const float* __restrict__ Vw,
                           const float* __restrict__ Aw, const float* __restrict__ Bw,
                           const float* __restrict__ Cw, const float* __restrict__ f1w,
                           const float* __restrict__ f2w){
    int y = blockIdx.y;
    const float* W; int slot;
    if      (y < 2){ W = Uw + y*DD*DD;      slot = y; }
    else if (y < 4){ W = Vw + (y-2)*DD*DD;  slot = 3 + (y-2); }
    else if (y < 7){ W = Aw + (y-4)*DD*DD;  slot = 6 + (y-4); }
    else if (y < 10){ W = Bw + (y-7)*DD*DD; slot = 9 + (y-7); }
    else if (y < 13){ W = Cw + (y-10)*DD*DD; slot = 12 + (y-10); }
    else if (y == 13){ W = f1w; slot = 15; }
    else            { W = f2w; slot = 16; }
    int k = blockIdx.x, n = threadIdx.x;
    unsigned short* base = g_wimg + (size_t)slot*32768;
    __nv_bfloat16 h, l; split_bf(W[k*DD + n], h, l);
    base[k*DD + n]         = __bfloat16_as_ushort(h);
    base[16384 + k*DD + n] = __bfloat16_as_ushort(l);
}

// ---------------- small kernels ----------------
__global__ void k_zero_f4(float4* p, int n){
    int i = blockIdx.x*blockDim.x + threadIdx.x;
    if (i < n) p[i] = make_float4(0.f,0.f,0.f,0.f);
}
__global__ void k_zero_i(int* p, int n){
    int i = blockIdx.x*blockDim.x + threadIdx.x;
    if (i < n) p[i] = 0;
}
__global__ void k_count(const int* __restrict__ src){
    int i = blockIdx.x*blockDim.x + threadIdx.x;
    if (i < EE) atomicAdd(&g_cnti[src[i]], 1);
}
__global__ void k_cntf(){
    int i = blockIdx.x*blockDim.x + threadIdx.x;
    if (i < NN) g_cnt[i] = fmaxf((float)g_cnti[i], 1.f);
}
__global__ void k_init_h(const float* __restrict__ x,
                         const float* __restrict__ hw, const float* __restrict__ hb){
    int n = blockIdx.x, d = threadIdx.x;
    float v = fmaf(x[n*2+0], hw[d], fmaf(x[n*2+1], hw[DD+d], hb[d]));
    g_h[n*DD+d] = silu(v);
}
__global__ void k_init_e(const float* __restrict__ ea,
                         const float* __restrict__ ew, const float* __restrict__ eb){
    int e = blockIdx.x, d = threadIdx.x;
    float v = fmaf(ea[e], ew[d], eb[d]);
    g_e[e*DD+d] = silu(v);
}
// fused: tmp = Uh + agg/cnt (write) + column stats into pst[0:2DD]
template<int R>
__global__ void k_node_tmp_stats(float* __restrict__ pst){
    const int d = threadIdx.x;
    const int r0 = blockIdx.x * R;
    const int r1 = min(NN, r0 + R);
    float s = 0.f, q = 0.f;
    for (int r = r0; r < r1; r++){
        float v = g_Uh[(size_t)r*DD + d] + g_agg[(size_t)r*DD + d] / g_cnt[r];
        g_tmp[(size_t)r*DD + d] = v;
        s += v; q = fmaf(v, v, q);
    }
    atomicAdd(&pst[d], s);
    atomicAdd(&pst[DD+d], q);
}
__global__ void k_bn_fin(const float* __restrict__ sum, const float* __restrict__ sumsq,
                         const float* __restrict__ gamma, const float* __restrict__ beta,
                         float rows, float* __restrict__ scale, float* __restrict__ shift){
    int d = threadIdx.x;
    float m   = sum[d] / rows;
    float var = sumsq[d] / rows - m*m;
    float inv = rsqrtf(var + BN_EPS);
    float sc  = inv * gamma[d];
    scale[d] = sc;
    shift[d] = beta[d] - m*sc;
}
__global__ void k_apply4(float4* __restrict__ base, const float4* __restrict__ X,
                         const float4* __restrict__ sc4, const float4* __restrict__ sh4, int n4){
    int i = blockIdx.x*blockDim.x + threadIdx.x;
    if (i >= n4) return;
    int c = i & 31;
    float4 x = X[i], s = sc4[c], h = sh4[c], b = base[i];
    b.x += silu(fmaf(x.x, s.x, h.x));
    b.y += silu(fmaf(x.y, s.y, h.y));
    b.z += silu(fmaf(x.z, s.z, h.z));
    b.w += silu(fmaf(x.w, s.w, h.w));
    base[i] = b;
}
// fused edge-BN: reduce partials + compute scale/shift + zero h-stat slots
__global__ void k_ebn(float* __restrict__ pst,
                      const float* __restrict__ gamma, const float* __restrict__ beta,
                      float* __restrict__ scale, float* __restrict__ shift){
    const int d = blockIdx.x;      // 0..127
    __shared__ float red[256];
    float s = 0.f;
    const float* ps = g_eps + (size_t)d*NT2;
    for (int i = threadIdx.x; i < NT2; i += 256) s += ps[i];
    red[threadIdx.x] = s; __syncthreads();
    for (int o = 128; o > 0; o >>= 1){
        if (threadIdx.x < o) red[threadIdx.x] += red[threadIdx.x + o];
        __syncthreads();
    }
    float sum = red[0];
    __syncthreads();
    float q = 0.f;
    const float* pq = g_eps + (size_t)(DD+d)*NT2;
    for (int i = threadIdx.x; i < NT2; i += 256) q += pq[i];
    red[threadIdx.x] = q; __syncthreads();
    for (int o = 128; o > 0; o >>= 1){
        if (threadIdx.x < o) red[threadIdx.x] += red[threadIdx.x + o];
        __syncthreads();
    }
    if (threadIdx.x == 0){
        float sumsq = red[0];
        float m   = sum / (float)EE;
        float var = sumsq / (float)EE - m*m;
        float inv = rsqrtf(var + BN_EPS);
        float sc  = inv * gamma[d];
        scale[d] = sc;
        shift[d] = beta[d] - m*sc;
        pst[d] = 0.f; pst[DD+d] = 0.f;   // pre-zero h-stat slots for this layer
    }
}

// ---------------- merged node GEMM (2x64-row tiles/block, W reused, 2 CTAs/SM) ----------------
__global__ void __launch_bounds__(512,2) k_mma_gemm4(const float* __restrict__ A,
        const unsigned short* __restrict__ w0, const unsigned short* __restrict__ w1,
        const unsigned short* __restrict__ w2, const unsigned short* __restrict__ w3,
        const float* __restrict__ b0, const float* __restrict__ b1,
        const float* __restrict__ b2, const float* __restrict__ b3,
        float* __restrict__ o0, float* __restrict__ o1,
        float* __restrict__ o2, float* __restrict__ o3, int rows){
    extern __shared__ __align__(16) char smem[];
    uint32_t sb = smem_u32(smem);
    const int t = threadIdx.x, lane = t & 31, wid = t >> 5;
    const int wm = wid >> 2, wn = wid & 3;
    const int y = blockIdx.y;
    const unsigned short* wslot = (y==0) ? w0 : (y==1) ? w1 : (y==2) ? w2 : w3;
    const float* bias           = (y==0) ? b0 : (y==1) ? b1 : (y==2) ? b2 : b3;
    float* out                  = (y==0) ? o0 : (y==1) ? o1 : (y==2) ? o2 : o3;

    copy_w_async(sb, H_BHI, wslot, t);
    CP_COMMIT();

    const float4* A4 = (const float4*)A;
    float4* out4 = (float4*)out;

    #pragma unroll
    for (int tile = 0; tile < 2; tile++){
        const int row0 = blockIdx.x * 128 + tile * 64;
        stage_tile(smem, A4, row0, rows, t);
        if (tile == 0) CP_WAIT();
        __syncthreads();

        float acc[1][4][4];
        #pragma unroll
        for (int j=0;j<4;j++) for(int k=0;k<4;k++) acc[0][j][k]=0.f;
        gemm_core<1,HPL>(sb, H_AHI, H_BHI, t, acc);
        __syncthreads();

        // fragments -> smem D [row][col] stride 132 (overlay A region)
        float* sD = (float*)(smem + H_AHI);
        {
            int r0 = wm*16 + (lane>>2);
            #pragma unroll
            for (int nt = 0; nt < 4; nt++){
                int c0 = wn*32 + nt*8 + (lane&3)*2;
                float* c = acc[0][nt];
                *(float2*)&sD[r0*132 + c0]     = make_float2(c[0], c[1]);
                *(float2*)&sD[(r0+8)*132 + c0] = make_float2(c[2], c[3]);
            }
        }
        __syncthreads();

        #pragma unroll
        for (int it = 0; it < 4; it++){
            int idx = it*512 + t;
            int r = idx >> 5, c4 = idx & 31;
            if (row0 + r < rows){
                float4 v = *(const float4*)&sD[r*132 + c4*4];
                const float4 b = *(const float4*)(bias + c4*4);
                v.x += b.x; v.y += b.y; v.z += b.z; v.w += b.w;
                out4[(size_t)(row0 + r)*32 + c4] = v;
            }
        }
        __syncthreads();
    }
}

// ---------------- fused edge kernel (2x64-edge tiles/block, W reused, 2 CTAs/SM) ----------------
template<int APPLY, int DOMSG>
__global__ void __launch_bounds__(512,2) k_edge_mma(const unsigned short* __restrict__ wslot,
                                                    const float* __restrict__ ab,
                                                    const int* __restrict__ src,
                                                    const int* __restrict__ dst,
                                                    const float* __restrict__ scE,
                                                    const float* __restrict__ shE){
    extern __shared__ __align__(16) char smem[];
    uint32_t sb = smem_u32(smem);
    const int t = threadIdx.x, lane = t & 31, wid = t >> 5;
    const int wm = wid >> 2, wn = wid & 3;
    const int blk = blockIdx.x;
    const int e0 = blk * 128;

    copy_w_async(sb, H_BHI, wslot, t);
    CP_COMMIT();

    int* shs = (int*)(smem + H_SRC);
    int* sht = (int*)(smem + H_DST);
    float* sS = (float*)(smem + H_SS);
    float* sQ = (float*)(smem + H_SQ);
    if (t < 128){ shs[t] = src[e0+t]; sht[t] = dst[e0+t]; sS[t] = 0.f; sQ[t] = 0.f; }

    float4* ge4  = (float4*)g_e;
    const float4* get4 = (const float4*)g_et;
    const float4* sc4 = (const float4*)scE;
    const float4* sh4 = (const float4*)shE;

    const int col = t & 127, qr = t >> 7;
    const float b = ab[col];
    float s = 0.f, q = 0.f;

    #pragma unroll
    for (int tile = 0; tile < 2; tile++){
        const int r0g = e0 + tile * 64;
        // stage: optional BN-apply + residual, then split into A planes
        #pragma unroll
        for (int it = 0; it < 4; it++){
            int idx = it*512 + t;
            int r = idx >> 5, c4 = idx & 31;
            size_t gi = (size_t)(r0g + r)*32 + c4;
            float4 ev = ge4[gi];
            if (APPLY){
                float4 et = get4[gi], S = sc4[c4], H = sh4[c4];
                ev.x += silu(fmaf(et.x, S.x, H.x));
                ev.y += silu(fmaf(et.y, S.y, H.y));
                ev.z += silu(fmaf(et.z, S.z, H.z));
                ev.w += silu(fmaf(et.w, S.w, H.w));
                ge4[gi] = ev;
            }
            int off = r*272 + c4*8;
            __nv_bfloat16 h0,l0,h1,l1,h2,l2,h3,l3;
            split_bf(ev.x,h0,l0); split_bf(ev.y,h1,l1); split_bf(ev.z,h2,l2); split_bf(ev.w,h3,l3);
            *(unsigned*)(smem + H_AHI + off)     = pack_bf2(h0,h1);
            *(unsigned*)(smem + H_AHI + off + 4) = pack_bf2(h2,h3);
            *(unsigned*)(smem + H_ALO + off)     = pack_bf2(l0,l1);
            *(unsigned*)(smem + H_ALO + off + 4) = pack_bf2(l2,l3);
        }
        if (tile == 0) CP_WAIT();
        __syncthreads();

        float acc[1][4][4];
        #pragma unroll
        for (int j=0;j<4;j++) for(int k=0;k<4;k++) acc[0][j][k]=0.f;
        gemm_core<1,HPL>(sb, H_AHI, H_BHI, t, acc);
        __syncthreads();

        // fragments -> smem D transposed [col][row] stride 65 (overlay A region)
        float* sDT = (float*)(smem + H_AHI);
        {
            int r0 = wm*16 + (lane>>2);
            #pragma unroll
            for (int nt = 0; nt < 4; nt++){
                int c0 = wn*32 + nt*8 + (lane&3)*2;
                float* c = acc[0][nt];
                sDT[c0*65 + r0]         = c[0];
                sDT[(c0+1)*65 + r0]     = c[1];
                sDT[c0*65 + r0 + 8]     = c[2];
                sDT[(c0+1)*65 + r0 + 8] = c[3];
            }
        }
        __syncthreads();

        // epilogue: each col handles a 16-row quarter of this 64-edge tile
        #pragma unroll 4
        for (int r = qr*16; r < qr*16 + 16; r++){
            int li = tile*64 + r;
            int ss = shs[li], tt = sht[li];
            float d = sDT[col*65 + r] + b + g_Bh[(size_t)ss*DD + col] + g_Ch[(size_t)tt*DD + col];
            g_et[(size_t)(r0g + r)*DD + col] = d;
            s += d; q = fmaf(d, d, q);
            if (DOMSG){
                float ev = g_e[(size_t)(r0g + r)*DD + col];  // L1/L2 hit (just written/read)
                atomicAdd(&g_agg[(size_t)ss*DD + col], sigm(ev) * g_Vh[(size_t)tt*DD + col]);
            }
        }
        __syncthreads();   // sDT consumed before next tile's staging overwrites A
    }

    atomicAdd(&sS[col], s);
    atomicAdd(&sQ[col], q);
    __syncthreads();
    if (t < 128){
        g_eps[(size_t)col*NT2 + blk]      = sS[col];
        g_eps[(size_t)(DD+col)*NT2 + blk] = sQ[col];
    }
}

// ---------------- fused final: e-apply -> MLP(2 GEMMs) -> sigmoid dot (M=128) ----------------
__global__ void __launch_bounds__(512,1) k_final_mma(const unsigned short* __restrict__ w1,
                                                     const unsigned short* __restrict__ w2,
                                                     const float* __restrict__ f1b,
                                                     const float* __restrict__ f2b,
                                                     const float* __restrict__ f3w,
                                                     const float* __restrict__ f3b,
                                                     const float* __restrict__ scE,
                                                     const float* __restrict__ shE,
                                                     float* __restrict__ out){
    extern __shared__ __align__(16) char smem[];
    uint32_t sb = smem_u32(smem);
    const int t = threadIdx.x, lane = t & 31, wid = t >> 5;
    const int wm = wid >> 2, wn = wid & 3;
    const int e0 = blockIdx.x * 128;

    float* sRow = (float*)(smem + F_ROW);
    if (t < 128) sRow[t] = 0.f;

    copy_w_async(sb, F_BHI, w1, t);
    CP_COMMIT();

    const float4* ge4  = (const float4*)g_e;
    const float4* get4 = (const float4*)g_et;
    const float4* sc4  = (const float4*)scE;
    const float4* sh4  = (const float4*)shE;
    #pragma unroll
    for (int it = 0; it < 8; it++){
        int idx = it*512 + t;
        int r = idx >> 5, c4 = idx & 31;
        size_t gi = (size_t)(e0 + r)*32 + c4;
        float4 ev = ge4[gi];
        float4 et = get4[gi], S = sc4[c4], H = sh4[c4];
        ev.x += silu(fmaf(et.x, S.x, H.x));
        ev.y += silu(fmaf(et.y, S.y, H.y));
        ev.z += silu(fmaf(et.z, S.z, H.z));
        ev.w += silu(fmaf(et.w, S.w, H.w));
        int off = r*272 + c4*8;
        __nv_bfloat16 h0,l0,h1,l1,h2,l2,h3,l3;
        split_bf(ev.x,h0,l0); split_bf(ev.y,h1,l1); split_bf(ev.z,h2,l2); split_bf(ev.w,h3,l3);
        *(unsigned*)(smem + F_AHI + off)     = pack_bf2(h0,h1);
        *(unsigned*)(smem + F_AHI + off + 4) = pack_bf2(h2,h3);
        *(unsigned*)(smem + F_ALO + off)     = pack_bf2(l0,l1);
        *(unsigned*)(smem + F_ALO + off + 4) = pack_bf2(l2,l3);
    }
    CP_WAIT();
    __syncthreads();

    float acc[2][4][4];
    #pragma unroll
    for (int i=0;i<2;i++) for(int j=0;j<4;j++) for(int k=0;k<4;k++) acc[i][j][k]=0.f;
    gemm_core<2,PL>(sb, F_AHI, F_BHI, t, acc);
    __syncthreads();   // everyone done reading A & B planes

    // stage1 epilogue: silu -> split bf16 from fragments into B region
    // (acts as A planes for GEMM 2); W2 async-loads into A region.
    copy_w_async(sb, F_AHI, w2, t);
    CP_COMMIT();
    #pragma unroll
    for (int mt = 0; mt < 2; mt++){
        int r0 = wm*32 + mt*16 + (lane>>2);
        #pragma unroll
        for (int nt = 0; nt < 4; nt++){
            int c0 = wn*32 + nt*8 + (lane&3)*2;
            float* c = acc[mt][nt];
            float v0 = silu(c[0] + f1b[c0]);
            float v1 = silu(c[1] + f1b[c0+1]);
            float v2 = silu(c[2] + f1b[c0]);
            float v3 = silu(c[3] + f1b[c0+1]);
            __nv_bfloat16 h0,l0,h1,l1;
            split_bf(v0,h0,l0); split_bf(v1,h1,l1);
            *(unsigned*)(smem + F_BHI + r0*272 + c0*2) = pack_bf2(h0,h1);
            *(unsigned*)(smem + F_BLO + r0*272 + c0*2) = pack_bf2(l0,l1);
            split_bf(v2,h0,l0); split_bf(v3,h1,l1);
            *(unsigned*)(smem + F_BHI + (r0+8)*272 + c0*2) = pack_bf2(h0,h1);
            *(unsigned*)(smem + F_BLO + (r0+8)*272 + c0*2) = pack_bf2(l0,l1);
        }
    }
    CP_WAIT();
    __syncthreads();

    #pragma unroll
    for (int i=0;i<2;i++) for(int j=0;j<4;j++) for(int k=0;k<4;k++) acc[i][j][k]=0.f;
    gemm_core<2,PL>(sb, F_BHI, F_AHI, t, acc);

    // stage3: silu(+f2b)*f3w, reduce per row
    #pragma unroll
    for (int mt = 0; mt < 2; mt++){
        float r0s = 0.f, r1s = 0.f;
        #pragma unroll
        for (int nt = 0; nt < 4; nt++){
            int c0 = wn*32 + nt*8 + (lane&3)*2;
            float* c = acc[mt][nt];
            float w0 = f3w[c0], w1 = f3w[c0+1];
            float b0 = f2b[c0], b1 = f2b[c0+1];
            r0s = fmaf(silu(c[0]+b0), w0, fmaf(silu(c[1]+b1), w1, r0s));
            r1s = fmaf(silu(c[2]+b0), w0, fmaf(silu(c[3]+b1), w1, r1s));
        }
        r0s += __shfl_xor_sync(0xffffffff, r0s, 1);
        r0s += __shfl_xor_sync(0xffffffff, r0s, 2);
        r1s += __shfl_xor_sync(0xffffffff, r1s, 1);
        r1s += __shfl_xor_sync(0xffffffff, r1s, 2);
        if ((lane & 3) == 0){
            int r0 = wm*32 + mt*16 + (lane>>2);
            atomicAdd(&sRow[r0], r0s);
            atomicAdd(&sRow[r0+8], r1s);
        }
    }
    __syncthreads();
    if (t < 128) out[e0 + t] = sigm(sRow[t] + f3b[0]);
}

// ---------------- host orchestration ----------------
extern "C" void kernel_launch(void* const* d_in, const int* in_sizes, int n_in,
                              void* d_out, int out_size){
    const float* x    = (const float*)d_in[0];
    const float* ea   = (const float*)d_in[1];
    const int*   eidx = (const int*)  d_in[2];
    const float* hp_w = (const float*)d_in[3];
    const float* hp_b = (const float*)d_in[4];
    const float* ep_w = (const float*)d_in[5];
    const float* ep_b = (const float*)d_in[6];
    const float* Uw   = (const float*)d_in[7];
    const float* Ub   = (const float*)d_in[8];
    const float* Vw   = (const float*)d_in[9];
    const float* Vb   = (const float*)d_in[10];
    const float* Aw   = (const float*)d_in[11];
    const float* Ab   = (const float*)d_in[12];
    const float* Bw   = (const float*)d_in[13];
    const float* Bb   = (const float*)d_in[14];
    const float* Cw   = (const float*)d_in[15];
    const float* Cb   = (const float*)d_in[16];
    const float* h_g  = (const float*)d_in[17];
    const float* h_bt = (const float*)d_in[18];
    const float* e_g  = (const float*)d_in[19];
    const float* e_bt = (const float*)d_in[20];
    const float* f1w  = (const float*)d_in[21];
    const float* f1b  = (const float*)d_in[22];
    const float* f2w  = (const float*)d_in[23];
    const float* f2b  = (const float*)d_in[24];
    const float* f3w  = (const float*)d_in[25];
    const float* f3b  = (const float*)d_in[26];
    float* out = (float*)d_out;

    const int* src = eidx;        // edge_index[0]: scatter target
    const int* dst = eidx + EE;   // edge_index[1]: gather source

    static bool attr_done = false;
    if (!attr_done){
        cudaFuncSetAttribute(k_mma_gemm4,     cudaFuncAttributeMaxDynamicSharedMemorySize, SZ_GEMM);
        cudaFuncSetAttribute(k_edge_mma<0,1>, cudaFuncAttributeMaxDynamicSharedMemorySize, SZ_EDGE);
        cudaFuncSetAttribute(k_edge_mma<1,1>, cudaFuncAttributeMaxDynamicSharedMemorySize, SZ_EDGE);
        cudaFuncSetAttribute(k_edge_mma<1,0>, cudaFuncAttributeMaxDynamicSharedMemorySize, SZ_EDGE);
        cudaFuncSetAttribute(k_final_mma,     cudaFuncAttributeMaxDynamicSharedMemorySize, SZ_FIN);
        attr_done = true;
    }

    void* p;
    cudaGetSymbolAddress(&p, g_agg);   float* pagg  = (float*)p;
    cudaGetSymbolAddress(&p, g_cnti);  int*   pcnti = (int*)p;
    cudaGetSymbolAddress(&p, g_stats); float* pst   = (float*)p;
    cudaGetSymbolAddress(&p, g_scale); float* psc   = (float*)p;
    cudaGetSymbolAddress(&p, g_shift); float* psh   = (float*)p;
    cudaGetSymbolAddress(&p, g_h);     float* ph    = (float*)p;
    cudaGetSymbolAddress(&p, g_Uh);    float* pUh   = (float*)p;
    cudaGetSymbolAddress(&p, g_Vh);    float* pVh   = (float*)p;
    cudaGetSymbolAddress(&p, g_Bh);    float* pBh   = (float*)p;
    cudaGetSymbolAddress(&p, g_Ch);    float* pCh   = (float*)p;
    cudaGetSymbolAddress(&p, g_tmp);   float* ptmp  = (float*)p;
    cudaGetSymbolAddress(&p, g_wimg);  unsigned short* pw = (unsigned short*)p;

    // Launch order note: ncu (-s 5 -c 1) profiles the 6th launch.
    // 1:prep_all 2:init_h 3:init_e 4:gemm4(L0) 5:zero_agg 6:edge(L0) <- profiled
    {
        dim3 g(DD, 15);
        k_prep_all<<<g, DD>>>(Uw, Vw, Aw, Bw, Cw, f1w, f2w);
    }
    k_init_h<<<NN, DD>>>(x, hp_w, hp_b);
    k_init_e<<<EE, DD>>>(ea, ep_w, ep_b);

    bool counts_done = false;
    for (int l = 0; l < LL; l++){
        const bool last = (l == LL-1);

        if (!last){
            dim3 grid(NTN, 4);
            k_mma_gemm4<<<grid, 512, SZ_GEMM>>>(ph,
                pw + (size_t)(0+l)*32768, pw + (size_t)(3+l)*32768,
                pw + (size_t)(9+l)*32768, pw + (size_t)(12+l)*32768,
                Ub + l*DD, Vb + l*DD, Bb + l*DD, Cb + l*DD,
                pUh, pVh, pBh, pCh, NN);
            k_zero_f4<<<(NN*DD/4+255)/256, 256>>>((float4*)pagg, NN*DD/4);
        } else {
            dim3 grid(NTN, 2);
            k_mma_gemm4<<<grid, 512, SZ_GEMM>>>(ph,
                pw + (size_t)(9+l)*32768, pw + (size_t)(12+l)*32768,
                pw + (size_t)(9+l)*32768, pw + (size_t)(12+l)*32768,
                Bb + l*DD, Cb + l*DD, Bb + l*DD, Cb + l*DD,
                pBh, pCh, pBh, pCh, NN);
        }

        const unsigned short* aimg = pw + (size_t)(6+l)*32768;
        if (l == 0)
            k_edge_mma<0,1><<<NT2, 512, SZ_EDGE>>>(aimg, Ab + l*DD, src, dst, psc+DD, psh+DD);
        else if (!last)
            k_edge_mma<1,1><<<NT2, 512, SZ_EDGE>>>(aimg, Ab + l*DD, src, dst, psc+DD, psh+DD);
        else
            k_edge_mma<1,0><<<NT2, 512, SZ_EDGE>>>(aimg, Ab + l*DD, src, dst, psc+DD, psh+DD);

        if (!counts_done){
            // per-node degree counts (needed first by k_node_tmp_stats below)
            k_zero_i<<<(NN+255)/256, 256>>>(pcnti, NN);
            k_count<<<(EE+255)/256, 256>>>(src);
            k_cntf<<<(NN+255)/256, 256>>>();
            counts_done = true;
        }

        // fused e-BN (also pre-zeroes h-stat slots in pst)
        k_ebn<<<DD, 256>>>(pst, e_g + l*DD, e_bt + l*DD, psc + DD, psh + DD);

        if (!last){
            k_node_tmp_stats<256><<<(NN+255)/256, DD>>>(pst);
            k_bn_fin<<<1, DD>>>(pst + 0*DD, pst + 1*DD, h_g + l*DD, h_bt + l*DD,
                                (float)NN, psc, psh);
            k_apply4<<<(NN*DD/4+255)/256, 256>>>((float4*)ph, (const float4*)ptmp,
                                                 (const float4*)psc, (const float4*)psh, NN*DD/4);
        }
    }

    // final: fuses layer-2 e BN-apply + 3-layer MLP
    k_final_mma<<<NT2, 512, SZ_FIN>>>(pw + (size_t)15*32768, pw + (size_t)16*32768,
                                      f1b, f2b, f3w, f3b, psc + DD, psh + DD, out);
}

// round 11
// speedup vs baseline: 1.9456x; 1.1460x over previous
#include <cuda_runtime.h>
#include <cuda_bf16.h>
#include <cstdint>
#include <math.h>

#define NN 20000
#define EE 320000
#define DD 128
#define LL 3
#define BN_EPS 1e-5f
#define NT2 2500            // edge blocks (128 edges = 2x64 tiles each)
#define NTN 157             // node blocks (2x64 rows each)

// plane geometry: rows padded to 272B (conflict-free ldmatrix)
#define PL  34816           // full plane (128 rows)
#define HPL 17408           // half plane (64 rows)

// half-M kernels (edge, node GEMM): A(2x17408) + W(2x34816); D overlays A
#define H_AHI 0
#define H_ALO 17408
#define H_BHI 34816
#define H_BLO 69632
#define H_SRC 104448
#define H_DST 104960
#define H_SS  105472
#define H_SQ  105984
#define SZ_EDGE 106496
#define SZ_GEMM 104448

// full-size final kernel
#define F_AHI 0
#define F_ALO 34816
#define F_BHI 69632
#define F_BLO 104448
#define F_ROW 139264
#define SZ_FIN 139776

// ---------------- scratch (device globals; no allocation) ----------------
__device__ float g_h [NN*DD];
__device__ float g_h2[NN*DD];
__device__ float g_e [EE*DD];
__device__ float g_et[EE*DD];
__device__ float g_Uh[NN*DD];
__device__ float g_Vh[NN*DD];
__device__ float g_Bh[NN*DD];
__device__ float g_Ch[NN*DD];
__device__ float g_agg[NN*DD];
__device__ float g_tmp[NN*DD];
__device__ float g_cnt[NN];
__device__ int   g_cnti[NN];
__device__ float g_eps[2*DD*NT2];      // edge BN partials
__device__ float g_stats[4*DD];
__device__ float g_scale[2*DD];
__device__ float g_shift[2*DD];
// 17 weight slots: dense [k][n] split planes, hi (16384 ushort) then lo
__device__ unsigned short g_wimg[17*32768];

// ---------------- helpers ----------------
__device__ __forceinline__ float sigm(float v){ return 1.f/(1.f+__expf(-v)); }
__device__ __forceinline__ float silu(float v){ return v*sigm(v); }

__device__ __forceinline__ uint32_t smem_u32(const void* p){
    uint32_t a;
    asm("{ .reg .u64 t; cvta.to.shared.u64 t, %1; cvt.u32.u64 %0, t; }" : "=r"(a) : "l"(p));
    return a;
}
__device__ __forceinline__ void split_bf(float v, __nv_bfloat16& h, __nv_bfloat16& l){
    h = __float2bfloat16(v);
    l = __float2bfloat16(v - __bfloat162float(h));
}
__device__ __forceinline__ unsigned pack_bf2(__nv_bfloat16 a, __nv_bfloat16 b){
    __nv_bfloat162 p = __halves2bfloat162(a, b);
    return *reinterpret_cast<unsigned*>(&p);
}
__device__ __forceinline__ void ldsm4(uint32_t addr, uint32_t r[4]){
    asm volatile("ldmatrix.sync.aligned.m8n8.x4.shared.b16 {%0,%1,%2,%3}, [%4];"
        : "=r"(r[0]), "=r"(r[1]), "=r"(r[2]), "=r"(r[3]) : "r"(addr));
}
__device__ __forceinline__ void ldsm4t(uint32_t addr, uint32_t r[4]){
    asm volatile("ldmatrix.sync.aligned.m8n8.x4.trans.shared.b16 {%0,%1,%2,%3}, [%4];"
        : "=r"(r[0]), "=r"(r[1]), "=r"(r[2]), "=r"(r[3]) : "r"(addr));
}
__device__ __forceinline__ void mma16816(float c[4], const uint32_t a[4], uint32_t b0, uint32_t b1){
    asm volatile("mma.sync.aligned.m16n8k16.row.col.f32.bf16.bf16.f32 "
        "{%0,%1,%2,%3}, {%4,%5,%6,%7}, {%8,%9}, {%0,%1,%2,%3};"
        : "+f"(c[0]), "+f"(c[1]), "+f"(c[2]), "+f"(c[3])
        : "r"(a[0]), "r"(a[1]), "r"(a[2]), "r"(a[3]), "r"(b0), "r"(b1));
}
__device__ __forceinline__ void cp16(uint32_t daddr, const void* src){
    asm volatile("cp.async.cg.shared.global [%0], [%1], 16;" :: "r"(daddr), "l"(src));
}
#define CP_COMMIT() asm volatile("cp.async.commit_group;" ::: "memory")
#define CP_WAIT()   asm volatile("cp.async.wait_group 0;" ::: "memory")

// vector reduction to global (sm_90+, baseline PTX)
__device__ __forceinline__ void red_add_v4(float* addr, float4 v){
    asm volatile("red.global.add.v4.f32 [%0], {%1,%2,%3,%4};"
        :: "l"(addr), "f"(v.x), "f"(v.y), "f"(v.z), "f"(v.w) : "memory");
}

// warp-tiled split-bf16 GEMM core (512 threads / 16 warps).
// MSUB = 16-row m-subtiles per warp; APL = A plane byte size.
template<int MSUB, int APL>
__device__ __forceinline__ void gemm_core(uint32_t sb, int offA, int offB, int t,
                                          float acc[MSUB][4][4]){
    const int lane = t & 31, wid = t >> 5;
    const int wm = wid >> 2, wn = wid & 3;
    uint32_t aBase = sb + offA + (uint32_t)(wm*(16*MSUB) + (lane&7) + ((lane>>3)&1)*8)*272
                   + (uint32_t)((lane>>4)*8)*2;
    uint32_t bBase = sb + offB + (uint32_t)((lane&7) + ((lane>>3)&1)*8)*272
                   + (uint32_t)(wn*32 + (lane>>4)*8)*2;
    #pragma unroll
    for (int kt = 0; kt < 8; kt++){
        uint32_t ah[MSUB][4], al[MSUB][4];
        #pragma unroll
        for (int ms = 0; ms < MSUB; ms++){
            ldsm4(aBase + ms*16*272 + kt*32,       ah[ms]);
            ldsm4(aBase + APL + ms*16*272 + kt*32, al[ms]);
        }
        uint32_t bh[2][4], bl[2][4];
        #pragma unroll
        for (int np = 0; np < 2; np++){
            ldsm4t(bBase + kt*4352 + np*32,      bh[np]);
            ldsm4t(bBase + PL + kt*4352 + np*32, bl[np]);
        }
        #pragma unroll
        for (int ms = 0; ms < MSUB; ms++){
            #pragma unroll
            for (int np = 0; np < 2; np++){
                #pragma unroll
                for (int sub = 0; sub < 2; sub++){
                    float* c = acc[ms][np*2 + sub];
                    uint32_t h0 = bh[np][sub*2], h1 = bh[np][sub*2+1];
                    mma16816(c, ah[ms], h0, h1);
                    mma16816(c, ah[ms], bl[np][sub*2], bl[np][sub*2+1]);
                    mma16816(c, al[ms], h0, h1);
                }
            }
        }
    }
}

// async copy of a prepped weight slot into padded smem planes (512 threads)
__device__ __forceinline__ void copy_w_async(uint32_t sb, int offB,
                                             const unsigned short* wslot, int t){
    const uint4* hi = (const uint4*)wslot;
    const uint4* lo = (const uint4*)(wslot + 16384);
    #pragma unroll
    for (int i = t; i < 2048; i += 512){
        int r = i >> 4, c = i & 15;
        uint32_t d = sb + offB + (uint32_t)(r*17 + c)*16;
        cp16(d,      hi + i);
        cp16(d + PL, lo + i);
    }
}

// split a staged float4 into A hi/lo planes
__device__ __forceinline__ void stage_store(char* smem, int r, int c4, float4 v){
    int off = r*272 + c4*8;
    __nv_bfloat16 h0,l0,h1,l1,h2,l2,h3,l3;
    split_bf(v.x,h0,l0); split_bf(v.y,h1,l1); split_bf(v.z,h2,l2); split_bf(v.w,h3,l3);
    *(unsigned*)(smem + H_AHI + off)     = pack_bf2(h0,h1);
    *(unsigned*)(smem + H_AHI + off + 4) = pack_bf2(h2,h3);
    *(unsigned*)(smem + H_ALO + off)     = pack_bf2(l0,l1);
    *(unsigned*)(smem + H_ALO + off + 4) = pack_bf2(l2,l3);
}

// ---------------- merged weight prep ----------------
__global__ void k_prep_all(const float* __restrict__ Uw, const float* __restrict__ Vw,
                           const float* __restrict__ Aw, const float* __restrict__ Bw,
                           const float* __restrict__ Cw, const float* __restrict__ f1w,
                           const float* __restrict__ f2w){
    int y = blockIdx.y;
    const float* W; int slot;
    if      (y < 2){ W = Uw + y*DD*DD;      slot = y; }
    else if (y < 4){ W = Vw + (y-2)*DD*DD;  slot = 3 + (y-2); }
    else if (y < 7){ W = Aw + (y-4)*DD*DD;  slot = 6 + (y-4); }
    else if (y < 10){ W = Bw + (y-7)*DD*DD; slot = 9 + (y-7); }
    else if (y < 13){ W = Cw + (y-10)*DD*DD; slot = 12 + (y-10); }
    else if (y == 13){ W = f1w; slot = 15; }
    else            { W = f2w; slot = 16; }
    int k = blockIdx.x, n = threadIdx.x;
    unsigned short* base = g_wimg + (size_t)slot*32768;
    __nv_bfloat16 h, l; split_bf(W[k*DD + n], h, l);
    base[k*DD + n]         = __bfloat16_as_ushort(h);
    base[16384 + k*DD + n] = __bfloat16_as_ushort(l);
}

// ---------------- small kernels ----------------
__global__ void k_zero_f4(float4* p, int n){
    int i = blockIdx.x*blockDim.x + threadIdx.x;
    if (i < n) p[i] = make_float4(0.f,0.f,0.f,0.f);
}
__global__ void k_zero_i(int* p, int n){
    int i = blockIdx.x*blockDim.x + threadIdx.x;
    if (i < n) p[i] = 0;
}
__global__ void k_count(const int* __restrict__ src){
    int i = blockIdx.x*blockDim.x + threadIdx.x;
    if (i < EE) atomicAdd(&g_cnti[src[i]], 1);
}
__global__ void k_cntf(){
    int i = blockIdx.x*blockDim.x + threadIdx.x;
    if (i < NN) g_cnt[i] = fmaxf((float)g_cnti[i], 1.f);
}
__global__ void k_init_h(const float* __restrict__ x,
                         const float* __restrict__ hw, const float* __restrict__ hb){
    int n = blockIdx.x, d = threadIdx.x;
    float v = fmaf(x[n*2+0], hw[d], fmaf(x[n*2+1], hw[DD+d], hb[d]));
    g_h[n*DD+d] = silu(v);
}
__global__ void k_init_e(const float* __restrict__ ea,
                         const float* __restrict__ ew, const float* __restrict__ eb){
    int e = blockIdx.x, d = threadIdx.x;
    float v = fmaf(ea[e], ew[d], eb[d]);
    g_e[e*DD+d] = silu(v);
}
// fused: tmp = Uh + agg/cnt (write) + column stats into pst[0:2DD]
template<int R>
__global__ void k_node_tmp_stats(float* __restrict__ pst){
    const int d = threadIdx.x;
    const int r0 = blockIdx.x * R;
    const int r1 = min(NN, r0 + R);
    float s = 0.f, q = 0.f;
    for (int r = r0; r < r1; r++){
        float v = g_Uh[(size_t)r*DD + d] + g_agg[(size_t)r*DD + d] / g_cnt[r];
        g_tmp[(size_t)r*DD + d] = v;
        s += v; q = fmaf(v, v, q);
    }
    atomicAdd(&pst[d], s);
    atomicAdd(&pst[DD+d], q);
}
__global__ void k_bn_fin(const float* __restrict__ sum, const float* __restrict__ sumsq,
                         const float* __restrict__ gamma, const float* __restrict__ beta,
                         float rows, float* __restrict__ scale, float* __restrict__ shift){
    int d = threadIdx.x;
    float m   = sum[d] / rows;
    float var = sumsq[d] / rows - m*m;
    float inv = rsqrtf(var + BN_EPS);
    float sc  = inv * gamma[d];
    scale[d] = sc;
    shift[d] = beta[d] - m*sc;
}
// fused edge-BN: reduce partials + compute scale/shift + zero h-stat slots
__global__ void k_ebn(float* __restrict__ pst,
                      const float* __restrict__ gamma, const float* __restrict__ beta,
                      float* __restrict__ scale, float* __restrict__ shift){
    const int d = blockIdx.x;      // 0..127
    __shared__ float red[256];
    float s = 0.f;
    const float* ps = g_eps + (size_t)d*NT2;
    for (int i = threadIdx.x; i < NT2; i += 256) s += ps[i];
    red[threadIdx.x] = s; __syncthreads();
    for (int o = 128; o > 0; o >>= 1){
        if (threadIdx.x < o) red[threadIdx.x] += red[threadIdx.x + o];
        __syncthreads();
    }
    float sum = red[0];
    __syncthreads();
    float q = 0.f;
    const float* pq = g_eps + (size_t)(DD+d)*NT2;
    for (int i = threadIdx.x; i < NT2; i += 256) q += pq[i];
    red[threadIdx.x] = q; __syncthreads();
    for (int o = 128; o > 0; o >>= 1){
        if (threadIdx.x < o) red[threadIdx.x] += red[threadIdx.x + o];
        __syncthreads();
    }
    if (threadIdx.x == 0){
        float sumsq = red[0];
        float m   = sum / (float)EE;
        float var = sumsq / (float)EE - m*m;
        float inv = rsqrtf(var + BN_EPS);
        float sc  = inv * gamma[d];
        scale[d] = sc;
        shift[d] = beta[d] - m*sc;
        pst[d] = 0.f; pst[DD+d] = 0.f;   // pre-zero h-stat slots for next layer
    }
}

// ---------------- merged node GEMM (2x64-row tiles/block, optional fused h-apply) ----
// APPLY: stages v = hin + silu(tmp*scH+shH); blockIdx.y==0 writes v to hout.
template<int APPLY>
__global__ void __launch_bounds__(512,2) k_mma_gemm4(const float* __restrict__ hin,
        float* __restrict__ hout,
        const unsigned short* __restrict__ w0, const unsigned short* __restrict__ w1,
        const unsigned short* __restrict__ w2, const unsigned short* __restrict__ w3,
        const float* __restrict__ b0, const float* __restrict__ b1,
        const float* __restrict__ b2, const float* __restrict__ b3,
        float* __restrict__ o0, float* __restrict__ o1,
        float* __restrict__ o2, float* __restrict__ o3,
        const float* __restrict__ scH, const float* __restrict__ shH, int rows){
    extern __shared__ __align__(16) char smem[];
    uint32_t sb = smem_u32(smem);
    const int t = threadIdx.x, lane = t & 31, wid = t >> 5;
    const int wm = wid >> 2, wn = wid & 3;
    const int y = blockIdx.y;
    const unsigned short* wslot = (y==0) ? w0 : (y==1) ? w1 : (y==2) ? w2 : w3;
    const float* bias           = (y==0) ? b0 : (y==1) ? b1 : (y==2) ? b2 : b3;
    float* out                  = (y==0) ? o0 : (y==1) ? o1 : (y==2) ? o2 : o3;

    copy_w_async(sb, H_BHI, wslot, t);
    CP_COMMIT();

    const float4* A4 = (const float4*)hin;
    const float4* T4 = (const float4*)g_tmp;
    float4* HO4 = (float4*)hout;
    const float4* sc4 = (const float4*)scH;
    const float4* sh4 = (const float4*)shH;
    float4* out4 = (float4*)out;

    #pragma unroll
    for (int tile = 0; tile < 2; tile++){
        const int row0 = blockIdx.x * 128 + tile * 64;
        #pragma unroll
        for (int it = 0; it < 4; it++){
            int idx = it*512 + t;
            int r = idx >> 5, c4 = idx & 31;
            float4 v = make_float4(0.f,0.f,0.f,0.f);
            if (row0 + r < rows){
                size_t gi = (size_t)(row0 + r)*32 + c4;
                v = A4[gi];
                if (APPLY){
                    float4 tm = T4[gi], S = sc4[c4], H = sh4[c4];
                    v.x += silu(fmaf(tm.x, S.x, H.x));
                    v.y += silu(fmaf(tm.y, S.y, H.y));
                    v.z += silu(fmaf(tm.z, S.z, H.z));
                    v.w += silu(fmaf(tm.w, S.w, H.w));
                    if (y == 0) HO4[gi] = v;
                }
            }
            stage_store(smem, r, c4, v);
        }
        if (tile == 0) CP_WAIT();
        __syncthreads();

        float acc[1][4][4];
        #pragma unroll
        for (int j=0;j<4;j++) for(int k=0;k<4;k++) acc[0][j][k]=0.f;
        gemm_core<1,HPL>(sb, H_AHI, H_BHI, t, acc);
        __syncthreads();

        // fragments -> smem D [row][col] stride 132 (overlay A region)
        float* sD = (float*)(smem + H_AHI);
        {
            int r0 = wm*16 + (lane>>2);
            #pragma unroll
            for (int nt = 0; nt < 4; nt++){
                int c0 = wn*32 + nt*8 + (lane&3)*2;
                float* c = acc[0][nt];
                *(float2*)&sD[r0*132 + c0]     = make_float2(c[0], c[1]);
                *(float2*)&sD[(r0+8)*132 + c0] = make_float2(c[2], c[3]);
            }
        }
        __syncthreads();

        #pragma unroll
        for (int it = 0; it < 4; it++){
            int idx = it*512 + t;
            int r = idx >> 5, c4 = idx & 31;
            if (row0 + r < rows){
                float4 v = *(const float4*)&sD[r*132 + c4*4];
                const float4 b = *(const float4*)(bias + c4*4);
                v.x += b.x; v.y += b.y; v.z += b.z; v.w += b.w;
                out4[(size_t)(row0 + r)*32 + c4] = v;
            }
        }
        __syncthreads();
    }
}

// ---------------- fused edge kernel (float4 epilogue + v4 red) ----------------
template<int APPLY, int DOMSG>
__global__ void __launch_bounds__(512,2) k_edge_mma(const unsigned short* __restrict__ wslot,
                                                    const float* __restrict__ ab,
                                                    const int* __restrict__ src,
                                                    const int* __restrict__ dst,
                                                    const float* __restrict__ scE,
                                                    const float* __restrict__ shE){
    extern __shared__ __align__(16) char smem[];
    uint32_t sb = smem_u32(smem);
    const int t = threadIdx.x, lane = t & 31, wid = t >> 5;
    const int wm = wid >> 2, wn = wid & 3;
    const int blk = blockIdx.x;
    const int e0 = blk * 128;

    copy_w_async(sb, H_BHI, wslot, t);
    CP_COMMIT();

    int* shs = (int*)(smem + H_SRC);
    int* sht = (int*)(smem + H_DST);
    float* sS = (float*)(smem + H_SS);
    float* sQ = (float*)(smem + H_SQ);
    if (t < 128){ shs[t] = src[e0+t]; sht[t] = dst[e0+t]; sS[t] = 0.f; sQ[t] = 0.f; }

    float4* ge4  = (float4*)g_e;
    const float4* get4 = (const float4*)g_et;
    const float4* sc4 = (const float4*)scE;
    const float4* sh4 = (const float4*)shE;

    // epilogue mapping: warp = row-group, lane = col4
    const int c4e = t & 31, rg = t >> 5;
    const float4 b4 = *(const float4*)(ab + c4e*4);
    float4 s4 = make_float4(0.f,0.f,0.f,0.f);
    float4 q4 = make_float4(0.f,0.f,0.f,0.f);

    #pragma unroll
    for (int tile = 0; tile < 2; tile++){
        const int r0g = e0 + tile * 64;
        // stage: optional BN-apply + residual, then split into A planes
        #pragma unroll
        for (int it = 0; it < 4; it++){
            int idx = it*512 + t;
            int r = idx >> 5, c4 = idx & 31;
            size_t gi = (size_t)(r0g + r)*32 + c4;
            float4 ev = ge4[gi];
            if (APPLY){
                float4 et = get4[gi], S = sc4[c4], H = sh4[c4];
                ev.x += silu(fmaf(et.x, S.x, H.x));
                ev.y += silu(fmaf(et.y, S.y, H.y));
                ev.z += silu(fmaf(et.z, S.z, H.z));
                ev.w += silu(fmaf(et.w, S.w, H.w));
                ge4[gi] = ev;
            }
            stage_store(smem, r, c4, ev);
        }
        if (tile == 0) CP_WAIT();
        __syncthreads();

        float acc[1][4][4];
        #pragma unroll
        for (int j=0;j<4;j++) for(int k=0;k<4;k++) acc[0][j][k]=0.f;
        gemm_core<1,HPL>(sb, H_AHI, H_BHI, t, acc);
        __syncthreads();

        // fragments -> smem D [row][col] stride 132 (overlay A region)
        float* sD = (float*)(smem + H_AHI);
        {
            int r0 = wm*16 + (lane>>2);
            #pragma unroll
            for (int nt = 0; nt < 4; nt++){
                int c0 = wn*32 + nt*8 + (lane&3)*2;
                float* c = acc[0][nt];
                *(float2*)&sD[r0*132 + c0]     = make_float2(c[0], c[1]);
                *(float2*)&sD[(r0+8)*132 + c0] = make_float2(c[2], c[3]);
            }
        }
        __syncthreads();

        // float4 epilogue: each warp owns rows rg, rg+16, rg+32, rg+48 (full 512B rows)
        #pragma unroll
        for (int i = 0; i < 4; i++){
            int r = rg + i*16;
            int li = tile*64 + r;
            int ss = shs[li], tt = sht[li];
            float4 d = *(const float4*)&sD[r*132 + c4e*4];
            float4 bh = *(const float4*)&g_Bh[(size_t)ss*DD + c4e*4];
            float4 ch = *(const float4*)&g_Ch[(size_t)tt*DD + c4e*4];
            d.x += b4.x + bh.x + ch.x;
            d.y += b4.y + bh.y + ch.y;
            d.z += b4.z + bh.z + ch.z;
            d.w += b4.w + bh.w + ch.w;
            *(float4*)&g_et[(size_t)(r0g + r)*DD + c4e*4] = d;
            s4.x += d.x; s4.y += d.y; s4.z += d.z; s4.w += d.w;
            q4.x = fmaf(d.x,d.x,q4.x); q4.y = fmaf(d.y,d.y,q4.y);
            q4.z = fmaf(d.z,d.z,q4.z); q4.w = fmaf(d.w,d.w,q4.w);
            if (DOMSG){
                float4 ev = *(const float4*)&g_e[(size_t)(r0g + r)*DD + c4e*4];
                float4 vh = *(const float4*)&g_Vh[(size_t)tt*DD + c4e*4];
                float4 m;
                m.x = sigm(ev.x)*vh.x; m.y = sigm(ev.y)*vh.y;
                m.z = sigm(ev.z)*vh.z; m.w = sigm(ev.w)*vh.w;
                red_add_v4(&g_agg[(size_t)ss*DD + c4e*4], m);
            }
        }
        __syncthreads();   // sD consumed before next tile's staging overwrites A
    }

    atomicAdd(&sS[c4e*4+0], s4.x); atomicAdd(&sS[c4e*4+1], s4.y);
    atomicAdd(&sS[c4e*4+2], s4.z); atomicAdd(&sS[c4e*4+3], s4.w);
    atomicAdd(&sQ[c4e*4+0], q4.x); atomicAdd(&sQ[c4e*4+1], q4.y);
    atomicAdd(&sQ[c4e*4+2], q4.z); atomicAdd(&sQ[c4e*4+3], q4.w);
    __syncthreads();
    if (t < 128){
        g_eps[(size_t)t*NT2 + blk]      = sS[t];
        g_eps[(size_t)(DD+t)*NT2 + blk] = sQ[t];
    }
}

// ---------------- fused final: e-apply -> MLP(2 GEMMs) -> sigmoid dot (M=128) ----------------
__global__ void __launch_bounds__(512,1) k_final_mma(const unsigned short* __restrict__ w1,
                                                     const unsigned short* __restrict__ w2,
                                                     const float* __restrict__ f1b,
                                                     const float* __restrict__ f2b,
                                                     const float* __restrict__ f3w,
                                                     const float* __restrict__ f3b,
                                                     const float* __restrict__ scE,
                                                     const float* __restrict__ shE,
                                                     float* __restrict__ out){
    extern __shared__ __align__(16) char smem[];
    uint32_t sb = smem_u32(smem);
    const int t = threadIdx.x, lane = t & 31, wid = t >> 5;
    const int wm = wid >> 2, wn = wid & 3;
    const int e0 = blockIdx.x * 128;

    float* sRow = (float*)(smem + F_ROW);
    if (t < 128) sRow[t] = 0.f;

    copy_w_async(sb, F_BHI, w1, t);
    CP_COMMIT();

    const float4* ge4  = (const float4*)g_e;
    const float4* get4 = (const float4*)g_et;
    const float4* sc4  = (const float4*)scE;
    const float4* sh4  = (const float4*)shE;
    #pragma unroll
    for (int it = 0; it < 8; it++){
        int idx = it*512 + t;
        int r = idx >> 5, c4 = idx & 31;
        size_t gi = (size_t)(e0 + r)*32 + c4;
        float4 ev = ge4[gi];
        float4 et = get4[gi], S = sc4[c4], H = sh4[c4];
        ev.x += silu(fmaf(et.x, S.x, H.x));
        ev.y += silu(fmaf(et.y, S.y, H.y));
        ev.z += silu(fmaf(et.z, S.z, H.z));
        ev.w += silu(fmaf(et.w, S.w, H.w));
        int off = r*272 + c4*8;
        __nv_bfloat16 h0,l0,h1,l1,h2,l2,h3,l3;
        split_bf(ev.x,h0,l0); split_bf(ev.y,h1,l1); split_bf(ev.z,h2,l2); split_bf(ev.w,h3,l3);
        *(unsigned*)(smem + F_AHI + off)     = pack_bf2(h0,h1);
        *(unsigned*)(smem + F_AHI + off + 4) = pack_bf2(h2,h3);
        *(unsigned*)(smem + F_ALO + off)     = pack_bf2(l0,l1);
        *(unsigned*)(smem + F_ALO + off + 4) = pack_bf2(l2,l3);
    }
    CP_WAIT();
    __syncthreads();

    float acc[2][4][4];
    #pragma unroll
    for (int i=0;i<2;i++) for(int j=0;j<4;j++) for(int k=0;k<4;k++) acc[i][j][k]=0.f;
    gemm_core<2,PL>(sb, F_AHI, F_BHI, t, acc);
    __syncthreads();   // everyone done reading A & B planes

    // stage1 epilogue: silu -> split bf16 from fragments into B region
    copy_w_async(sb, F_AHI, w2, t);
    CP_COMMIT();
    #pragma unroll
    for (int mt = 0; mt < 2; mt++){
        int r0 = wm*32 + mt*16 + (lane>>2);
        #pragma unroll
        for (int nt = 0; nt < 4; nt++){
            int c0 = wn*32 + nt*8 + (lane&3)*2;
            float* c = acc[mt][nt];
            float v0 = silu(c[0] + f1b[c0]);
            float v1 = silu(c[1] + f1b[c0+1]);
            float v2 = silu(c[2] + f1b[c0]);
            float v3 = silu(c[3] + f1b[c0+1]);
            __nv_bfloat16 h0,l0,h1,l1;
            split_bf(v0,h0,l0); split_bf(v1,h1,l1);
            *(unsigned*)(smem + F_BHI + r0*272 + c0*2) = pack_bf2(h0,h1);
            *(unsigned*)(smem + F_BLO + r0*272 + c0*2) = pack_bf2(l0,l1);
            split_bf(v2,h0,l0); split_bf(v3,h1,l1);
            *(unsigned*)(smem + F_BHI + (r0+8)*272 + c0*2) = pack_bf2(h0,h1);
            *(unsigned*)(smem + F_BLO + (r0+8)*272 + c0*2) = pack_bf2(l0,l1);
        }
    }
    CP_WAIT();
    __syncthreads();

    #pragma unroll
    for (int i=0;i<2;i++) for(int j=0;j<4;j++) for(int k=0;k<4;k++) acc[i][j][k]=0.f;
    gemm_core<2,PL>(sb, F_BHI, F_AHI, t, acc);

    // stage3: silu(+f2b)*f3w, reduce per row
    #pragma unroll
    for (int mt = 0; mt < 2; mt++){
        float r0s = 0.f, r1s = 0.f;
        #pragma unroll
        for (int nt = 0; nt < 4; nt++){
            int c0 = wn*32 + nt*8 + (lane&3)*2;
            float* c = acc[mt][nt];
            float w0 = f3w[c0], w1 = f3w[c0+1];
            float b0 = f2b[c0], b1 = f2b[c0+1];
            r0s = fmaf(silu(c[0]+b0), w0, fmaf(silu(c[1]+b1), w1, r0s));
            r1s = fmaf(silu(c[2]+b0), w0, fmaf(silu(c[3]+b1), w1, r1s));
        }
        r0s += __shfl_xor_sync(0xffffffff, r0s, 1);
        r0s += __shfl_xor_sync(0xffffffff, r0s, 2);
        r1s += __shfl_xor_sync(0xffffffff, r1s, 1);
        r1s += __shfl_xor_sync(0xffffffff, r1s, 2);
        if ((lane & 3) == 0){
            int r0 = wm*32 + mt*16 + (lane>>2);
            atomicAdd(&sRow[r0], r0s);
            atomicAdd(&sRow[r0+8], r1s);
        }
    }
    __syncthreads();
    if (t < 128) out[e0 + t] = sigm(sRow[t] + f3b[0]);
}

// ---------------- host orchestration ----------------
extern "C" void kernel_launch(void* const* d_in, const int* in_sizes, int n_in,
                              void* d_out, int out_size){
    const float* x    = (const float*)d_in[0];
    const float* ea   = (const float*)d_in[1];
    const int*   eidx = (const int*)  d_in[2];
    const float* hp_w = (const float*)d_in[3];
    const float* hp_b = (const float*)d_in[4];
    const float* ep_w = (const float*)d_in[5];
    const float* ep_b = (const float*)d_in[6];
    const float* Uw   = (const float*)d_in[7];
    const float* Ub   = (const float*)d_in[8];
    const float* Vw   = (const float*)d_in[9];
    const float* Vb   = (const float*)d_in[10];
    const float* Aw   = (const float*)d_in[11];
    const float* Ab   = (const float*)d_in[12];
    const float* Bw   = (const float*)d_in[13];
    const float* Bb   = (const float*)d_in[14];
    const float* Cw   = (const float*)d_in[15];
    const float* Cb   = (const float*)d_in[16];
    const float* h_g  = (const float*)d_in[17];
    const float* h_bt = (const float*)d_in[18];
    const float* e_g  = (const float*)d_in[19];
    const float* e_bt = (const float*)d_in[20];
    const float* f1w  = (const float*)d_in[21];
    const float* f1b  = (const float*)d_in[22];
    const float* f2w  = (const float*)d_in[23];
    const float* f2b  = (const float*)d_in[24];
    const float* f3w  = (const float*)d_in[25];
    const float* f3b  = (const float*)d_in[26];
    float* out = (float*)d_out;

    const int* src = eidx;        // edge_index[0]: scatter target
    const int* dst = eidx + EE;   // edge_index[1]: gather source

    static bool attr_done = false;
    if (!attr_done){
        cudaFuncSetAttribute(k_mma_gemm4<0>,  cudaFuncAttributeMaxDynamicSharedMemorySize, SZ_GEMM);
        cudaFuncSetAttribute(k_mma_gemm4<1>,  cudaFuncAttributeMaxDynamicSharedMemorySize, SZ_GEMM);
        cudaFuncSetAttribute(k_edge_mma<0,1>, cudaFuncAttributeMaxDynamicSharedMemorySize, SZ_EDGE);
        cudaFuncSetAttribute(k_edge_mma<1,1>, cudaFuncAttributeMaxDynamicSharedMemorySize, SZ_EDGE);
        cudaFuncSetAttribute(k_edge_mma<1,0>, cudaFuncAttributeMaxDynamicSharedMemorySize, SZ_EDGE);
        cudaFuncSetAttribute(k_final_mma,     cudaFuncAttributeMaxDynamicSharedMemorySize, SZ_FIN);
        attr_done = true;
    }

    void* p;
    cudaGetSymbolAddress(&p, g_agg);   float* pagg  = (float*)p;
    cudaGetSymbolAddress(&p, g_cnti);  int*   pcnti = (int*)p;
    cudaGetSymbolAddress(&p, g_stats); float* pst   = (float*)p;
    cudaGetSymbolAddress(&p, g_scale); float* psc   = (float*)p;
    cudaGetSymbolAddress(&p, g_shift); float* psh   = (float*)p;
    cudaGetSymbolAddress(&p, g_h);     float* ph    = (float*)p;
    cudaGetSymbolAddress(&p, g_h2);    float* ph2   = (float*)p;
    cudaGetSymbolAddress(&p, g_Uh);    float* pUh   = (float*)p;
    cudaGetSymbolAddress(&p, g_Vh);    float* pVh   = (float*)p;
    cudaGetSymbolAddress(&p, g_Bh);    float* pBh   = (float*)p;
    cudaGetSymbolAddress(&p, g_Ch);    float* pCh   = (float*)p;
    cudaGetSymbolAddress(&p, g_wimg);  unsigned short* pw = (unsigned short*)p;

    // launch order: 1 prep, 2 init_h, 3 gemm4(L0), 4 init_e, 5 zero_agg, 6 edge(L0)
    {
        dim3 g(DD, 15);
        k_prep_all<<<g, DD>>>(Uw, Vw, Aw, Bw, Cw, f1w, f2w);
    }
    k_init_h<<<NN, DD>>>(x, hp_w, hp_b);

    // h ping-pong: layer l reads hbuf[l], layer l+1 gemm writes hbuf[l+1]
    float* hbuf[3] = { ph, ph2, ph };

    for (int l = 0; l < LL; l++){
        const bool last = (l == LL-1);

        if (l == 0){
            dim3 grid(NTN, 4);
            k_mma_gemm4<0><<<grid, 512, SZ_GEMM>>>(hbuf[0], nullptr,
                pw + (size_t)0*32768, pw + (size_t)3*32768,
                pw + (size_t)9*32768, pw + (size_t)12*32768,
                Ub, Vb, Bb, Cb, pUh, pVh, pBh, pCh, psc, psh, NN);
            k_init_e<<<EE, DD>>>(ea, ep_w, ep_b);
            k_zero_f4<<<(NN*DD/4+255)/256, 256>>>((float4*)pagg, NN*DD/4);
        } else if (!last){
            dim3 grid(NTN, 4);
            k_mma_gemm4<1><<<grid, 512, SZ_GEMM>>>(hbuf[l-1], hbuf[l],
                pw + (size_t)(0+l)*32768, pw + (size_t)(3+l)*32768,
                pw + (size_t)(9+l)*32768, pw + (size_t)(12+l)*32768,
                Ub + l*DD, Vb + l*DD, Bb + l*DD, Cb + l*DD,
                pUh, pVh, pBh, pCh, psc, psh, NN);
            k_zero_f4<<<(NN*DD/4+255)/256, 256>>>((float4*)pagg, NN*DD/4);
        } else {
            dim3 grid(NTN, 2);
            k_mma_gemm4<1><<<grid, 512, SZ_GEMM>>>(hbuf[l-1], hbuf[l],
                pw + (size_t)(9+l)*32768, pw + (size_t)(12+l)*32768,
                pw + (size_t)(9+l)*32768, pw + (size_t)(12+l)*32768,
                Bb + l*DD, Cb + l*DD, Bb + l*DD, Cb + l*DD,
                pBh, pCh, pBh, pCh, psc, psh, NN);
        }

        const unsigned short* aimg = pw + (size_t)(6+l)*32768;
        if (l == 0)
            k_edge_mma<0,1><<<NT2, 512, SZ_EDGE>>>(aimg, Ab + l*DD, src, dst, psc+DD, psh+DD);
        else if (!last)
            k_edge_mma<1,1><<<NT2, 512, SZ_EDGE>>>(aimg, Ab + l*DD, src, dst, psc+DD, psh+DD);
        else
            k_edge_mma<1,0><<<NT2, 512, SZ_EDGE>>>(aimg, Ab + l*DD, src, dst, psc+DD, psh+DD);

        if (l == 0){
            // per-node degree counts (needed by k_node_tmp_stats)
            k_zero_i<<<(NN+255)/256, 256>>>(pcnti, NN);
            k_count<<<(EE+255)/256, 256>>>(src);
            k_cntf<<<(NN+255)/256, 256>>>();
        }

        // fused e-BN (also pre-zeroes h-stat slots in pst)
        k_ebn<<<DD, 256>>>(pst, e_g + l*DD, e_bt + l*DD, psc + DD, psh + DD);

        if (!last){
            k_node_tmp_stats<256><<<(NN+255)/256, DD>>>(pst);
            k_bn_fin<<<1, DD>>>(pst + 0*DD, pst + 1*DD, h_g + l*DD, h_bt + l*DD,
                                (float)NN, psc, psh);
        }
    }

    // final: fuses layer-2 e BN-apply + 3-layer MLP
    k_final_mma<<<NT2, 512, SZ_FIN>>>(pw + (size_t)15*32768, pw + (size_t)16*32768,
                                      f1b, f2b, f3w, f3b, psc + DD, psh + DD, out);
}

// round 12
// speedup vs baseline: 2.1757x; 1.1183x over previous
#include <cuda_runtime.h>
#include <cuda_bf16.h>
#include <cstdint>
#include <math.h>

#define NN 20000
#define EE 320000
#define DD 128
#define LL 3
#define BN_EPS 1e-5f
#define NT2 2500            // edge blocks (128 edges = 2x64 tiles each)
#define NTN 157             // node blocks (2x64 rows each)

// plane geometry: rows padded to 272B (conflict-free ldmatrix)
#define PL  34816           // full plane (128 rows)
#define HPL 17408           // half plane (64 rows)

// half-M kernels (edge, node GEMM): A(2x17408) + W(2x34816); D overlays A
#define H_AHI 0
#define H_ALO 17408
#define H_BHI 34816
#define H_BLO 69632
#define H_SRC 104448
#define H_DST 104960
#define H_SS  105472
#define H_SQ  105984
#define SZ_EDGE 106496
#define SZ_GEMM 104448

// full-size final kernel
#define F_AHI 0
#define F_ALO 34816
#define F_BHI 69632
#define F_BLO 104448
#define F_ROW 139264
#define SZ_FIN 139776

// ---------------- scratch (device globals; no allocation) ----------------
__device__ float g_h [NN*DD];
__device__ float g_h2[NN*DD];
__device__ float g_e [EE*DD];
__device__ float g_et[EE*DD];
__device__ float g_Uh[NN*DD];
__device__ float g_Vh[NN*DD];
__device__ float g_Bh[NN*DD];
__device__ float g_Ch[NN*DD];
__device__ float g_agg[NN*DD];
__device__ float g_tmp[NN*DD];
__device__ float g_cnt[NN];
__device__ int   g_cnti[NN];
__device__ float g_eps[2*DD*NT2];      // edge BN partials
__device__ float g_stats[4*DD];
__device__ float g_scale[2*DD];
__device__ float g_shift[2*DD];
// 17 weight slots: dense [k][n] split planes, hi (16384 ushort) then lo
__device__ unsigned short g_wimg[17*32768];

// ---------------- helpers ----------------
__device__ __forceinline__ float sigm(float v){ return 1.f/(1.f+__expf(-v)); }
__device__ __forceinline__ float silu(float v){ return v*sigm(v); }

__device__ __forceinline__ uint32_t smem_u32(const void* p){
    uint32_t a;
    asm("{ .reg .u64 t; cvta.to.shared.u64 t, %1; cvt.u32.u64 %0, t; }" : "=r"(a) : "l"(p));
    return a;
}
__device__ __forceinline__ void split_bf(float v, __nv_bfloat16& h, __nv_bfloat16& l){
    h = __float2bfloat16(v);
    l = __float2bfloat16(v - __bfloat162float(h));
}
__device__ __forceinline__ unsigned pack_bf2(__nv_bfloat16 a, __nv_bfloat16 b){
    __nv_bfloat162 p = __halves2bfloat162(a, b);
    return *reinterpret_cast<unsigned*>(&p);
}
__device__ __forceinline__ void ldsm4(uint32_t addr, uint32_t r[4]){
    asm volatile("ldmatrix.sync.aligned.m8n8.x4.shared.b16 {%0,%1,%2,%3}, [%4];"
        : "=r"(r[0]), "=r"(r[1]), "=r"(r[2]), "=r"(r[3]) : "r"(addr));
}
__device__ __forceinline__ void ldsm4t(uint32_t addr, uint32_t r[4]){
    asm volatile("ldmatrix.sync.aligned.m8n8.x4.trans.shared.b16 {%0,%1,%2,%3}, [%4];"
        : "=r"(r[0]), "=r"(r[1]), "=r"(r[2]), "=r"(r[3]) : "r"(addr));
}
__device__ __forceinline__ void mma16816(float c[4], const uint32_t a[4], uint32_t b0, uint32_t b1){
    asm volatile("mma.sync.aligned.m16n8k16.row.col.f32.bf16.bf16.f32 "
        "{%0,%1,%2,%3}, {%4,%5,%6,%7}, {%8,%9}, {%0,%1,%2,%3};"
        : "+f"(c[0]), "+f"(c[1]), "+f"(c[2]), "+f"(c[3])
        : "r"(a[0]), "r"(a[1]), "r"(a[2]), "r"(a[3]), "r"(b0), "r"(b1));
}
__device__ __forceinline__ void cp16(uint32_t daddr, const void* src){
    asm volatile("cp.async.cg.shared.global [%0], [%1], 16;" :: "r"(daddr), "l"(src));
}
#define CP_COMMIT() asm volatile("cp.async.commit_group;" ::: "memory")
#define CP_WAIT()   asm volatile("cp.async.wait_group 0;" ::: "memory")

// vector reduction to global (sm_90+, baseline PTX)
__device__ __forceinline__ void red_add_v4(float* addr, float4 v){
    asm volatile("red.global.add.v4.f32 [%0], {%1,%2,%3,%4};"
        :: "l"(addr), "f"(v.x), "f"(v.y), "f"(v.z), "f"(v.w) : "memory");
}

// warp-tiled split-bf16 GEMM core (512 threads / 16 warps).
template<int MSUB, int APL>
__device__ __forceinline__ void gemm_core(uint32_t sb, int offA, int offB, int t,
                                          float acc[MSUB][4][4]){
    const int lane = t & 31, wid = t >> 5;
    const int wm = wid >> 2, wn = wid & 3;
    uint32_t aBase = sb + offA + (uint32_t)(wm*(16*MSUB) + (lane&7) + ((lane>>3)&1)*8)*272
                   + (uint32_t)((lane>>4)*8)*2;
    uint32_t bBase = sb + offB + (uint32_t)((lane&7) + ((lane>>3)&1)*8)*272
                   + (uint32_t)(wn*32 + (lane>>4)*8)*2;
    #pragma unroll
    for (int kt = 0; kt < 8; kt++){
        uint32_t ah[MSUB][4], al[MSUB][4];
        #pragma unroll
        for (int ms = 0; ms < MSUB; ms++){
            ldsm4(aBase + ms*16*272 + kt*32,       ah[ms]);
            ldsm4(aBase + APL + ms*16*272 + kt*32, al[ms]);
        }
        uint32_t bh[2][4], bl[2][4];
        #pragma unroll
        for (int np = 0; np < 2; np++){
            ldsm4t(bBase + kt*4352 + np*32,      bh[np]);
            ldsm4t(bBase + PL + kt*4352 + np*32, bl[np]);
        }
        #pragma unroll
        for (int ms = 0; ms < MSUB; ms++){
            #pragma unroll
            for (int np = 0; np < 2; np++){
                #pragma unroll
                for (int sub = 0; sub < 2; sub++){
                    float* c = acc[ms][np*2 + sub];
                    uint32_t h0 = bh[np][sub*2], h1 = bh[np][sub*2+1];
                    mma16816(c, ah[ms], h0, h1);
                    mma16816(c, ah[ms], bl[np][sub*2], bl[np][sub*2+1]);
                    mma16816(c, al[ms], h0, h1);
                }
            }
        }
    }
}

// async copy of a prepped weight slot into padded smem planes (512 threads)
__device__ __forceinline__ void copy_w_async(uint32_t sb, int offB,
                                             const unsigned short* wslot, int t){
    const uint4* hi = (const uint4*)wslot;
    const uint4* lo = (const uint4*)(wslot + 16384);
    #pragma unroll
    for (int i = t; i < 2048; i += 512){
        int r = i >> 4, c = i & 15;
        uint32_t d = sb + offB + (uint32_t)(r*17 + c)*16;
        cp16(d,      hi + i);
        cp16(d + PL, lo + i);
    }
}

// split a staged float4 into A hi/lo planes
__device__ __forceinline__ void stage_store(char* smem, int r, int c4, float4 v){
    int off = r*272 + c4*8;
    __nv_bfloat16 h0,l0,h1,l1,h2,l2,h3,l3;
    split_bf(v.x,h0,l0); split_bf(v.y,h1,l1); split_bf(v.z,h2,l2); split_bf(v.w,h3,l3);
    *(unsigned*)(smem + H_AHI + off)     = pack_bf2(h0,h1);
    *(unsigned*)(smem + H_AHI + off + 4) = pack_bf2(h2,h3);
    *(unsigned*)(smem + H_ALO + off)     = pack_bf2(l0,l1);
    *(unsigned*)(smem + H_ALO + off + 4) = pack_bf2(l2,l3);
}

// ---------------- merged weight prep ----------------
__global__ void k_prep_all(const float* __restrict__ Uw, const float* __restrict__ Vw,
                           const float* __restrict__ Aw, const float* __restrict__ Bw,
                           const float* __restrict__ Cw, const float* __restrict__ f1w,
                           const float* __restrict__ f2w){
    int y = blockIdx.y;
    const float* W; int slot;
    if      (y < 2){ W = Uw + y*DD*DD;      slot = y; }
    else if (y < 4){ W = Vw + (y-2)*DD*DD;  slot = 3 + (y-2); }
    else if (y < 7){ W = Aw + (y-4)*DD*DD;  slot = 6 + (y-4); }
    else if (y < 10){ W = Bw + (y-7)*DD*DD; slot = 9 + (y-7); }
    else if (y < 13){ W = Cw + (y-10)*DD*DD; slot = 12 + (y-10); }
    else if (y == 13){ W = f1w; slot = 15; }
    else            { W = f2w; slot = 16; }
    int k = blockIdx.x, n = threadIdx.x;
    unsigned short* base = g_wimg + (size_t)slot*32768;
    __nv_bfloat16 h, l; split_bf(W[k*DD + n], h, l);
    base[k*DD + n]         = __bfloat16_as_ushort(h);
    base[16384 + k*DD + n] = __bfloat16_as_ushort(l);
}

// ---------------- small kernels ----------------
__global__ void k_zero_f4(float4* p, int n){
    int i = blockIdx.x*blockDim.x + threadIdx.x;
    if (i < n) p[i] = make_float4(0.f,0.f,0.f,0.f);
}
__global__ void k_zero_i(int* p, int n){
    int i = blockIdx.x*blockDim.x + threadIdx.x;
    if (i < n) p[i] = 0;
}
__global__ void k_count(const int* __restrict__ src){
    int i = blockIdx.x*blockDim.x + threadIdx.x;
    if (i < EE) atomicAdd(&g_cnti[src[i]], 1);
}
__global__ void k_cntf(){
    int i = blockIdx.x*blockDim.x + threadIdx.x;
    if (i < NN) g_cnt[i] = fmaxf((float)g_cnti[i], 1.f);
}
// vectorized h init: one float4 per thread
__global__ void k_init_h(const float* __restrict__ x,
                         const float* __restrict__ hw, const float* __restrict__ hb){
    int idx = blockIdx.x*blockDim.x + threadIdx.x;
    if (idx >= NN*32) return;
    int n = idx >> 5, c4 = idx & 31;
    float2 xv = *(const float2*)(x + n*2);
    float4 w0 = *(const float4*)(hw + c4*4);
    float4 w1 = *(const float4*)(hw + DD + c4*4);
    float4 bb = *(const float4*)(hb + c4*4);
    float4 v;
    v.x = silu(fmaf(xv.x, w0.x, fmaf(xv.y, w1.x, bb.x)));
    v.y = silu(fmaf(xv.x, w0.y, fmaf(xv.y, w1.y, bb.y)));
    v.z = silu(fmaf(xv.x, w0.z, fmaf(xv.y, w1.z, bb.z)));
    v.w = silu(fmaf(xv.x, w0.w, fmaf(xv.y, w1.w, bb.w)));
    *(float4*)&g_h[(size_t)n*DD + c4*4] = v;
}
// fused: tmp = Uh + agg/cnt (write) + column stats into pst[0:2DD]
template<int R>
__global__ void k_node_tmp_stats(float* __restrict__ pst){
    const int d = threadIdx.x;
    const int r0 = blockIdx.x * R;
    const int r1 = min(NN, r0 + R);
    float s = 0.f, q = 0.f;
    for (int r = r0; r < r1; r++){
        float v = g_Uh[(size_t)r*DD + d] + g_agg[(size_t)r*DD + d] / g_cnt[r];
        g_tmp[(size_t)r*DD + d] = v;
        s += v; q = fmaf(v, v, q);
    }
    atomicAdd(&pst[d], s);
    atomicAdd(&pst[DD+d], q);
}
__global__ void k_bn_fin(const float* __restrict__ sum, const float* __restrict__ sumsq,
                         const float* __restrict__ gamma, const float* __restrict__ beta,
                         float rows, float* __restrict__ scale, float* __restrict__ shift){
    int d = threadIdx.x;
    float m   = sum[d] / rows;
    float var = sumsq[d] / rows - m*m;
    float inv = rsqrtf(var + BN_EPS);
    float sc  = inv * gamma[d];
    scale[d] = sc;
    shift[d] = beta[d] - m*sc;
}
// fused edge-BN: reduce partials + compute scale/shift + zero h-stat slots
__global__ void k_ebn(float* __restrict__ pst,
                      const float* __restrict__ gamma, const float* __restrict__ beta,
                      float* __restrict__ scale, float* __restrict__ shift){
    const int d = blockIdx.x;      // 0..127
    __shared__ float red[256];
    float s = 0.f;
    const float* ps = g_eps + (size_t)d*NT2;
    for (int i = threadIdx.x; i < NT2; i += 256) s += ps[i];
    red[threadIdx.x] = s; __syncthreads();
    for (int o = 128; o > 0; o >>= 1){
        if (threadIdx.x < o) red[threadIdx.x] += red[threadIdx.x + o];
        __syncthreads();
    }
    float sum = red[0];
    __syncthreads();
    float q = 0.f;
    const float* pq = g_eps + (size_t)(DD+d)*NT2;
    for (int i = threadIdx.x; i < NT2; i += 256) q += pq[i];
    red[threadIdx.x] = q; __syncthreads();
    for (int o = 128; o > 0; o >>= 1){
        if (threadIdx.x < o) red[threadIdx.x] += red[threadIdx.x + o];
        __syncthreads();
    }
    if (threadIdx.x == 0){
        float sumsq = red[0];
        float m   = sum / (float)EE;
        float var = sumsq / (float)EE - m*m;
        float inv = rsqrtf(var + BN_EPS);
        float sc  = inv * gamma[d];
        scale[d] = sc;
        shift[d] = beta[d] - m*sc;
        pst[d] = 0.f; pst[DD+d] = 0.f;   // pre-zero h-stat slots for next layer
    }
}

// ---------------- merged node GEMM (2x64-row tiles/block, optional fused h-apply) ----
template<int APPLY>
__global__ void __launch_bounds__(512,2) k_mma_gemm4(const float* __restrict__ hin,
        float* __restrict__ hout,
        const unsigned short* __restrict__ w0, const unsigned short* __restrict__ w1,
        const unsigned short* __restrict__ w2, const unsigned short* __restrict__ w3,
        const float* __restrict__ b0, const float* __restrict__ b1,
        const float* __restrict__ b2, const float* __restrict__ b3,
        float* __restrict__ o0, float* __restrict__ o1,
        float* __restrict__ o2, float* __restrict__ o3,
        const float* __restrict__ scH, const float* __restrict__ shH, int rows){
    extern __shared__ __align__(16) char smem[];
    uint32_t sb = smem_u32(smem);
    const int t = threadIdx.x, lane = t & 31, wid = t >> 5;
    const int wm = wid >> 2, wn = wid & 3;
    const int y = blockIdx.y;
    const unsigned short* wslot = (y==0) ? w0 : (y==1) ? w1 : (y==2) ? w2 : w3;
    const float* bias           = (y==0) ? b0 : (y==1) ? b1 : (y==2) ? b2 : b3;
    float* out                  = (y==0) ? o0 : (y==1) ? o1 : (y==2) ? o2 : o3;

    copy_w_async(sb, H_BHI, wslot, t);
    CP_COMMIT();

    const float4* A4 = (const float4*)hin;
    const float4* T4 = (const float4*)g_tmp;
    float4* HO4 = (float4*)hout;
    const float4* sc4 = (const float4*)scH;
    const float4* sh4 = (const float4*)shH;
    float4* out4 = (float4*)out;

    #pragma unroll
    for (int tile = 0; tile < 2; tile++){
        const int row0 = blockIdx.x * 128 + tile * 64;
        #pragma unroll
        for (int it = 0; it < 4; it++){
            int idx = it*512 + t;
            int r = idx >> 5, c4 = idx & 31;
            float4 v = make_float4(0.f,0.f,0.f,0.f);
            if (row0 + r < rows){
                size_t gi = (size_t)(row0 + r)*32 + c4;
                v = A4[gi];
                if (APPLY){
                    float4 tm = T4[gi], S = sc4[c4], H = sh4[c4];
                    v.x += silu(fmaf(tm.x, S.x, H.x));
                    v.y += silu(fmaf(tm.y, S.y, H.y));
                    v.z += silu(fmaf(tm.z, S.z, H.z));
                    v.w += silu(fmaf(tm.w, S.w, H.w));
                    if (y == 0) HO4[gi] = v;
                }
            }
            stage_store(smem, r, c4, v);
        }
        if (tile == 0) CP_WAIT();
        __syncthreads();

        float acc[1][4][4];
        #pragma unroll
        for (int j=0;j<4;j++) for(int k=0;k<4;k++) acc[0][j][k]=0.f;
        gemm_core<1,HPL>(sb, H_AHI, H_BHI, t, acc);
        __syncthreads();

        // fragments -> smem D [row][col] stride 132 (overlay A region)
        float* sD = (float*)(smem + H_AHI);
        {
            int r0 = wm*16 + (lane>>2);
            #pragma unroll
            for (int nt = 0; nt < 4; nt++){
                int c0 = wn*32 + nt*8 + (lane&3)*2;
                float* c = acc[0][nt];
                *(float2*)&sD[r0*132 + c0]     = make_float2(c[0], c[1]);
                *(float2*)&sD[(r0+8)*132 + c0] = make_float2(c[2], c[3]);
            }
        }
        __syncthreads();

        #pragma unroll
        for (int it = 0; it < 4; it++){
            int idx = it*512 + t;
            int r = idx >> 5, c4 = idx & 31;
            if (row0 + r < rows){
                float4 v = *(const float4*)&sD[r*132 + c4*4];
                const float4 b = *(const float4*)(bias + c4*4);
                v.x += b.x; v.y += b.y; v.z += b.z; v.w += b.w;
                out4[(size_t)(row0 + r)*32 + c4] = v;
            }
        }
        __syncthreads();
    }
}

// ---------------- fused edge kernel ----------------
// EINIT: e = silu(ea*ew+eb) computed in staging (layer 0), written to g_e.
// APPLY: e = e + silu(et*sc+sh) (later layers). DOMSG: gated message scatter.
template<int EINIT, int APPLY, int DOMSG>
__global__ void __launch_bounds__(512,2) k_edge_mma(const unsigned short* __restrict__ wslot,
                                                    const float* __restrict__ ab,
                                                    const int* __restrict__ src,
                                                    const int* __restrict__ dst,
                                                    const float* __restrict__ scE,
                                                    const float* __restrict__ shE,
                                                    const float* __restrict__ ea,
                                                    const float* __restrict__ ew,
                                                    const float* __restrict__ eb){
    extern __shared__ __align__(16) char smem[];
    uint32_t sb = smem_u32(smem);
    const int t = threadIdx.x, lane = t & 31, wid = t >> 5;
    const int wm = wid >> 2, wn = wid & 3;
    const int blk = blockIdx.x;
    const int e0 = blk * 128;

    copy_w_async(sb, H_BHI, wslot, t);
    CP_COMMIT();

    int* shs = (int*)(smem + H_SRC);
    int* sht = (int*)(smem + H_DST);
    float* sS = (float*)(smem + H_SS);
    float* sQ = (float*)(smem + H_SQ);
    if (t < 128){ shs[t] = src[e0+t]; sht[t] = dst[e0+t]; sS[t] = 0.f; sQ[t] = 0.f; }

    float4* ge4  = (float4*)g_e;
    const float4* get4 = (const float4*)g_et;
    const float4* sc4 = (const float4*)scE;
    const float4* sh4 = (const float4*)shE;

    // epilogue mapping: warp = row-group, lane = col4
    const int c4e = t & 31, rg = t >> 5;
    const float4 b4 = *(const float4*)(ab + c4e*4);
    float4 s4 = make_float4(0.f,0.f,0.f,0.f);
    float4 q4 = make_float4(0.f,0.f,0.f,0.f);

    #pragma unroll
    for (int tile = 0; tile < 2; tile++){
        const int r0g = e0 + tile * 64;
        // stage: compute/apply e, split into A planes
        #pragma unroll
        for (int it = 0; it < 4; it++){
            int idx = it*512 + t;
            int r = idx >> 5, c4 = idx & 31;
            size_t gi = (size_t)(r0g + r)*32 + c4;
            float4 ev;
            if (EINIT){
                float a = ea[r0g + r];
                float4 W  = *(const float4*)(ew + c4*4);
                float4 B  = *(const float4*)(eb + c4*4);
                ev.x = silu(fmaf(a, W.x, B.x));
                ev.y = silu(fmaf(a, W.y, B.y));
                ev.z = silu(fmaf(a, W.z, B.z));
                ev.w = silu(fmaf(a, W.w, B.w));
                ge4[gi] = ev;
            } else {
                ev = ge4[gi];
                if (APPLY){
                    float4 et = get4[gi], S = sc4[c4], H = sh4[c4];
                    ev.x += silu(fmaf(et.x, S.x, H.x));
                    ev.y += silu(fmaf(et.y, S.y, H.y));
                    ev.z += silu(fmaf(et.z, S.z, H.z));
                    ev.w += silu(fmaf(et.w, S.w, H.w));
                    ge4[gi] = ev;
                }
            }
            stage_store(smem, r, c4, ev);
        }
        if (tile == 0) CP_WAIT();
        __syncthreads();

        float acc[1][4][4];
        #pragma unroll
        for (int j=0;j<4;j++) for(int k=0;k<4;k++) acc[0][j][k]=0.f;
        gemm_core<1,HPL>(sb, H_AHI, H_BHI, t, acc);
        __syncthreads();

        // fragments -> smem D [row][col] stride 132 (overlay A region)
        float* sD = (float*)(smem + H_AHI);
        {
            int r0 = wm*16 + (lane>>2);
            #pragma unroll
            for (int nt = 0; nt < 4; nt++){
                int c0 = wn*32 + nt*8 + (lane&3)*2;
                float* c = acc[0][nt];
                *(float2*)&sD[r0*132 + c0]     = make_float2(c[0], c[1]);
                *(float2*)&sD[(r0+8)*132 + c0] = make_float2(c[2], c[3]);
            }
        }
        __syncthreads();

        // float4 epilogue: each warp owns rows rg, rg+16, rg+32, rg+48
        #pragma unroll
        for (int i = 0; i < 4; i++){
            int r = rg + i*16;
            int li = tile*64 + r;
            int ss = shs[li], tt = sht[li];
            float4 d = *(const float4*)&sD[r*132 + c4e*4];
            float4 bh = *(const float4*)&g_Bh[(size_t)ss*DD + c4e*4];
            float4 ch = *(const float4*)&g_Ch[(size_t)tt*DD + c4e*4];
            d.x += b4.x + bh.x + ch.x;
            d.y += b4.y + bh.y + ch.y;
            d.z += b4.z + bh.z + ch.z;
            d.w += b4.w + bh.w + ch.w;
            *(float4*)&g_et[(size_t)(r0g + r)*DD + c4e*4] = d;
            s4.x += d.x; s4.y += d.y; s4.z += d.z; s4.w += d.w;
            q4.x = fmaf(d.x,d.x,q4.x); q4.y = fmaf(d.y,d.y,q4.y);
            q4.z = fmaf(d.z,d.z,q4.z); q4.w = fmaf(d.w,d.w,q4.w);
            if (DOMSG){
                float4 ev = *(const float4*)&g_e[(size_t)(r0g + r)*DD + c4e*4];
                float4 vh = *(const float4*)&g_Vh[(size_t)tt*DD + c4e*4];
                float4 m;
                m.x = sigm(ev.x)*vh.x; m.y = sigm(ev.y)*vh.y;
                m.z = sigm(ev.z)*vh.z; m.w = sigm(ev.w)*vh.w;
                red_add_v4(&g_agg[(size_t)ss*DD + c4e*4], m);
            }
        }
        __syncthreads();   // sD consumed before next tile's staging overwrites A
    }

    atomicAdd(&sS[c4e*4+0], s4.x); atomicAdd(&sS[c4e*4+1], s4.y);
    atomicAdd(&sS[c4e*4+2], s4.z); atomicAdd(&sS[c4e*4+3], s4.w);
    atomicAdd(&sQ[c4e*4+0], q4.x); atomicAdd(&sQ[c4e*4+1], q4.y);
    atomicAdd(&sQ[c4e*4+2], q4.z); atomicAdd(&sQ[c4e*4+3], q4.w);
    __syncthreads();
    if (t < 128){
        g_eps[(size_t)t*NT2 + blk]      = sS[t];
        g_eps[(size_t)(DD+t)*NT2 + blk] = sQ[t];
    }
}

// ---------------- fused final: e-apply -> MLP(2 GEMMs) -> sigmoid dot (M=128) ----------------
__global__ void __launch_bounds__(512,1) k_final_mma(const unsigned short* __restrict__ w1,
                                                     const unsigned short* __restrict__ w2,
                                                     const float* __restrict__ f1b,
                                                     const float* __restrict__ f2b,
                                                     const float* __restrict__ f3w,
                                                     const float* __restrict__ f3b,
                                                     const float* __restrict__ scE,
                                                     const float* __restrict__ shE,
                                                     float* __restrict__ out){
    extern __shared__ __align__(16) char smem[];
    uint32_t sb = smem_u32(smem);
    const int t = threadIdx.x, lane = t & 31, wid = t >> 5;
    const int wm = wid >> 2, wn = wid & 3;
    const int e0 = blockIdx.x * 128;

    float* sRow = (float*)(smem + F_ROW);
    if (t < 128) sRow[t] = 0.f;

    copy_w_async(sb, F_BHI, w1, t);
    CP_COMMIT();

    const float4* ge4  = (const float4*)g_e;
    const float4* get4 = (const float4*)g_et;
    const float4* sc4  = (const float4*)scE;
    const float4* sh4  = (const float4*)shE;
    #pragma unroll
    for (int it = 0; it < 8; it++){
        int idx = it*512 + t;
        int r = idx >> 5, c4 = idx & 31;
        size_t gi = (size_t)(e0 + r)*32 + c4;
        float4 ev = ge4[gi];
        float4 et = get4[gi], S = sc4[c4], H = sh4[c4];
        ev.x += silu(fmaf(et.x, S.x, H.x));
        ev.y += silu(fmaf(et.y, S.y, H.y));
        ev.z += silu(fmaf(et.z, S.z, H.z));
        ev.w += silu(fmaf(et.w, S.w, H.w));
        int off = r*272 + c4*8;
        __nv_bfloat16 h0,l0,h1,l1,h2,l2,h3,l3;
        split_bf(ev.x,h0,l0); split_bf(ev.y,h1,l1); split_bf(ev.z,h2,l2); split_bf(ev.w,h3,l3);
        *(unsigned*)(smem + F_AHI + off)     = pack_bf2(h0,h1);
        *(unsigned*)(smem + F_AHI + off + 4) = pack_bf2(h2,h3);
        *(unsigned*)(smem + F_ALO + off)     = pack_bf2(l0,l1);
        *(unsigned*)(smem + F_ALO + off + 4) = pack_bf2(l2,l3);
    }
    CP_WAIT();
    __syncthreads();

    float acc[2][4][4];
    #pragma unroll
    for (int i=0;i<2;i++) for(int j=0;j<4;j++) for(int k=0;k<4;k++) acc[i][j][k]=0.f;
    gemm_core<2,PL>(sb, F_AHI, F_BHI, t, acc);
    __syncthreads();

    copy_w_async(sb, F_AHI, w2, t);
    CP_COMMIT();
    #pragma unroll
    for (int mt = 0; mt < 2; mt++){
        int r0 = wm*32 + mt*16 + (lane>>2);
        #pragma unroll
        for (int nt = 0; nt < 4; nt++){
            int c0 = wn*32 + nt*8 + (lane&3)*2;
            float* c = acc[mt][nt];
            float v0 = silu(c[0] + f1b[c0]);
            float v1 = silu(c[1] + f1b[c0+1]);
            float v2 = silu(c[2] + f1b[c0]);
            float v3 = silu(c[3] + f1b[c0+1]);
            __nv_bfloat16 h0,l0,h1,l1;
            split_bf(v0,h0,l0); split_bf(v1,h1,l1);
            *(unsigned*)(smem + F_BHI + r0*272 + c0*2) = pack_bf2(h0,h1);
            *(unsigned*)(smem + F_BLO + r0*272 + c0*2) = pack_bf2(l0,l1);
            split_bf(v2,h0,l0); split_bf(v3,h1,l1);
            *(unsigned*)(smem + F_BHI + (r0+8)*272 + c0*2) = pack_bf2(h0,h1);
            *(unsigned*)(smem + F_BLO + (r0+8)*272 + c0*2) = pack_bf2(l0,l1);
        }
    }
    CP_WAIT();
    __syncthreads();

    #pragma unroll
    for (int i=0;i<2;i++) for(int j=0;j<4;j++) for(int k=0;k<4;k++) acc[i][j][k]=0.f;
    gemm_core<2,PL>(sb, F_BHI, F_AHI, t, acc);

    #pragma unroll
    for (int mt = 0; mt < 2; mt++){
        float r0s = 0.f, r1s = 0.f;
        #pragma unroll
        for (int nt = 0; nt < 4; nt++){
            int c0 = wn*32 + nt*8 + (lane&3)*2;
            float* c = acc[mt][nt];
            float w0 = f3w[c0], w1 = f3w[c0+1];
            float b0 = f2b[c0], b1 = f2b[c0+1];
            r0s = fmaf(silu(c[0]+b0), w0, fmaf(silu(c[1]+b1), w1, r0s));
            r1s = fmaf(silu(c[2]+b0), w0, fmaf(silu(c[3]+b1), w1, r1s));
        }
        r0s += __shfl_xor_sync(0xffffffff, r0s, 1);
        r0s += __shfl_xor_sync(0xffffffff, r0s, 2);
        r1s += __shfl_xor_sync(0xffffffff, r1s, 1);
        r1s += __shfl_xor_sync(0xffffffff, r1s, 2);
        if ((lane & 3) == 0){
            int r0 = wm*32 + mt*16 + (lane>>2);
            atomicAdd(&sRow[r0], r0s);
            atomicAdd(&sRow[r0+8], r1s);
        }
    }
    __syncthreads();
    if (t < 128) out[e0 + t] = sigm(sRow[t] + f3b[0]);
}

// ---------------- host orchestration ----------------
extern "C" void kernel_launch(void* const* d_in, const int* in_sizes, int n_in,
                              void* d_out, int out_size){
    const float* x    = (const float*)d_in[0];
    const float* ea   = (const float*)d_in[1];
    const int*   eidx = (const int*)  d_in[2];
    const float* hp_w = (const float*)d_in[3];
    const float* hp_b = (const float*)d_in[4];
    const float* ep_w = (const float*)d_in[5];
    const float* ep_b = (const float*)d_in[6];
    const float* Uw   = (const float*)d_in[7];
    const float* Ub   = (const float*)d_in[8];
    const float* Vw   = (const float*)d_in[9];
    const float* Vb   = (const float*)d_in[10];
    const float* Aw   = (const float*)d_in[11];
    const float* Ab   = (const float*)d_in[12];
    const float* Bw   = (const float*)d_in[13];
    const float* Bb   = (const float*)d_in[14];
    const float* Cw   = (const float*)d_in[15];
    const float* Cb   = (const float*)d_in[16];
    const float* h_g  = (const float*)d_in[17];
    const float* h_bt = (const float*)d_in[18];
    const float* e_g  = (const float*)d_in[19];
    const float* e_bt = (const float*)d_in[20];
    const float* f1w  = (const float*)d_in[21];
    const float* f1b  = (const float*)d_in[22];
    const float* f2w  = (const float*)d_in[23];
    const float* f2b  = (const float*)d_in[24];
    const float* f3w  = (const float*)d_in[25];
    const float* f3b  = (const float*)d_in[26];
    float* out = (float*)d_out;

    const int* src = eidx;        // edge_index[0]: scatter target
    const int* dst = eidx + EE;   // edge_index[1]: gather source

    static bool attr_done = false;
    if (!attr_done){
        cudaFuncSetAttribute(k_mma_gemm4<0>,    cudaFuncAttributeMaxDynamicSharedMemorySize, SZ_GEMM);
        cudaFuncSetAttribute(k_mma_gemm4<1>,    cudaFuncAttributeMaxDynamicSharedMemorySize, SZ_GEMM);
        cudaFuncSetAttribute(k_edge_mma<1,0,1>, cudaFuncAttributeMaxDynamicSharedMemorySize, SZ_EDGE);
        cudaFuncSetAttribute(k_edge_mma<0,1,1>, cudaFuncAttributeMaxDynamicSharedMemorySize, SZ_EDGE);
        cudaFuncSetAttribute(k_edge_mma<0,1,0>, cudaFuncAttributeMaxDynamicSharedMemorySize, SZ_EDGE);
        cudaFuncSetAttribute(k_final_mma,       cudaFuncAttributeMaxDynamicSharedMemorySize, SZ_FIN);
        attr_done = true;
    }

    void* p;
    cudaGetSymbolAddress(&p, g_agg);   float* pagg  = (float*)p;
    cudaGetSymbolAddress(&p, g_cnti);  int*   pcnti = (int*)p;
    cudaGetSymbolAddress(&p, g_stats); float* pst   = (float*)p;
    cudaGetSymbolAddress(&p, g_scale); float* psc   = (float*)p;
    cudaGetSymbolAddress(&p, g_shift); float* psh   = (float*)p;
    cudaGetSymbolAddress(&p, g_h);     float* ph    = (float*)p;
    cudaGetSymbolAddress(&p, g_h2);    float* ph2   = (float*)p;
    cudaGetSymbolAddress(&p, g_Uh);    float* pUh   = (float*)p;
    cudaGetSymbolAddress(&p, g_Vh);    float* pVh   = (float*)p;
    cudaGetSymbolAddress(&p, g_Bh);    float* pBh   = (float*)p;
    cudaGetSymbolAddress(&p, g_Ch);    float* pCh   = (float*)p;
    cudaGetSymbolAddress(&p, g_wimg);  unsigned short* pw = (unsigned short*)p;

    // launch order: 1 prep, 2 init_h, 3 gemm4(L0), 4 zero_agg, 5 zero_cnti, 6 edge(L0)
    {
        dim3 g(DD, 15);
        k_prep_all<<<g, DD>>>(Uw, Vw, Aw, Bw, Cw, f1w, f2w);
    }
    k_init_h<<<(NN*32+255)/256, 256>>>(x, hp_w, hp_b);

    // h ping-pong: layer l reads hbuf[l], layer l+1 gemm writes hbuf[l+1]
    float* hbuf[3] = { ph, ph2, ph };

    for (int l = 0; l < LL; l++){
        const bool last = (l == LL-1);

        if (l == 0){
            dim3 grid(NTN, 4);
            k_mma_gemm4<0><<<grid, 512, SZ_GEMM>>>(hbuf[0], nullptr,
                pw + (size_t)0*32768, pw + (size_t)3*32768,
                pw + (size_t)9*32768, pw + (size_t)12*32768,
                Ub, Vb, Bb, Cb, pUh, pVh, pBh, pCh, psc, psh, NN);
            k_zero_f4<<<(NN*DD/4+255)/256, 256>>>((float4*)pagg, NN*DD/4);
            k_zero_i<<<(NN+255)/256, 256>>>(pcnti, NN);
        } else if (!last){
            dim3 grid(NTN, 4);
            k_mma_gemm4<1><<<grid, 512, SZ_GEMM>>>(hbuf[l-1], hbuf[l],
                pw + (size_t)(0+l)*32768, pw + (size_t)(3+l)*32768,
                pw + (size_t)(9+l)*32768, pw + (size_t)(12+l)*32768,
                Ub + l*DD, Vb + l*DD, Bb + l*DD, Cb + l*DD,
                pUh, pVh, pBh, pCh, psc, psh, NN);
            k_zero_f4<<<(NN*DD/4+255)/256, 256>>>((float4*)pagg, NN*DD/4);
        } else {
            dim3 grid(NTN, 2);
            k_mma_gemm4<1><<<grid, 512, SZ_GEMM>>>(hbuf[l-1], hbuf[l],
                pw + (size_t)(9+l)*32768, pw + (size_t)(12+l)*32768,
                pw + (size_t)(9+l)*32768, pw + (size_t)(12+l)*32768,
                Bb + l*DD, Cb + l*DD, Bb + l*DD, Cb + l*DD,
                pBh, pCh, pBh, pCh, psc, psh, NN);
        }

        const unsigned short* aimg = pw + (size_t)(6+l)*32768;
        if (l == 0)
            k_edge_mma<1,0,1><<<NT2, 512, SZ_EDGE>>>(aimg, Ab + l*DD, src, dst,
                                                     psc+DD, psh+DD, ea, ep_w, ep_b);
        else if (!last)
            k_edge_mma<0,1,1><<<NT2, 512, SZ_EDGE>>>(aimg, Ab + l*DD, src, dst,
                                                     psc+DD, psh+DD, nullptr, nullptr, nullptr);
        else
            k_edge_mma<0,1,0><<<NT2, 512, SZ_EDGE>>>(aimg, Ab + l*DD, src, dst,
                                                     psc+DD, psh+DD, nullptr, nullptr, nullptr);

        if (l == 0){
            // per-node degree counts (needed by k_node_tmp_stats)
            k_count<<<(EE+255)/256, 256>>>(src);
            k_cntf<<<(NN+255)/256, 256>>>();
        }

        // fused e-BN (also pre-zeroes h-stat slots in pst)
        k_ebn<<<DD, 256>>>(pst, e_g + l*DD, e_bt + l*DD, psc + DD, psh + DD);

        if (!last){
            k_node_tmp_stats<256><<<(NN+255)/256, DD>>>(pst);
            k_bn_fin<<<1, DD>>>(pst + 0*DD, pst + 1*DD, h_g + l*DD, h_bt + l*DD,
                                (float)NN, psc, psh);
        }
    }

    // final: fuses layer-2 e BN-apply + 3-layer MLP
    k_final_mma<<<NT2, 512, SZ_FIN>>>(pw + (size_t)15*32768, pw + (size_t)16*32768,
                                      f1b, f2b, f3w, f3b, psc + DD, psh + DD, out);
}

// round 13
// speedup vs baseline: 2.2130x; 1.0172x over previous
#include <cuda_runtime.h>
#include <cuda_bf16.h>
#include <cstdint>
#include <math.h>

#define NN 20000
#define EE 320000
#define DD 128
#define LL 3
#define BN_EPS 1e-5f
#define NT2 2500            // edge blocks (128 edges = 2x64 tiles each)
#define NTN 157             // node blocks (2x64 rows each)

// plane geometry: rows padded to 272B (conflict-free ldmatrix)
#define PL  34816           // full plane (128 rows)
#define HPL 17408           // half plane (64 rows)

// half-M kernels (edge, node GEMM): A(2x17408) + W(2x34816); D overlays A
#define H_AHI 0
#define H_ALO 17408
#define H_BHI 34816
#define H_BLO 69632
#define H_SRC 104448
#define H_DST 104960
#define H_SS  105472
#define H_SQ  105984
#define SZ_EDGE 106496
#define SZ_GEMM 104448

// full-size final kernel
#define F_AHI 0
#define F_ALO 34816
#define F_BHI 69632
#define F_BLO 104448
#define F_ROW 139264
#define SZ_FIN 139776

// ---------------- scratch (device globals; no allocation) ----------------
__device__ float g_h [NN*DD];
__device__ float g_h2[NN*DD];
__device__ float g_e [EE*DD];
__device__ float g_et[EE*DD];
__device__ float g_Uh[NN*DD];
__device__ float g_Vh[NN*DD];
__device__ float g_Bh[NN*DD];
__device__ float g_Ch[NN*DD];
__device__ float g_agg[NN*DD];
__device__ float g_tmp[NN*DD];
__device__ int   g_cnti[NN];
__device__ float g_eps[2*DD*NT2];      // edge BN partials
__device__ float g_stats[4*DD];
__device__ float g_scale[2*DD];
__device__ float g_shift[2*DD];
// 17 weight slots: dense [k][n] split planes, hi (16384 ushort) then lo
__device__ unsigned short g_wimg[17*32768];

// ---------------- helpers ----------------
__device__ __forceinline__ float sigm(float v){ return 1.f/(1.f+__expf(-v)); }
__device__ __forceinline__ float silu(float v){ return v*sigm(v); }

__device__ __forceinline__ uint32_t smem_u32(const void* p){
    uint32_t a;
    asm("{ .reg .u64 t; cvta.to.shared.u64 t, %1; cvt.u32.u64 %0, t; }" : "=r"(a) : "l"(p));
    return a;
}
__device__ __forceinline__ void split_bf(float v, __nv_bfloat16& h, __nv_bfloat16& l){
    h = __float2bfloat16(v);
    l = __float2bfloat16(v - __bfloat162float(h));
}
__device__ __forceinline__ unsigned pack_bf2(__nv_bfloat16 a, __nv_bfloat16 b){
    __nv_bfloat162 p = __halves2bfloat162(a, b);
    return *reinterpret_cast<unsigned*>(&p);
}
__device__ __forceinline__ void ldsm4(uint32_t addr, uint32_t r[4]){
    asm volatile("ldmatrix.sync.aligned.m8n8.x4.shared.b16 {%0,%1,%2,%3}, [%4];"
        : "=r"(r[0]), "=r"(r[1]), "=r"(r[2]), "=r"(r[3]) : "r"(addr));
}
__device__ __forceinline__ void ldsm4t(uint32_t addr, uint32_t r[4]){
    asm volatile("ldmatrix.sync.aligned.m8n8.x4.trans.shared.b16 {%0,%1,%2,%3}, [%4];"
        : "=r"(r[0]), "=r"(r[1]), "=r"(r[2]), "=r"(r[3]) : "r"(addr));
}
__device__ __forceinline__ void mma16816(float c[4], const uint32_t a[4], uint32_t b0, uint32_t b1){
    asm volatile("mma.sync.aligned.m16n8k16.row.col.f32.bf16.bf16.f32 "
        "{%0,%1,%2,%3}, {%4,%5,%6,%7}, {%8,%9}, {%0,%1,%2,%3};"
        : "+f"(c[0]), "+f"(c[1]), "+f"(c[2]), "+f"(c[3])
        : "r"(a[0]), "r"(a[1]), "r"(a[2]), "r"(a[3]), "r"(b0), "r"(b1));
}
__device__ __forceinline__ void cp16(uint32_t daddr, const void* src){
    asm volatile("cp.async.cg.shared.global [%0], [%1], 16;" :: "r"(daddr), "l"(src));
}
#define CP_COMMIT() asm volatile("cp.async.commit_group;" ::: "memory")
#define CP_WAIT()   asm volatile("cp.async.wait_group 0;" ::: "memory")

// vector reduction to global (sm_90+, baseline PTX)
__device__ __forceinline__ void red_add_v4(float* addr, float4 v){
    asm volatile("red.global.add.v4.f32 [%0], {%1,%2,%3,%4};"
        :: "l"(addr), "f"(v.x), "f"(v.y), "f"(v.z), "f"(v.w) : "memory");
}

// warp-tiled split-bf16 GEMM core (512 threads / 16 warps).
template<int MSUB, int APL>
__device__ __forceinline__ void gemm_core(uint32_t sb, int offA, int offB, int t,
                                          float acc[MSUB][4][4]){
    const int lane = t & 31, wid = t >> 5;
    const int wm = wid >> 2, wn = wid & 3;
    uint32_t aBase = sb + offA + (uint32_t)(wm*(16*MSUB) + (lane&7) + ((lane>>3)&1)*8)*272
                   + (uint32_t)((lane>>4)*8)*2;
    uint32_t bBase = sb + offB + (uint32_t)((lane&7) + ((lane>>3)&1)*8)*272
                   + (uint32_t)(wn*32 + (lane>>4)*8)*2;
    #pragma unroll
    for (int kt = 0; kt < 8; kt++){
        uint32_t ah[MSUB][4], al[MSUB][4];
        #pragma unroll
        for (int ms = 0; ms < MSUB; ms++){
            ldsm4(aBase + ms*16*272 + kt*32,       ah[ms]);
            ldsm4(aBase + APL + ms*16*272 + kt*32, al[ms]);
        }
        uint32_t bh[2][4], bl[2][4];
        #pragma unroll
        for (int np = 0; np < 2; np++){
            ldsm4t(bBase + kt*4352 + np*32,      bh[np]);
            ldsm4t(bBase + PL + kt*4352 + np*32, bl[np]);
        }
        #pragma unroll
        for (int ms = 0; ms < MSUB; ms++){
            #pragma unroll
            for (int np = 0; np < 2; np++){
                #pragma unroll
                for (int sub = 0; sub < 2; sub++){
                    float* c = acc[ms][np*2 + sub];
                    uint32_t h0 = bh[np][sub*2], h1 = bh[np][sub*2+1];
                    mma16816(c, ah[ms], h0, h1);
                    mma16816(c, ah[ms], bl[np][sub*2], bl[np][sub*2+1]);
                    mma16816(c, al[ms], h0, h1);
                }
            }
        }
    }
}

// async copy of a prepped weight slot into padded smem planes (512 threads)
__device__ __forceinline__ void copy_w_async(uint32_t sb, int offB,
                                             const unsigned short* wslot, int t){
    const uint4* hi = (const uint4*)wslot;
    const uint4* lo = (const uint4*)(wslot + 16384);
    #pragma unroll
    for (int i = t; i < 2048; i += 512){
        int r = i >> 4, c = i & 15;
        uint32_t d = sb + offB + (uint32_t)(r*17 + c)*16;
        cp16(d,      hi + i);
        cp16(d + PL, lo + i);
    }
}

// split a staged float4 into A hi/lo planes
__device__ __forceinline__ void stage_store(char* smem, int r, int c4, float4 v){
    int off = r*272 + c4*8;
    __nv_bfloat16 h0,l0,h1,l1,h2,l2,h3,l3;
    split_bf(v.x,h0,l0); split_bf(v.y,h1,l1); split_bf(v.z,h2,l2); split_bf(v.w,h3,l3);
    *(unsigned*)(smem + H_AHI + off)     = pack_bf2(h0,h1);
    *(unsigned*)(smem + H_AHI + off + 4) = pack_bf2(h2,h3);
    *(unsigned*)(smem + H_ALO + off)     = pack_bf2(l0,l1);
    *(unsigned*)(smem + H_ALO + off + 4) = pack_bf2(l2,l3);
}

// ---------------- merged weight prep (also zeroes h-stat slots of g_stats) -------
__global__ void k_prep_all(const float* __restrict__ Uw, const float* __restrict__ Vw,
                           const float* __restrict__ Aw, const float* __restrict__ Bw,
                           const float* __restrict__ Cw, const float* __restrict__ f1w,
                           const float* __restrict__ f2w){
    int y = blockIdx.y;
    const float* W; int slot;
    if      (y < 2){ W = Uw + y*DD*DD;      slot = y; }
    else if (y < 4){ W = Vw + (y-2)*DD*DD;  slot = 3 + (y-2); }
    else if (y < 7){ W = Aw + (y-4)*DD*DD;  slot = 6 + (y-4); }
    else if (y < 10){ W = Bw + (y-7)*DD*DD; slot = 9 + (y-7); }
    else if (y < 13){ W = Cw + (y-10)*DD*DD; slot = 12 + (y-10); }
    else if (y == 13){ W = f1w; slot = 15; }
    else            { W = f2w; slot = 16; }
    int k = blockIdx.x, n = threadIdx.x;
    if (k == 0 && y == 0){ g_stats[n] = 0.f; g_stats[DD+n] = 0.f; }
    unsigned short* base = g_wimg + (size_t)slot*32768;
    __nv_bfloat16 h, l; split_bf(W[k*DD + n], h, l);
    base[k*DD + n]         = __bfloat16_as_ushort(h);
    base[16384 + k*DD + n] = __bfloat16_as_ushort(l);
}

// ---------------- small kernels ----------------
__global__ void k_zero_f4(float4* p, int n){
    int i = blockIdx.x*blockDim.x + threadIdx.x;
    if (i < n) p[i] = make_float4(0.f,0.f,0.f,0.f);
}
__global__ void k_zero_i(int* p, int n){
    int i = blockIdx.x*blockDim.x + threadIdx.x;
    if (i < n) p[i] = 0;
}
__global__ void k_count(const int* __restrict__ src){
    int i = blockIdx.x*blockDim.x + threadIdx.x;
    if (i < EE) atomicAdd(&g_cnti[src[i]], 1);
}
// vectorized h init: one float4 per thread
__global__ void k_init_h(const float* __restrict__ x,
                         const float* __restrict__ hw, const float* __restrict__ hb){
    int idx = blockIdx.x*blockDim.x + threadIdx.x;
    if (idx >= NN*32) return;
    int n = idx >> 5, c4 = idx & 31;
    float2 xv = *(const float2*)(x + n*2);
    float4 w0 = *(const float4*)(hw + c4*4);
    float4 w1 = *(const float4*)(hw + DD + c4*4);
    float4 bb = *(const float4*)(hb + c4*4);
    float4 v;
    v.x = silu(fmaf(xv.x, w0.x, fmaf(xv.y, w1.x, bb.x)));
    v.y = silu(fmaf(xv.x, w0.y, fmaf(xv.y, w1.y, bb.y)));
    v.z = silu(fmaf(xv.x, w0.z, fmaf(xv.y, w1.z, bb.z)));
    v.w = silu(fmaf(xv.x, w0.w, fmaf(xv.y, w1.w, bb.w)));
    *(float4*)&g_h[(size_t)n*DD + c4*4] = v;
}
// fused: tmp = Uh + agg/cnt (write) + column stats into pst[0:2DD]; reads g_cnti
template<int R>
__global__ void k_node_tmp_stats(float* __restrict__ pst){
    const int d = threadIdx.x;
    const int r0 = blockIdx.x * R;
    const int r1 = min(NN, r0 + R);
    float s = 0.f, q = 0.f;
    for (int r = r0; r < r1; r++){
        float rc = fmaxf((float)g_cnti[r], 1.f);
        float v = g_Uh[(size_t)r*DD + d] + g_agg[(size_t)r*DD + d] / rc;
        g_tmp[(size_t)r*DD + d] = v;
        s += v; q = fmaf(v, v, q);
    }
    atomicAdd(&pst[d], s);
    atomicAdd(&pst[DD+d], q);
}
// h BN finalize; also re-zeroes the h-stat slots for the next layer
__global__ void k_bn_fin(float* __restrict__ pst,
                         const float* __restrict__ gamma, const float* __restrict__ beta,
                         float rows, float* __restrict__ scale, float* __restrict__ shift){
    int d = threadIdx.x;
    float m   = pst[d] / rows;
    float var = pst[DD+d] / rows - m*m;
    float inv = rsqrtf(var + BN_EPS);
    float sc  = inv * gamma[d];
    scale[d] = sc;
    shift[d] = beta[d] - m*sc;
    pst[d] = 0.f; pst[DD+d] = 0.f;
}
// fused edge-BN: reduce partials + compute scale/shift (no pst touch)
__global__ void k_ebn(const float* __restrict__ gamma, const float* __restrict__ beta,
                      float* __restrict__ scale, float* __restrict__ shift){
    const int d = blockIdx.x;      // 0..127
    __shared__ float red[256];
    float s = 0.f;
    const float* ps = g_eps + (size_t)d*NT2;
    for (int i = threadIdx.x; i < NT2; i += 256) s += ps[i];
    red[threadIdx.x] = s; __syncthreads();
    for (int o = 128; o > 0; o >>= 1){
        if (threadIdx.x < o) red[threadIdx.x] += red[threadIdx.x + o];
        __syncthreads();
    }
    float sum = red[0];
    __syncthreads();
    float q = 0.f;
    const float* pq = g_eps + (size_t)(DD+d)*NT2;
    for (int i = threadIdx.x; i < NT2; i += 256) q += pq[i];
    red[threadIdx.x] = q; __syncthreads();
    for (int o = 128; o > 0; o >>= 1){
        if (threadIdx.x < o) red[threadIdx.x] += red[threadIdx.x + o];
        __syncthreads();
    }
    if (threadIdx.x == 0){
        float sumsq = red[0];
        float m   = sum / (float)EE;
        float var = sumsq / (float)EE - m*m;
        float inv = rsqrtf(var + BN_EPS);
        float sc  = inv * gamma[d];
        scale[d] = sc;
        shift[d] = beta[d] - m*sc;
    }
}

// ---------------- merged node GEMM (2x64-row tiles/block, optional fused h-apply) ----
template<int APPLY>
__global__ void __launch_bounds__(512,2) k_mma_gemm4(const float* __restrict__ hin,
        float* __restrict__ hout,
        const unsigned short* __restrict__ w0, const unsigned short* __restrict__ w1,
        const unsigned short* __restrict__ w2, const unsigned short* __restrict__ w3,
        const float* __restrict__ b0, const float* __restrict__ b1,
        const float* __restrict__ b2, const float* __restrict__ b3,
        float* __restrict__ o0, float* __restrict__ o1,
        float* __restrict__ o2, float* __restrict__ o3,
        const float* __restrict__ scH, const float* __restrict__ shH, int rows){
    extern __shared__ __align__(16) char smem[];
    uint32_t sb = smem_u32(smem);
    const int t = threadIdx.x, lane = t & 31, wid = t >> 5;
    const int wm = wid >> 2, wn = wid & 3;
    const int y = blockIdx.y;
    const unsigned short* wslot = (y==0) ? w0 : (y==1) ? w1 : (y==2) ? w2 : w3;
    const float* bias           = (y==0) ? b0 : (y==1) ? b1 : (y==2) ? b2 : b3;
    float* out                  = (y==0) ? o0 : (y==1) ? o1 : (y==2) ? o2 : o3;

    copy_w_async(sb, H_BHI, wslot, t);
    CP_COMMIT();

    const float4* A4 = (const float4*)hin;
    const float4* T4 = (const float4*)g_tmp;
    float4* HO4 = (float4*)hout;
    const float4* sc4 = (const float4*)scH;
    const float4* sh4 = (const float4*)shH;
    float4* out4 = (float4*)out;

    #pragma unroll
    for (int tile = 0; tile < 2; tile++){
        const int row0 = blockIdx.x * 128 + tile * 64;
        #pragma unroll
        for (int it = 0; it < 4; it++){
            int idx = it*512 + t;
            int r = idx >> 5, c4 = idx & 31;
            float4 v = make_float4(0.f,0.f,0.f,0.f);
            if (row0 + r < rows){
                size_t gi = (size_t)(row0 + r)*32 + c4;
                v = A4[gi];
                if (APPLY){
                    float4 tm = T4[gi], S = sc4[c4], H = sh4[c4];
                    v.x += silu(fmaf(tm.x, S.x, H.x));
                    v.y += silu(fmaf(tm.y, S.y, H.y));
                    v.z += silu(fmaf(tm.z, S.z, H.z));
                    v.w += silu(fmaf(tm.w, S.w, H.w));
                    if (y == 0) HO4[gi] = v;
                }
            }
            stage_store(smem, r, c4, v);
        }
        if (tile == 0) CP_WAIT();
        __syncthreads();

        float acc[1][4][4];
        #pragma unroll
        for (int j=0;j<4;j++) for(int k=0;k<4;k++) acc[0][j][k]=0.f;
        gemm_core<1,HPL>(sb, H_AHI, H_BHI, t, acc);
        __syncthreads();

        // fragments -> smem D [row][col] stride 132 (overlay A region)
        float* sD = (float*)(smem + H_AHI);
        {
            int r0 = wm*16 + (lane>>2);
            #pragma unroll
            for (int nt = 0; nt < 4; nt++){
                int c0 = wn*32 + nt*8 + (lane&3)*2;
                float* c = acc[0][nt];
                *(float2*)&sD[r0*132 + c0]     = make_float2(c[0], c[1]);
                *(float2*)&sD[(r0+8)*132 + c0] = make_float2(c[2], c[3]);
            }
        }
        __syncthreads();

        #pragma unroll
        for (int it = 0; it < 4; it++){
            int idx = it*512 + t;
            int r = idx >> 5, c4 = idx & 31;
            if (row0 + r < rows){
                float4 v = *(const float4*)&sD[r*132 + c4*4];
                const float4 b = *(const float4*)(bias + c4*4);
                v.x += b.x; v.y += b.y; v.z += b.z; v.w += b.w;
                out4[(size_t)(row0 + r)*32 + c4] = v;
            }
        }
        __syncthreads();
    }
}

// ---------------- fused edge kernel ----------------
// EINIT: e = silu(ea*ew+eb) computed in staging (layer 0), written to g_e.
// APPLY: e = e + silu(et*sc+sh) (later layers). DOMSG: gated message scatter.
template<int EINIT, int APPLY, int DOMSG>
__global__ void __launch_bounds__(512,2) k_edge_mma(const unsigned short* __restrict__ wslot,
                                                    const float* __restrict__ ab,
                                                    const int* __restrict__ src,
                                                    const int* __restrict__ dst,
                                                    const float* __restrict__ scE,
                                                    const float* __restrict__ shE,
                                                    const float* __restrict__ ea,
                                                    const float* __restrict__ ew,
                                                    const float* __restrict__ eb){
    extern __shared__ __align__(16) char smem[];
    uint32_t sb = smem_u32(smem);
    const int t = threadIdx.x, lane = t & 31, wid = t >> 5;
    const int wm = wid >> 2, wn = wid & 3;
    const int blk = blockIdx.x;
    const int e0 = blk * 128;

    copy_w_async(sb, H_BHI, wslot, t);
    CP_COMMIT();

    int* shs = (int*)(smem + H_SRC);
    int* sht = (int*)(smem + H_DST);
    float* sS = (float*)(smem + H_SS);
    float* sQ = (float*)(smem + H_SQ);
    if (t < 128){ shs[t] = src[e0+t]; sht[t] = dst[e0+t]; sS[t] = 0.f; sQ[t] = 0.f; }

    float4* ge4  = (float4*)g_e;
    const float4* get4 = (const float4*)g_et;
    const float4* sc4 = (const float4*)scE;
    const float4* sh4 = (const float4*)shE;

    // epilogue mapping: warp = row-group, lane = col4
    const int c4e = t & 31, rg = t >> 5;
    const float4 b4 = *(const float4*)(ab + c4e*4);
    float4 s4 = make_float4(0.f,0.f,0.f,0.f);
    float4 q4 = make_float4(0.f,0.f,0.f,0.f);

    #pragma unroll
    for (int tile = 0; tile < 2; tile++){
        const int r0g = e0 + tile * 64;
        // stage: compute/apply e, split into A planes
        #pragma unroll
        for (int it = 0; it < 4; it++){
            int idx = it*512 + t;
            int r = idx >> 5, c4 = idx & 31;
            size_t gi = (size_t)(r0g + r)*32 + c4;
            float4 ev;
            if (EINIT){
                float a = ea[r0g + r];
                float4 W  = *(const float4*)(ew + c4*4);
                float4 B  = *(const float4*)(eb + c4*4);
                ev.x = silu(fmaf(a, W.x, B.x));
                ev.y = silu(fmaf(a, W.y, B.y));
                ev.z = silu(fmaf(a, W.z, B.z));
                ev.w = silu(fmaf(a, W.w, B.w));
                ge4[gi] = ev;
            } else {
                ev = ge4[gi];
                if (APPLY){
                    float4 et = get4[gi], S = sc4[c4], H = sh4[c4];
                    ev.x += silu(fmaf(et.x, S.x, H.x));
                    ev.y += silu(fmaf(et.y, S.y, H.y));
                    ev.z += silu(fmaf(et.z, S.z, H.z));
                    ev.w += silu(fmaf(et.w, S.w, H.w));
                    ge4[gi] = ev;
                }
            }
            stage_store(smem, r, c4, ev);
        }
        if (tile == 0) CP_WAIT();
        __syncthreads();

        float acc[1][4][4];
        #pragma unroll
        for (int j=0;j<4;j++) for(int k=0;k<4;k++) acc[0][j][k]=0.f;
        gemm_core<1,HPL>(sb, H_AHI, H_BHI, t, acc);
        __syncthreads();

        // fragments -> smem D [row][col] stride 132 (overlay A region)
        float* sD = (float*)(smem + H_AHI);
        {
            int r0 = wm*16 + (lane>>2);
            #pragma unroll
            for (int nt = 0; nt < 4; nt++){
                int c0 = wn*32 + nt*8 + (lane&3)*2;
                float* c = acc[0][nt];
                *(float2*)&sD[r0*132 + c0]     = make_float2(c[0], c[1]);
                *(float2*)&sD[(r0+8)*132 + c0] = make_float2(c[2], c[3]);
            }
        }
        __syncthreads();

        // float4 epilogue with cross-iteration Bh/Ch prefetch
        int css = shs[tile*64 + rg], ctt = sht[tile*64 + rg];
        float4 cbh = *(const float4*)&g_Bh[(size_t)css*DD + c4e*4];
        float4 cch = *(const float4*)&g_Ch[(size_t)ctt*DD + c4e*4];
        #pragma unroll
        for (int i = 0; i < 4; i++){
            int r = rg + i*16;
            int nss = 0, ntt = 0;
            float4 nbh, nch;
            if (i < 3){
                int nli = tile*64 + r + 16;
                nss = shs[nli]; ntt = sht[nli];
                nbh = *(const float4*)&g_Bh[(size_t)nss*DD + c4e*4];
                nch = *(const float4*)&g_Ch[(size_t)ntt*DD + c4e*4];
            }
            float4 d = *(const float4*)&sD[r*132 + c4e*4];
            d.x += b4.x + cbh.x + cch.x;
            d.y += b4.y + cbh.y + cch.y;
            d.z += b4.z + cbh.z + cch.z;
            d.w += b4.w + cbh.w + cch.w;
            *(float4*)&g_et[(size_t)(r0g + r)*DD + c4e*4] = d;
            s4.x += d.x; s4.y += d.y; s4.z += d.z; s4.w += d.w;
            q4.x = fmaf(d.x,d.x,q4.x); q4.y = fmaf(d.y,d.y,q4.y);
            q4.z = fmaf(d.z,d.z,q4.z); q4.w = fmaf(d.w,d.w,q4.w);
            if (DOMSG){
                float4 ev = *(const float4*)&g_e[(size_t)(r0g + r)*DD + c4e*4];
                float4 vh = *(const float4*)&g_Vh[(size_t)ctt*DD + c4e*4];
                float4 m;
                m.x = sigm(ev.x)*vh.x; m.y = sigm(ev.y)*vh.y;
                m.z = sigm(ev.z)*vh.z; m.w = sigm(ev.w)*vh.w;
                red_add_v4(&g_agg[(size_t)css*DD + c4e*4], m);
            }
            css = nss; ctt = ntt; cbh = nbh; cch = nch;
        }
        __syncthreads();   // sD consumed before next tile's staging overwrites A
    }

    atomicAdd(&sS[c4e*4+0], s4.x); atomicAdd(&sS[c4e*4+1], s4.y);
    atomicAdd(&sS[c4e*4+2], s4.z); atomicAdd(&sS[c4e*4+3], s4.w);
    atomicAdd(&sQ[c4e*4+0], q4.x); atomicAdd(&sQ[c4e*4+1], q4.y);
    atomicAdd(&sQ[c4e*4+2], q4.z); atomicAdd(&sQ[c4e*4+3], q4.w);
    __syncthreads();
    if (t < 128){
        g_eps[(size_t)t*NT2 + blk]      = sS[t];
        g_eps[(size_t)(DD+t)*NT2 + blk] = sQ[t];
    }
}

// ---------------- fused final: e-apply -> MLP(2 GEMMs) -> sigmoid dot (M=128) ----------------
__global__ void __launch_bounds__(512,1) k_final_mma(const unsigned short* __restrict__ w1,
                                                     const unsigned short* __restrict__ w2,
                                                     const float* __restrict__ f1b,
                                                     const float* __restrict__ f2b,
                                                     const float* __restrict__ f3w,
                                                     const float* __restrict__ f3b,
                                                     const float* __restrict__ scE,
                                                     const float* __restrict__ shE,
                                                     float* __restrict__ out){
    extern __shared__ __align__(16) char smem[];
    uint32_t sb = smem_u32(smem);
    const int t = threadIdx.x, lane = t & 31, wid = t >> 5;
    const int wm = wid >> 2, wn = wid & 3;
    const int e0 = blockIdx.x * 128;

    float* sRow = (float*)(smem + F_ROW);
    if (t < 128) sRow[t] = 0.f;

    copy_w_async(sb, F_BHI, w1, t);
    CP_COMMIT();

    const float4* ge4  = (const float4*)g_e;
    const float4* get4 = (const float4*)g_et;
    const float4* sc4  = (const float4*)scE;
    const float4* sh4  = (const float4*)shE;
    #pragma unroll
    for (int it = 0; it < 8; it++){
        int idx = it*512 + t;
        int r = idx >> 5, c4 = idx & 31;
        size_t gi = (size_t)(e0 + r)*32 + c4;
        float4 ev = ge4[gi];
        float4 et = get4[gi], S = sc4[c4], H = sh4[c4];
        ev.x += silu(fmaf(et.x, S.x, H.x));
        ev.y += silu(fmaf(et.y, S.y, H.y));
        ev.z += silu(fmaf(et.z, S.z, H.z));
        ev.w += silu(fmaf(et.w, S.w, H.w));
        int off = r*272 + c4*8;
        __nv_bfloat16 h0,l0,h1,l1,h2,l2,h3,l3;
        split_bf(ev.x,h0,l0); split_bf(ev.y,h1,l1); split_bf(ev.z,h2,l2); split_bf(ev.w,h3,l3);
        *(unsigned*)(smem + F_AHI + off)     = pack_bf2(h0,h1);
        *(unsigned*)(smem + F_AHI + off + 4) = pack_bf2(h2,h3);
        *(unsigned*)(smem + F_ALO + off)     = pack_bf2(l0,l1);
        *(unsigned*)(smem + F_ALO + off + 4) = pack_bf2(l2,l3);
    }
    CP_WAIT();
    __syncthreads();

    float acc[2][4][4];
    #pragma unroll
    for (int i=0;i<2;i++) for(int j=0;j<4;j++) for(int k=0;k<4;k++) acc[i][j][k]=0.f;
    gemm_core<2,PL>(sb, F_AHI, F_BHI, t, acc);
    __syncthreads();

    copy_w_async(sb, F_AHI, w2, t);
    CP_COMMIT();
    #pragma unroll
    for (int mt = 0; mt < 2; mt++){
        int r0 = wm*32 + mt*16 + (lane>>2);
        #pragma unroll
        for (int nt = 0; nt < 4; nt++){
            int c0 = wn*32 + nt*8 + (lane&3)*2;
            float* c = acc[mt][nt];
            float v0 = silu(c[0] + f1b[c0]);
            float v1 = silu(c[1] + f1b[c0+1]);
            float v2 = silu(c[2] + f1b[c0]);
            float v3 = silu(c[3] + f1b[c0+1]);
            __nv_bfloat16 h0,l0,h1,l1;
            split_bf(v0,h0,l0); split_bf(v1,h1,l1);
            *(unsigned*)(smem + F_BHI + r0*272 + c0*2) = pack_bf2(h0,h1);
            *(unsigned*)(smem + F_BLO + r0*272 + c0*2) = pack_bf2(l0,l1);
            split_bf(v2,h0,l0); split_bf(v3,h1,l1);
            *(unsigned*)(smem + F_BHI + (r0+8)*272 + c0*2) = pack_bf2(h0,h1);
            *(unsigned*)(smem + F_BLO + (r0+8)*272 + c0*2) = pack_bf2(l0,l1);
        }
    }
    CP_WAIT();
    __syncthreads();

    #pragma unroll
    for (int i=0;i<2;i++) for(int j=0;j<4;j++) for(int k=0;k<4;k++) acc[i][j][k]=0.f;
    gemm_core<2,PL>(sb, F_BHI, F_AHI, t, acc);

    #pragma unroll
    for (int mt = 0; mt < 2; mt++){
        float r0s = 0.f, r1s = 0.f;
        #pragma unroll
        for (int nt = 0; nt < 4; nt++){
            int c0 = wn*32 + nt*8 + (lane&3)*2;
            float* c = acc[mt][nt];
            float w0 = f3w[c0], w1 = f3w[c0+1];
            float b0 = f2b[c0], b1 = f2b[c0+1];
            r0s = fmaf(silu(c[0]+b0), w0, fmaf(silu(c[1]+b1), w1, r0s));
            r1s = fmaf(silu(c[2]+b0), w0, fmaf(silu(c[3]+b1), w1, r1s));
        }
        r0s += __shfl_xor_sync(0xffffffff, r0s, 1);
        r0s += __shfl_xor_sync(0xffffffff, r0s, 2);
        r1s += __shfl_xor_sync(0xffffffff, r1s, 1);
        r1s += __shfl_xor_sync(0xffffffff, r1s, 2);
        if ((lane & 3) == 0){
            int r0 = wm*32 + mt*16 + (lane>>2);
            atomicAdd(&sRow[r0], r0s);
            atomicAdd(&sRow[r0+8], r1s);
        }
    }
    __syncthreads();
    if (t < 128) out[e0 + t] = sigm(sRow[t] + f3b[0]);
}

// ---------------- host orchestration ----------------
extern "C" void kernel_launch(void* const* d_in, const int* in_sizes, int n_in,
                              void* d_out, int out_size){
    const float* x    = (const float*)d_in[0];
    const float* ea   = (const float*)d_in[1];
    const int*   eidx = (const int*)  d_in[2];
    const float* hp_w = (const float*)d_in[3];
    const float* hp_b = (const float*)d_in[4];
    const float* ep_w = (const float*)d_in[5];
    const float* ep_b = (const float*)d_in[6];
    const float* Uw   = (const float*)d_in[7];
    const float* Ub   = (const float*)d_in[8];
    const float* Vw   = (const float*)d_in[9];
    const float* Vb   = (const float*)d_in[10];
    const float* Aw   = (const float*)d_in[11];
    const float* Ab   = (const float*)d_in[12];
    const float* Bw   = (const float*)d_in[13];
    const float* Bb   = (const float*)d_in[14];
    const float* Cw   = (const float*)d_in[15];
    const float* Cb   = (const float*)d_in[16];
    const float* h_g  = (const float*)d_in[17];
    const float* h_bt = (const float*)d_in[18];
    const float* e_g  = (const float*)d_in[19];
    const float* e_bt = (const float*)d_in[20];
    const float* f1w  = (const float*)d_in[21];
    const float* f1b  = (const float*)d_in[22];
    const float* f2w  = (const float*)d_in[23];
    const float* f2b  = (const float*)d_in[24];
    const float* f3w  = (const float*)d_in[25];
    const float* f3b  = (const float*)d_in[26];
    float* out = (float*)d_out;

    const int* src = eidx;        // edge_index[0]: scatter target
    const int* dst = eidx + EE;   // edge_index[1]: gather source

    static bool init_done = false;
    static cudaStream_t s2;
    static cudaEvent_t evF[3], evE[3];
    if (!init_done){
        cudaFuncSetAttribute(k_mma_gemm4<0>,    cudaFuncAttributeMaxDynamicSharedMemorySize, SZ_GEMM);
        cudaFuncSetAttribute(k_mma_gemm4<1>,    cudaFuncAttributeMaxDynamicSharedMemorySize, SZ_GEMM);
        cudaFuncSetAttribute(k_edge_mma<1,0,1>, cudaFuncAttributeMaxDynamicSharedMemorySize, SZ_EDGE);
        cudaFuncSetAttribute(k_edge_mma<0,1,1>, cudaFuncAttributeMaxDynamicSharedMemorySize, SZ_EDGE);
        cudaFuncSetAttribute(k_edge_mma<0,1,0>, cudaFuncAttributeMaxDynamicSharedMemorySize, SZ_EDGE);
        cudaFuncSetAttribute(k_final_mma,       cudaFuncAttributeMaxDynamicSharedMemorySize, SZ_FIN);
        cudaStreamCreateWithFlags(&s2, cudaStreamNonBlocking);
        for (int i = 0; i < 3; i++){
            cudaEventCreateWithFlags(&evF[i], cudaEventDisableTiming);
            cudaEventCreateWithFlags(&evE[i], cudaEventDisableTiming);
        }
        init_done = true;
    }

    void* p;
    cudaGetSymbolAddress(&p, g_agg);   float* pagg  = (float*)p;
    cudaGetSymbolAddress(&p, g_cnti);  int*   pcnti = (int*)p;
    cudaGetSymbolAddress(&p, g_stats); float* pst   = (float*)p;
    cudaGetSymbolAddress(&p, g_scale); float* psc   = (float*)p;
    cudaGetSymbolAddress(&p, g_shift); float* psh   = (float*)p;
    cudaGetSymbolAddress(&p, g_h);     float* ph    = (float*)p;
    cudaGetSymbolAddress(&p, g_h2);    float* ph2   = (float*)p;
    cudaGetSymbolAddress(&p, g_Uh);    float* pUh   = (float*)p;
    cudaGetSymbolAddress(&p, g_Vh);    float* pVh   = (float*)p;
    cudaGetSymbolAddress(&p, g_Bh);    float* pBh   = (float*)p;
    cudaGetSymbolAddress(&p, g_Ch);    float* pCh   = (float*)p;
    cudaGetSymbolAddress(&p, g_wimg);  unsigned short* pw = (unsigned short*)p;

    // launch order (main): 1 prep, 2 init_h, 3 gemm4(L0), 4 zero_agg, 5 zero_cnti, 6 edge(L0)
    {
        dim3 g(DD, 15);
        k_prep_all<<<g, DD>>>(Uw, Vw, Aw, Bw, Cw, f1w, f2w);
    }
    k_init_h<<<(NN*32+255)/256, 256>>>(x, hp_w, hp_b);

    // h ping-pong: layer l reads hbuf[l], layer l+1 gemm writes hbuf[l+1]
    float* hbuf[3] = { ph, ph2, ph };

    for (int l = 0; l < LL; l++){
        const bool last = (l == LL-1);

        if (l == 0){
            dim3 grid(NTN, 4);
            k_mma_gemm4<0><<<grid, 512, SZ_GEMM>>>(hbuf[0], nullptr,
                pw + (size_t)0*32768, pw + (size_t)3*32768,
                pw + (size_t)9*32768, pw + (size_t)12*32768,
                Ub, Vb, Bb, Cb, pUh, pVh, pBh, pCh, psc, psh, NN);
            k_zero_f4<<<(NN*DD/4+255)/256, 256>>>((float4*)pagg, NN*DD/4);
            k_zero_i<<<(NN+255)/256, 256>>>(pcnti, NN);
        } else if (!last){
            dim3 grid(NTN, 4);
            k_mma_gemm4<1><<<grid, 512, SZ_GEMM>>>(hbuf[l-1], hbuf[l],
                pw + (size_t)(0+l)*32768, pw + (size_t)(3+l)*32768,
                pw + (size_t)(9+l)*32768, pw + (size_t)(12+l)*32768,
                Ub + l*DD, Vb + l*DD, Bb + l*DD, Cb + l*DD,
                pUh, pVh, pBh, pCh, psc, psh, NN);
            k_zero_f4<<<(NN*DD/4+255)/256, 256>>>((float4*)pagg, NN*DD/4);
        } else {
            dim3 grid(NTN, 2);
            k_mma_gemm4<1><<<grid, 512, SZ_GEMM>>>(hbuf[l-1], hbuf[l],
                pw + (size_t)(9+l)*32768, pw + (size_t)(12+l)*32768,
                pw + (size_t)(9+l)*32768, pw + (size_t)(12+l)*32768,
                Bb + l*DD, Cb + l*DD, Bb + l*DD, Cb + l*DD,
                pBh, pCh, pBh, pCh, psc, psh, NN);
        }

        // join: edge(l) needs scE/shE from ebn(l-1) on s2
        if (l > 0) cudaStreamWaitEvent(0, evE[l-1], 0);

        const unsigned short* aimg = pw + (size_t)(6+l)*32768;
        if (l == 0)
            k_edge_mma<1,0,1><<<NT2, 512, SZ_EDGE>>>(aimg, Ab + l*DD, src, dst,
                                                     psc+DD, psh+DD, ea, ep_w, ep_b);
        else if (!last)
            k_edge_mma<0,1,1><<<NT2, 512, SZ_EDGE>>>(aimg, Ab + l*DD, src, dst,
                                                     psc+DD, psh+DD, nullptr, nullptr, nullptr);
        else
            k_edge_mma<0,1,0><<<NT2, 512, SZ_EDGE>>>(aimg, Ab + l*DD, src, dst,
                                                     psc+DD, psh+DD, nullptr, nullptr, nullptr);

        // fork: ebn(l) on s2, overlapped with the node path below
        cudaEventRecord(evF[l], 0);
        cudaStreamWaitEvent(s2, evF[l], 0);
        k_ebn<<<DD, 256, 0, s2>>>(e_g + l*DD, e_bt + l*DD, psc + DD, psh + DD);
        cudaEventRecord(evE[l], s2);

        if (l == 0){
            k_count<<<(EE+255)/256, 256>>>(src);   // degrees (needed by tmp_stats)
        }

        if (!last){
            k_node_tmp_stats<256><<<(NN+255)/256, DD>>>(pst);
            k_bn_fin<<<1, DD>>>(pst, h_g + l*DD, h_bt + l*DD, (float)NN, psc, psh);
        }
    }

    // final needs ebn(L-1)
    cudaStreamWaitEvent(0, evE[LL-1], 0);
    k_final_mma<<<NT2, 512, SZ_FIN>>>(pw + (size_t)15*32768, pw + (size_t)16*32768,
                                      f1b, f2b, f3w, f3b, psc + DD, psh + DD, out);
}

// round 16
// speedup vs baseline: 2.2449x; 1.0144x over previous
#include <cuda_runtime.h>
#include <cuda_bf16.h>
#include <cstdint>
#include <math.h>

#define NN 20000
#define EE 320000
#define DD 128
#define LL 3
#define BN_EPS 1e-5f
#define NT2 2500            // edge blocks (128 edges = 2x64 tiles each)
#define NTN 157             // node blocks (2x64 rows each)
#define NTS 79              // tmp_stats blocks (256 rows each)

// plane geometry: rows padded to 272B (conflict-free ldmatrix)
#define PL  34816           // full plane (128 rows)
#define HPL 17408           // half plane (64 rows)

// half-M kernels (edge, node GEMM): A(2x17408) + W(2x34816); D overlays A
#define H_AHI 0
#define H_ALO 17408
#define H_BHI 34816
#define H_BLO 69632
#define H_SRC 104448
#define H_DST 104960
#define H_SS  105472
#define H_SQ  105984
#define SZ_EDGE 106496
#define SZ_GEMM 104448

// full-size final kernel
#define F_AHI 0
#define F_ALO 34816
#define F_BHI 69632
#define F_BLO 104448
#define F_ROW 139264
#define SZ_FIN 139776

// ---------------- scratch (device globals; no allocation) ----------------
__device__ float g_h [NN*DD];
__device__ float g_h2[NN*DD];
__device__ float g_e [EE*DD];
__device__ float g_et[EE*DD];
__device__ float g_Uh[NN*DD];
__device__ float g_Vh[NN*DD];
__device__ float g_Bh[NN*DD];
__device__ float g_Ch[NN*DD];
__device__ float g_agg[NN*DD];
__device__ float g_tmp[NN*DD];
__device__ int   g_cnti[NN];
__device__ unsigned g_tick;
__device__ float g_eps[2*DD*NT2];      // edge BN partials
__device__ float g_stats[4*DD];
__device__ float g_scale[2*DD];
__device__ float g_shift[2*DD];
// 17 weight slots: dense [k][n] split planes, hi (16384 ushort) then lo
__device__ unsigned short g_wimg[17*32768];

// ---------------- helpers ----------------
__device__ __forceinline__ float sigm(float v){ return 1.f/(1.f+__expf(-v)); }
__device__ __forceinline__ float silu(float v){ return v*sigm(v); }

__device__ __forceinline__ uint32_t smem_u32(const void* p){
    uint32_t a;
    asm("{ .reg .u64 t; cvta.to.shared.u64 t, %1; cvt.u32.u64 %0, t; }" : "=r"(a) : "l"(p));
    return a;
}
__device__ __forceinline__ void split_bf(float v, __nv_bfloat16& h, __nv_bfloat16& l){
    h = __float2bfloat16(v);
    l = __float2bfloat16(v - __bfloat162float(h));
}
__device__ __forceinline__ unsigned pack_bf2(__nv_bfloat16 a, __nv_bfloat16 b){
    __nv_bfloat162 p = __halves2bfloat162(a, b);
    return *reinterpret_cast<unsigned*>(&p);
}
__device__ __forceinline__ void ldsm4(uint32_t addr, uint32_t r[4]){
    asm volatile("ldmatrix.sync.aligned.m8n8.x4.shared.b16 {%0,%1,%2,%3}, [%4];"
        : "=r"(r[0]), "=r"(r[1]), "=r"(r[2]), "=r"(r[3]) : "r"(addr));
}
__device__ __forceinline__ void ldsm4t(uint32_t addr, uint32_t r[4]){
    asm volatile("ldmatrix.sync.aligned.m8n8.x4.trans.shared.b16 {%0,%1,%2,%3}, [%4];"
        : "=r"(r[0]), "=r"(r[1]), "=r"(r[2]), "=r"(r[3]) : "r"(addr));
}
__device__ __forceinline__ void mma16816(float c[4], const uint32_t a[4], uint32_t b0, uint32_t b1){
    asm volatile("mma.sync.aligned.m16n8k16.row.col.f32.bf16.bf16.f32 "
        "{%0,%1,%2,%3}, {%4,%5,%6,%7}, {%8,%9}, {%0,%1,%2,%3};"
        : "+f"(c[0]), "+f"(c[1]), "+f"(c[2]), "+f"(c[3])
        : "r"(a[0]), "r"(a[1]), "r"(a[2]), "r"(a[3]), "r"(b0), "r"(b1));
}
__device__ __forceinline__ void cp16(uint32_t daddr, const void* src){
    asm volatile("cp.async.cg.shared.global [%0], [%1], 16;" :: "r"(daddr), "l"(src));
}
#define CP_COMMIT() asm volatile("cp.async.commit_group;" ::: "memory")
#define CP_WAIT()   asm volatile("cp.async.wait_group 0;" ::: "memory")

// vector reduction to global (sm_90+, baseline PTX)
__device__ __forceinline__ void red_add_v4(float* addr, float4 v){
    asm volatile("red.global.add.v4.f32 [%0], {%1,%2,%3,%4};"
        :: "l"(addr), "f"(v.x), "f"(v.y), "f"(v.z), "f"(v.w) : "memory");
}

// warp-tiled split-bf16 GEMM core (512 threads / 16 warps).
template<int MSUB, int APL>
__device__ __forceinline__ void gemm_core(uint32_t sb, int offA, int offB, int t,
                                          float acc[MSUB][4][4]){
    const int lane = t & 31, wid = t >> 5;
    const int wm = wid >> 2, wn = wid & 3;
    uint32_t aBase = sb + offA + (uint32_t)(wm*(16*MSUB) + (lane&7) + ((lane>>3)&1)*8)*272
                   + (uint32_t)((lane>>4)*8)*2;
    uint32_t bBase = sb + offB + (uint32_t)((lane&7) + ((lane>>3)&1)*8)*272
                   + (uint32_t)(wn*32 + (lane>>4)*8)*2;
    #pragma unroll
    for (int kt = 0; kt < 8; kt++){
        uint32_t ah[MSUB][4], al[MSUB][4];
        #pragma unroll
        for (int ms = 0; ms < MSUB; ms++){
            ldsm4(aBase + ms*16*272 + kt*32,       ah[ms]);
            ldsm4(aBase + APL + ms*16*272 + kt*32, al[ms]);
        }
        uint32_t bh[2][4], bl[2][4];
        #pragma unroll
        for (int np = 0; np < 2; np++){
            ldsm4t(bBase + kt*4352 + np*32,      bh[np]);
            ldsm4t(bBase + PL + kt*4352 + np*32, bl[np]);
        }
        #pragma unroll
        for (int ms = 0; ms < MSUB; ms++){
            #pragma unroll
            for (int np = 0; np < 2; np++){
                #pragma unroll
                for (int sub = 0; sub < 2; sub++){
                    float* c = acc[ms][np*2 + sub];
                    uint32_t h0 = bh[np][sub*2], h1 = bh[np][sub*2+1];
                    mma16816(c, ah[ms], h0, h1);
                    mma16816(c, ah[ms], bl[np][sub*2], bl[np][sub*2+1]);
                    mma16816(c, al[ms], h0, h1);
                }
            }
        }
    }
}

// async copy of a prepped weight slot into padded smem planes (512 threads)
__device__ __forceinline__ void copy_w_async(uint32_t sb, int offB,
                                             const unsigned short* wslot, int t){
    const uint4* hi = (const uint4*)wslot;
    const uint4* lo = (const uint4*)(wslot + 16384);
    #pragma unroll
    for (int i = t; i < 2048; i += 512){
        int r = i >> 4, c = i & 15;
        uint32_t d = sb + offB + (uint32_t)(r*17 + c)*16;
        cp16(d,      hi + i);
        cp16(d + PL, lo + i);
    }
}

// split a staged float4 into A hi/lo planes
__device__ __forceinline__ void stage_store(char* smem, int r, int c4, float4 v){
    int off = r*272 + c4*8;
    __nv_bfloat16 h0,l0,h1,l1,h2,l2,h3,l3;
    split_bf(v.x,h0,l0); split_bf(v.y,h1,l1); split_bf(v.z,h2,l2); split_bf(v.w,h3,l3);
    *(unsigned*)(smem + H_AHI + off)     = pack_bf2(h0,h1);
    *(unsigned*)(smem + H_AHI + off + 4) = pack_bf2(h2,h3);
    *(unsigned*)(smem + H_ALO + off)     = pack_bf2(l0,l1);
    *(unsigned*)(smem + H_ALO + off + 4) = pack_bf2(l2,l3);
}

// ---------------- merged weight prep (also zeroes h-stat slots + tick) -------
__global__ void k_prep_all(const float* __restrict__ Uw, const float* __restrict__ Vw,
                           const float* __restrict__ Aw, const float* __restrict__ Bw,
                           const float* __restrict__ Cw, const float* __restrict__ f1w,
                           const float* __restrict__ f2w){
    int y = blockIdx.y;
    const float* W; int slot;
    if      (y < 2){ W = Uw + y*DD*DD;      slot = y; }
    else if (y < 4){ W = Vw + (y-2)*DD*DD;  slot = 3 + (y-2); }
    else if (y < 7){ W = Aw + (y-4)*DD*DD;  slot = 6 + (y-4); }
    else if (y < 10){ W = Bw + (y-7)*DD*DD; slot = 9 + (y-7); }
    else if (y < 13){ W = Cw + (y-10)*DD*DD; slot = 12 + (y-10); }
    else if (y == 13){ W = f1w; slot = 15; }
    else            { W = f2w; slot = 16; }
    int k = blockIdx.x, n = threadIdx.x;
    if (k == 0 && y == 0){
        g_stats[n] = 0.f; g_stats[DD+n] = 0.f;
        if (n == 0) g_tick = 0u;
    }
    unsigned short* base = g_wimg + (size_t)slot*32768;
    __nv_bfloat16 h, l; split_bf(W[k*DD + n], h, l);
    base[k*DD + n]         = __bfloat16_as_ushort(h);
    base[16384 + k*DD + n] = __bfloat16_as_ushort(l);
}

// ---------------- small kernels ----------------
__global__ void k_zero_f4(float4* p, int n){
    int i = blockIdx.x*blockDim.x + threadIdx.x;
    if (i < n) p[i] = make_float4(0.f,0.f,0.f,0.f);
}
__global__ void k_zero_i(int* p, int n){
    int i = blockIdx.x*blockDim.x + threadIdx.x;
    if (i < n) p[i] = 0;
}
__global__ void k_count(const int* __restrict__ src){
    int i = blockIdx.x*blockDim.x + threadIdx.x;
    if (i < EE) atomicAdd(&g_cnti[src[i]], 1);
}
// vectorized h init: one float4 per thread
__global__ void k_init_h(const float* __restrict__ x,
                         const float* __restrict__ hw, const float* __restrict__ hb){
    int idx = blockIdx.x*blockDim.x + threadIdx.x;
    if (idx >= NN*32) return;
    int n = idx >> 5, c4 = idx & 31;
    float2 xv = *(const float2*)(x + n*2);
    float4 w0 = *(const float4*)(hw + c4*4);
    float4 w1 = *(const float4*)(hw + DD + c4*4);
    float4 bb = *(const float4*)(hb + c4*4);
    float4 v;
    v.x = silu(fmaf(xv.x, w0.x, fmaf(xv.y, w1.x, bb.x)));
    v.y = silu(fmaf(xv.x, w0.y, fmaf(xv.y, w1.y, bb.y)));
    v.z = silu(fmaf(xv.x, w0.z, fmaf(xv.y, w1.z, bb.z)));
    v.w = silu(fmaf(xv.x, w0.w, fmaf(xv.y, w1.w, bb.w)));
    *(float4*)&g_h[(size_t)n*DD + c4*4] = v;
}
// fused: tmp = Uh + agg/cnt (write, then zero agg) + column stats;
// last block finalizes h-BN (scale/shift) via ticket and re-zeroes pst.
template<int R>
__global__ void k_node_tmp_stats(float* __restrict__ pst,
                                 const float* __restrict__ gamma,
                                 const float* __restrict__ beta,
                                 float* __restrict__ scale, float* __restrict__ shift){
    const int d = threadIdx.x;
    const int r0 = blockIdx.x * R;
    const int r1 = min(NN, r0 + R);
    float s = 0.f, q = 0.f;
    for (int r = r0; r < r1; r++){
        float rc = fmaxf((float)g_cnti[r], 1.f);
        float v = g_Uh[(size_t)r*DD + d] + g_agg[(size_t)r*DD + d] / rc;
        g_tmp[(size_t)r*DD + d] = v;
        g_agg[(size_t)r*DD + d] = 0.f;      // pre-zero for next layer's scatter
        s += v; q = fmaf(v, v, q);
    }
    atomicAdd(&pst[d], s);
    atomicAdd(&pst[DD+d], q);
    __threadfence();
    __shared__ unsigned ord;
    if (d == 0) ord = atomicInc(&g_tick, gridDim.x - 1);
    __syncthreads();
    if (ord == gridDim.x - 1){
        float m   = pst[d] / (float)NN;
        float var = pst[DD+d] / (float)NN - m*m;
        float inv = rsqrtf(var + BN_EPS);
        float sc  = inv * gamma[d];
        scale[d] = sc;
        shift[d] = beta[d] - m*sc;
        pst[d] = 0.f; pst[DD+d] = 0.f;
    }
}
// fused edge-BN: reduce partials + compute scale/shift
__global__ void k_ebn(const float* __restrict__ gamma, const float* __restrict__ beta,
                      float* __restrict__ scale, float* __restrict__ shift){
    const int d = blockIdx.x;      // 0..127
    __shared__ float red[256];
    float s = 0.f;
    const float* ps = g_eps + (size_t)d*NT2;
    for (int i = threadIdx.x; i < NT2; i += 256) s += ps[i];
    red[threadIdx.x] = s; __syncthreads();
    for (int o = 128; o > 0; o >>= 1){
        if (threadIdx.x < o) red[threadIdx.x] += red[threadIdx.x + o];
        __syncthreads();
    }
    float sum = red[0];
    __syncthreads();
    float q = 0.f;
    const float* pq = g_eps + (size_t)(DD+d)*NT2;
    for (int i = threadIdx.x; i < NT2; i += 256) q += pq[i];
    red[threadIdx.x] = q; __syncthreads();
    for (int o = 128; o > 0; o >>= 1){
        if (threadIdx.x < o) red[threadIdx.x] += red[threadIdx.x + o];
        __syncthreads();
    }
    if (threadIdx.x == 0){
        float sumsq = red[0];
        float m   = sum / (float)EE;
        float var = sumsq / (float)EE - m*m;
        float inv = rsqrtf(var + BN_EPS);
        float sc  = inv * gamma[d];
        scale[d] = sc;
        shift[d] = beta[d] - m*sc;
    }
}

// ---------------- merged node GEMM (2x64-row tiles/block, optional fused h-apply) ----
// APPLY: stages v = hin + silu(tmp*scH+shH); writeH && y==0 writes v to hout.
template<int APPLY>
__global__ void __launch_bounds__(512,2) k_mma_gemm4(const float* __restrict__ hin,
        float* __restrict__ hout, int writeH,
        const unsigned short* __restrict__ w0, const unsigned short* __restrict__ w1,
        const unsigned short* __restrict__ w2,
        const float* __restrict__ b0, const float* __restrict__ b1,
        const float* __restrict__ b2,
        float* __restrict__ o0, float* __restrict__ o1, float* __restrict__ o2,
        const float* __restrict__ scH, const float* __restrict__ shH, int rows){
    extern __shared__ __align__(16) char smem[];
    uint32_t sb = smem_u32(smem);
    const int t = threadIdx.x, lane = t & 31, wid = t >> 5;
    const int wm = wid >> 2, wn = wid & 3;
    const int y = blockIdx.y;
    const unsigned short* wslot = (y==0) ? w0 : (y==1) ? w1 : w2;
    const float* bias           = (y==0) ? b0 : (y==1) ? b1 : b2;
    float* out                  = (y==0) ? o0 : (y==1) ? o1 : o2;

    copy_w_async(sb, H_BHI, wslot, t);
    CP_COMMIT();

    const float4* A4 = (const float4*)hin;
    const float4* T4 = (const float4*)g_tmp;
    float4* HO4 = (float4*)hout;
    const float4* sc4 = (const float4*)scH;
    const float4* sh4 = (const float4*)shH;
    float4* out4 = (float4*)out;

    #pragma unroll
    for (int tile = 0; tile < 2; tile++){
        const int row0 = blockIdx.x * 128 + tile * 64;
        #pragma unroll
        for (int it = 0; it < 4; it++){
            int idx = it*512 + t;
            int r = idx >> 5, c4 = idx & 31;
            float4 v = make_float4(0.f,0.f,0.f,0.f);
            if (row0 + r < rows){
                size_t gi = (size_t)(row0 + r)*32 + c4;
                v = A4[gi];
                if (APPLY){
                    float4 tm = T4[gi], S = sc4[c4], H = sh4[c4];
                    v.x += silu(fmaf(tm.x, S.x, H.x));
                    v.y += silu(fmaf(tm.y, S.y, H.y));
                    v.z += silu(fmaf(tm.z, S.z, H.z));
                    v.w += silu(fmaf(tm.w, S.w, H.w));
                    if (writeH && y == 0) HO4[gi] = v;
                }
            }
            stage_store(smem, r, c4, v);
        }
        if (tile == 0) CP_WAIT();
        __syncthreads();

        float acc[1][4][4];
        #pragma unroll
        for (int j=0;j<4;j++) for(int k=0;k<4;k++) acc[0][j][k]=0.f;
        gemm_core<1,HPL>(sb, H_AHI, H_BHI, t, acc);
        __syncthreads();

        // fragments -> smem D [row][col] stride 132 (overlay A region)
        float* sD = (float*)(smem + H_AHI);
        {
            int r0 = wm*16 + (lane>>2);
            #pragma unroll
            for (int nt = 0; nt < 4; nt++){
                int c0 = wn*32 + nt*8 + (lane&3)*2;
                float* c = acc[0][nt];
                *(float2*)&sD[r0*132 + c0]     = make_float2(c[0], c[1]);
                *(float2*)&sD[(r0+8)*132 + c0] = make_float2(c[2], c[3]);
            }
        }
        __syncthreads();

        #pragma unroll
        for (int it = 0; it < 4; it++){
            int idx = it*512 + t;
            int r = idx >> 5, c4 = idx & 31;
            if (row0 + r < rows){
                float4 v = *(const float4*)&sD[r*132 + c4*4];
                const float4 b = *(const float4*)(bias + c4*4);
                v.x += b.x; v.y += b.y; v.z += b.z; v.w += b.w;
                out4[(size_t)(row0 + r)*32 + c4] = v;
            }
        }
        __syncthreads();
    }
}

// ---------------- fused edge kernel ----------------
template<int EINIT, int APPLY, int DOMSG>
__global__ void __launch_bounds__(512,2) k_edge_mma(const unsigned short* __restrict__ wslot,
                                                    const float* __restrict__ ab,
                                                    const int* __restrict__ src,
                                                    const int* __restrict__ dst,
                                                    const float* __restrict__ scE,
                                                    const float* __restrict__ shE,
                                                    const float* __restrict__ ea,
                                                    const float* __restrict__ ew,
                                                    const float* __restrict__ eb){
    extern __shared__ __align__(16) char smem[];
    uint32_t sb = smem_u32(smem);
    const int t = threadIdx.x, lane = t & 31, wid = t >> 5;
    const int wm = wid >> 2, wn = wid & 3;
    const int blk = blockIdx.x;
    const int e0 = blk * 128;

    copy_w_async(sb, H_BHI, wslot, t);
    CP_COMMIT();

    int* shs = (int*)(smem + H_SRC);
    int* sht = (int*)(smem + H_DST);
    float* sS = (float*)(smem + H_SS);
    float* sQ = (float*)(smem + H_SQ);
    if (t < 128){ shs[t] = src[e0+t]; sht[t] = dst[e0+t]; sS[t] = 0.f; sQ[t] = 0.f; }

    float4* ge4  = (float4*)g_e;
    const float4* get4 = (const float4*)g_et;
    const float4* sc4 = (const float4*)scE;
    const float4* sh4 = (const float4*)shE;

    const int c4e = t & 31, rg = t >> 5;
    const float4 b4 = *(const float4*)(ab + c4e*4);
    float4 s4 = make_float4(0.f,0.f,0.f,0.f);
    float4 q4 = make_float4(0.f,0.f,0.f,0.f);

    #pragma unroll
    for (int tile = 0; tile < 2; tile++){
        const int r0g = e0 + tile * 64;
        #pragma unroll
        for (int it = 0; it < 4; it++){
            int idx = it*512 + t;
            int r = idx >> 5, c4 = idx & 31;
            size_t gi = (size_t)(r0g + r)*32 + c4;
            float4 ev;
            if (EINIT){
                float a = ea[r0g + r];
                float4 W  = *(const float4*)(ew + c4*4);
                float4 B  = *(const float4*)(eb + c4*4);
                ev.x = silu(fmaf(a, W.x, B.x));
                ev.y = silu(fmaf(a, W.y, B.y));
                ev.z = silu(fmaf(a, W.z, B.z));
                ev.w = silu(fmaf(a, W.w, B.w));
                ge4[gi] = ev;
            } else {
                ev = ge4[gi];
                if (APPLY){
                    float4 et = get4[gi], S = sc4[c4], H = sh4[c4];
                    ev.x += silu(fmaf(et.x, S.x, H.x));
                    ev.y += silu(fmaf(et.y, S.y, H.y));
                    ev.z += silu(fmaf(et.z, S.z, H.z));
                    ev.w += silu(fmaf(et.w, S.w, H.w));
                    ge4[gi] = ev;
                }
            }
            stage_store(smem, r, c4, ev);
        }
        if (tile == 0) CP_WAIT();
        __syncthreads();

        float acc[1][4][4];
        #pragma unroll
        for (int j=0;j<4;j++) for(int k=0;k<4;k++) acc[0][j][k]=0.f;
        gemm_core<1,HPL>(sb, H_AHI, H_BHI, t, acc);
        __syncthreads();

        float* sD = (float*)(smem + H_AHI);
        {
            int r0 = wm*16 + (lane>>2);
            #pragma unroll
            for (int nt = 0; nt < 4; nt++){
                int c0 = wn*32 + nt*8 + (lane&3)*2;
                float* c = acc[0][nt];
                *(float2*)&sD[r0*132 + c0]     = make_float2(c[0], c[1]);
                *(float2*)&sD[(r0+8)*132 + c0] = make_float2(c[2], c[3]);
            }
        }
        __syncthreads();

        // float4 epilogue with cross-iteration Bh/Ch prefetch
        int css = shs[tile*64 + rg], ctt = sht[tile*64 + rg];
        float4 cbh = *(const float4*)&g_Bh[(size_t)css*DD + c4e*4];
        float4 cch = *(const float4*)&g_Ch[(size_t)ctt*DD + c4e*4];
        #pragma unroll
        for (int i = 0; i < 4; i++){
            int r = rg + i*16;
            int nss = 0, ntt = 0;
            float4 nbh, nch;
            if (i < 3){
                int nli = tile*64 + r + 16;
                nss = shs[nli]; ntt = sht[nli];
                nbh = *(const float4*)&g_Bh[(size_t)nss*DD + c4e*4];
                nch = *(const float4*)&g_Ch[(size_t)ntt*DD + c4e*4];
            }
            float4 d = *(const float4*)&sD[r*132 + c4e*4];
            d.x += b4.x + cbh.x + cch.x;
            d.y += b4.y + cbh.y + cch.y;
            d.z += b4.z + cbh.z + cch.z;
            d.w += b4.w + cbh.w + cch.w;
            *(float4*)&g_et[(size_t)(r0g + r)*DD + c4e*4] = d;
            s4.x += d.x; s4.y += d.y; s4.z += d.z; s4.w += d.w;
            q4.x = fmaf(d.x,d.x,q4.x); q4.y = fmaf(d.y,d.y,q4.y);
            q4.z = fmaf(d.z,d.z,q4.z); q4.w = fmaf(d.w,d.w,q4.w);
            if (DOMSG){
                float4 ev = *(const float4*)&g_e[(size_t)(r0g + r)*DD + c4e*4];
                float4 vh = *(const float4*)&g_Vh[(size_t)ctt*DD + c4e*4];
                float4 m;
                m.x = sigm(ev.x)*vh.x; m.y = sigm(ev.y)*vh.y;
                m.z = sigm(ev.z)*vh.z; m.w = sigm(ev.w)*vh.w;
                red_add_v4(&g_agg[(size_t)css*DD + c4e*4], m);
            }
            css = nss; ctt = ntt; cbh = nbh; cch = nch;
        }
        __syncthreads();
    }

    atomicAdd(&sS[c4e*4+0], s4.x); atomicAdd(&sS[c4e*4+1], s4.y);
    atomicAdd(&sS[c4e*4+2], s4.z); atomicAdd(&sS[c4e*4+3], s4.w);
    atomicAdd(&sQ[c4e*4+0], q4.x); atomicAdd(&sQ[c4e*4+1], q4.y);
    atomicAdd(&sQ[c4e*4+2], q4.z); atomicAdd(&sQ[c4e*4+3], q4.w);
    __syncthreads();
    if (t < 128){
        g_eps[(size_t)t*NT2 + blk]      = sS[t];
        g_eps[(size_t)(DD+t)*NT2 + blk] = sQ[t];
    }
}

// ---------------- fused final: e-apply -> MLP(2 GEMMs) -> sigmoid dot (M=128) ----------------
__global__ void __launch_bounds__(512,1) k_final_mma(const unsigned short* __restrict__ w1,
                                                     const unsigned short* __restrict__ w2,
                                                     const float* __restrict__ f1b,
                                                     const float* __restrict__ f2b,
                                                     const float* __restrict__ f3w,
                                                     const float* __restrict__ f3b,
                                                     const float* __restrict__ scE,
                                                     const float* __restrict__ shE,
                                                     float* __restrict__ out){
    extern __shared__ __align__(16) char smem[];
    uint32_t sb = smem_u32(smem);
    const int t = threadIdx.x, lane = t & 31, wid = t >> 5;
    const int wm = wid >> 2, wn = wid & 3;
    const int e0 = blockIdx.x * 128;

    float* sRow = (float*)(smem + F_ROW);
    if (t < 128) sRow[t] = 0.f;

    copy_w_async(sb, F_BHI, w1, t);
    CP_COMMIT();

    const float4* ge4  = (const float4*)g_e;
    const float4* get4 = (const float4*)g_et;
    const float4* sc4  = (const float4*)scE;
    const float4* sh4  = (const float4*)shE;
    #pragma unroll
    for (int it = 0; it < 8; it++){
        int idx = it*512 + t;
        int r = idx >> 5, c4 = idx & 31;
        size_t gi = (size_t)(e0 + r)*32 + c4;
        float4 ev = ge4[gi];
        float4 et = get4[gi], S = sc4[c4], H = sh4[c4];
        ev.x += silu(fmaf(et.x, S.x, H.x));
        ev.y += silu(fmaf(et.y, S.y, H.y));
        ev.z += silu(fmaf(et.z, S.z, H.z));
        ev.w += silu(fmaf(et.w, S.w, H.w));
        int off = r*272 + c4*8;
        __nv_bfloat16 h0,l0,h1,l1,h2,l2,h3,l3;
        split_bf(ev.x,h0,l0); split_bf(ev.y,h1,l1); split_bf(ev.z,h2,l2); split_bf(ev.w,h3,l3);
        *(unsigned*)(smem + F_AHI + off)     = pack_bf2(h0,h1);
        *(unsigned*)(smem + F_AHI + off + 4) = pack_bf2(h2,h3);
        *(unsigned*)(smem + F_ALO + off)     = pack_bf2(l0,l1);
        *(unsigned*)(smem + F_ALO + off + 4) = pack_bf2(l2,l3);
    }
    CP_WAIT();
    __syncthreads();

    float acc[2][4][4];
    #pragma unroll
    for (int i=0;i<2;i++) for(int j=0;j<4;j++) for(int k=0;k<4;k++) acc[i][j][k]=0.f;
    gemm_core<2,PL>(sb, F_AHI, F_BHI, t, acc);
    __syncthreads();

    copy_w_async(sb, F_AHI, w2, t);
    CP_COMMIT();
    #pragma unroll
    for (int mt = 0; mt < 2; mt++){
        int r0 = wm*32 + mt*16 + (lane>>2);
        #pragma unroll
        for (int nt = 0; nt < 4; nt++){
            int c0 = wn*32 + nt*8 + (lane&3)*2;
            float* c = acc[mt][nt];
            float v0 = silu(c[0] + f1b[c0]);
            float v1 = silu(c[1] + f1b[c0+1]);
            float v2 = silu(c[2] + f1b[c0]);
            float v3 = silu(c[3] + f1b[c0+1]);
            __nv_bfloat16 h0,l0,h1,l1;
            split_bf(v0,h0,l0); split_bf(v1,h1,l1);
            *(unsigned*)(smem + F_BHI + r0*272 + c0*2) = pack_bf2(h0,h1);
            *(unsigned*)(smem + F_BLO + r0*272 + c0*2) = pack_bf2(l0,l1);
            split_bf(v2,h0,l0); split_bf(v3,h1,l1);
            *(unsigned*)(smem + F_BHI + (r0+8)*272 + c0*2) = pack_bf2(h0,h1);
            *(unsigned*)(smem + F_BLO + (r0+8)*272 + c0*2) = pack_bf2(l0,l1);
        }
    }
    CP_WAIT();
    __syncthreads();

    #pragma unroll
    for (int i=0;i<2;i++) for(int j=0;j<4;j++) for(int k=0;k<4;k++) acc[i][j][k]=0.f;
    gemm_core<2,PL>(sb, F_BHI, F_AHI, t, acc);

    #pragma unroll
    for (int mt = 0; mt < 2; mt++){
        float r0s = 0.f, r1s = 0.f;
        #pragma unroll
        for (int nt = 0; nt < 4; nt++){
            int c0 = wn*32 + nt*8 + (lane&3)*2;
            float* c = acc[mt][nt];
            float w0 = f3w[c0], w1 = f3w[c0+1];
            float b0 = f2b[c0], b1 = f2b[c0+1];
            r0s = fmaf(silu(c[0]+b0), w0, fmaf(silu(c[1]+b1), w1, r0s));
            r1s = fmaf(silu(c[2]+b0), w0, fmaf(silu(c[3]+b1), w1, r1s));
        }
        r0s += __shfl_xor_sync(0xffffffff, r0s, 1);
        r0s += __shfl_xor_sync(0xffffffff, r0s, 2);
        r1s += __shfl_xor_sync(0xffffffff, r1s, 1);
        r1s += __shfl_xor_sync(0xffffffff, r1s, 2);
        if ((lane & 3) == 0){
            int r0 = wm*32 + mt*16 + (lane>>2);
            atomicAdd(&sRow[r0], r0s);
            atomicAdd(&sRow[r0+8], r1s);
        }
    }
    __syncthreads();
    if (t < 128) out[e0 + t] = sigm(sRow[t] + f3b[0]);
}

// ---------------- host orchestration ----------------
extern "C" void kernel_launch(void* const* d_in, const int* in_sizes, int n_in,
                              void* d_out, int out_size){
    const float* x    = (const float*)d_in[0];
    const float* ea   = (const float*)d_in[1];
    const int*   eidx = (const int*)  d_in[2];
    const float* hp_w = (const float*)d_in[3];
    const float* hp_b = (const float*)d_in[4];
    const float* ep_w = (const float*)d_in[5];
    const float* ep_b = (const float*)d_in[6];
    const float* Uw   = (const float*)d_in[7];
    const float* Ub   = (const float*)d_in[8];
    const float* Vw   = (const float*)d_in[9];
    const float* Vb   = (const float*)d_in[10];
    const float* Aw   = (const float*)d_in[11];
    const float* Ab   = (const float*)d_in[12];
    const float* Bw   = (const float*)d_in[13];
    const float* Bb   = (const float*)d_in[14];
    const float* Cw   = (const float*)d_in[15];
    const float* Cb   = (const float*)d_in[16];
    const float* h_g  = (const float*)d_in[17];
    const float* h_bt = (const float*)d_in[18];
    const float* e_g  = (const float*)d_in[19];
    const float* e_bt = (const float*)d_in[20];
    const float* f1w  = (const float*)d_in[21];
    const float* f1b  = (const float*)d_in[22];
    const float* f2w  = (const float*)d_in[23];
    const float* f2b  = (const float*)d_in[24];
    const float* f3w  = (const float*)d_in[25];
    const float* f3b  = (const float*)d_in[26];
    float* out = (float*)d_out;

    const int* src = eidx;        // edge_index[0]: scatter target
    const int* dst = eidx + EE;   // edge_index[1]: gather source

    static bool init_done = false;
    static cudaStream_t s2;
    static cudaEvent_t evF[3], evE[3], evT[2], evU[2], evZ, evC;
    if (!init_done){
        cudaFuncSetAttribute(k_mma_gemm4<0>,    cudaFuncAttributeMaxDynamicSharedMemorySize, SZ_GEMM);
        cudaFuncSetAttribute(k_mma_gemm4<1>,    cudaFuncAttributeMaxDynamicSharedMemorySize, SZ_GEMM);
        cudaFuncSetAttribute(k_edge_mma<1,0,1>, cudaFuncAttributeMaxDynamicSharedMemorySize, SZ_EDGE);
        cudaFuncSetAttribute(k_edge_mma<0,1,1>, cudaFuncAttributeMaxDynamicSharedMemorySize, SZ_EDGE);
        cudaFuncSetAttribute(k_edge_mma<0,1,0>, cudaFuncAttributeMaxDynamicSharedMemorySize, SZ_EDGE);
        cudaFuncSetAttribute(k_final_mma,       cudaFuncAttributeMaxDynamicSharedMemorySize, SZ_FIN);
        cudaStreamCreateWithFlags(&s2, cudaStreamNonBlocking);
        for (int i = 0; i < 3; i++){
            cudaEventCreateWithFlags(&evF[i], cudaEventDisableTiming);
            cudaEventCreateWithFlags(&evE[i], cudaEventDisableTiming);
        }
        for (int i = 0; i < 2; i++){
            cudaEventCreateWithFlags(&evT[i], cudaEventDisableTiming);
            cudaEventCreateWithFlags(&evU[i], cudaEventDisableTiming);
        }
        cudaEventCreateWithFlags(&evZ, cudaEventDisableTiming);
        cudaEventCreateWithFlags(&evC, cudaEventDisableTiming);
        init_done = true;
    }

    void* p;
    cudaGetSymbolAddress(&p, g_agg);   float* pagg  = (float*)p;
    cudaGetSymbolAddress(&p, g_cnti);  int*   pcnti = (int*)p;
    cudaGetSymbolAddress(&p, g_stats); float* pst   = (float*)p;
    cudaGetSymbolAddress(&p, g_scale); float* psc   = (float*)p;
    cudaGetSymbolAddress(&p, g_shift); float* psh   = (float*)p;
    cudaGetSymbolAddress(&p, g_h);     float* ph    = (float*)p;
    cudaGetSymbolAddress(&p, g_h2);    float* ph2   = (float*)p;
    cudaGetSymbolAddress(&p, g_Uh);    float* pUh   = (float*)p;
    cudaGetSymbolAddress(&p, g_Vh);    float* pVh   = (float*)p;
    cudaGetSymbolAddress(&p, g_Bh);    float* pBh   = (float*)p;
    cudaGetSymbolAddress(&p, g_Ch);    float* pCh   = (float*)p;
    cudaGetSymbolAddress(&p, g_wimg);  unsigned short* pw = (unsigned short*)p;

    float* hbuf[3] = { ph, ph2, ph };

    // 1: prep (also zeroes pst + tick)
    {
        dim3 g(DD, 15);
        k_prep_all<<<g, DD>>>(Uw, Vw, Aw, Bw, Cw, f1w, f2w);
    }
    // 2: init_h
    k_init_h<<<(NN*32+255)/256, 256>>>(x, hp_w, hp_b);
    cudaEventRecord(evT[0], 0);   // h ready -> U0 on s2

    // 3: gemm4 VBC layer 0 (main)
    {
        dim3 grid(NTN, 3);
        k_mma_gemm4<0><<<grid, 512, SZ_GEMM>>>(hbuf[0], nullptr, 0,
            pw + (size_t)3*32768, pw + (size_t)9*32768, pw + (size_t)12*32768,
            Vb, Bb, Cb, pVh, pBh, pCh, psc, psh, NN);
    }
    // 4 (s2): zero_agg  -> evZ
    cudaStreamWaitEvent(s2, evT[0], 0);
    k_zero_f4<<<(NN*DD/4+255)/256, 256, 0, s2>>>((float4*)pagg, NN*DD/4);
    cudaEventRecord(evZ, s2);
    // 5 (s2): U-gemm layer 0
    {
        dim3 grid(NTN, 1);
        k_mma_gemm4<0><<<grid, 512, SZ_GEMM, s2>>>(hbuf[0], nullptr, 0,
            pw + (size_t)0*32768, pw + (size_t)0*32768, pw + (size_t)0*32768,
            Ub, Ub, Ub, pUh, pUh, pUh, psc, psh, NN);
    }
    // degree counts on s2 (after U0; joined via evC before tmp_stats(0))
    k_zero_i<<<(NN+255)/256, 256, 0, s2>>>(pcnti, NN);
    k_count<<<(EE+255)/256, 256, 0, s2>>>(src);
    cudaEventRecord(evC, s2);

    for (int l = 0; l < LL; l++){
        const bool last = (l == LL-1);

        if (l > 0){
            // gemm4 for this layer (APPLY): VBC or BC
            if (!last){
                dim3 grid(NTN, 3);
                k_mma_gemm4<1><<<grid, 512, SZ_GEMM>>>(hbuf[l-1], hbuf[l], 1,
                    pw + (size_t)(3+l)*32768, pw + (size_t)(9+l)*32768, pw + (size_t)(12+l)*32768,
                    Vb + l*DD, Bb + l*DD, Cb + l*DD, pVh, pBh, pCh, psc, psh, NN);
            } else {
                dim3 grid(NTN, 2);
                k_mma_gemm4<1><<<grid, 512, SZ_GEMM>>>(hbuf[l-1], nullptr, 0,
                    pw + (size_t)(9+l)*32768, pw + (size_t)(12+l)*32768, pw + (size_t)(12+l)*32768,
                    Bb + l*DD, Cb + l*DD, Cb + l*DD, pBh, pCh, pCh, psc, psh, NN);
            }
            cudaStreamWaitEvent(0, evE[l-1], 0);   // scE/shE from ebn(l-1)
        } else {
            cudaStreamWaitEvent(0, evZ, 0);        // agg zeroed before scatter
        }

        const unsigned short* aimg = pw + (size_t)(6+l)*32768;
        if (l == 0)
            k_edge_mma<1,0,1><<<NT2, 512, SZ_EDGE>>>(aimg, Ab + l*DD, src, dst,
                                                     psc+DD, psh+DD, ea, ep_w, ep_b);
        else if (!last)
            k_edge_mma<0,1,1><<<NT2, 512, SZ_EDGE>>>(aimg, Ab + l*DD, src, dst,
                                                     psc+DD, psh+DD, nullptr, nullptr, nullptr);
        else
            k_edge_mma<0,1,0><<<NT2, 512, SZ_EDGE>>>(aimg, Ab + l*DD, src, dst,
                                                     psc+DD, psh+DD, nullptr, nullptr, nullptr);

        // fork ebn(l) on s2
        cudaEventRecord(evF[l], 0);
        cudaStreamWaitEvent(s2, evF[l], 0);
        k_ebn<<<DD, 256, 0, s2>>>(e_g + l*DD, e_bt + l*DD, psc + DD, psh + DD);
        cudaEventRecord(evE[l], s2);

        if (!last){
            // tmp_stats (fused h-BN finalize + agg re-zero); needs U(l) + counts
            cudaStreamWaitEvent(0, (l == 0) ? evC : evU[l], 0);
            k_node_tmp_stats<256><<<NTS, DD>>>(pst, h_g + l*DD, h_bt + l*DD, psc, psh);
            if (l + 1 < LL - 1){
                // U-gemm for layer l+1 on s2 (overlaps edge(l+1))
                cudaEventRecord(evT[1], 0);
                cudaStreamWaitEvent(s2, evT[1], 0);
                dim3 grid(NTN, 1);
                k_mma_gemm4<1><<<grid, 512, SZ_GEMM, s2>>>(hbuf[l], nullptr, 0,
                    pw + (size_t)(1+l)*32768, pw + (size_t)(1+l)*32768, pw + (size_t)(1+l)*32768,
                    Ub + (l+1)*DD, Ub + (l+1)*DD, Ub + (l+1)*DD, pUh, pUh, pUh, psc, psh, NN);
                cudaEventRecord(evU[l+1], s2);
            }
        }
    }

    // final needs ebn(L-1)
    cudaStreamWaitEvent(0, evE[LL-1], 0);
    k_final_mma<<<NT2, 512, SZ_FIN>>>(pw + (size_t)15*32768, pw + (size_t)16*32768,
                                      f1b, f2b, f3w, f3b, psc + DD, psh + DD, out);
}